// round 10
// baseline (speedup 1.0000x reference)
#include <cuda_runtime.h>
#include <cuda_fp16.h>
#include <math.h>

// Problem constants
#define T_TOK 3072
#define HID 5120
#define NH 16
#define DN 128
#define DR 64
#define DQK 192       // DN + DR
#define DV 128
#define Q_RANK 1536
#define KV_RANK 512
#define KV_A_OUT (KV_RANK + DR)   // 576
#define KV_OUT (DN + DV)          // 256
#define FUSED_N (Q_RANK + KV_A_OUT)   // 2112

typedef __half hf;

// ---------------------------------------------------------------------------
// Scratch (allocation-free: __device__ globals)
// ---------------------------------------------------------------------------
__device__ hf g_Hh[T_TOK * HID], g_Hl[T_TOK * HID];
__device__ hf g_Wa_h[HID * FUSED_N];                 // fused [5120,2112] hi
__device__ hf g_Wqb_h[Q_RANK * NH * DQK];
__device__ hf g_Wkvb_h[KV_RANK * NH * KV_OUT];
__device__ hf g_Wo_h[NH * DV * HID];
__device__ float g_qalat[T_TOK * FUSED_N];           // fused qa | latent (fp32)
__device__ hf g_qa_h[T_TOK * Q_RANK], g_qa_l[T_TOK * Q_RANK];
__device__ hf g_kvan_h[T_TOK * KV_RANK], g_kvan_l[T_TOK * KV_RANK];
__device__ float g_q[T_TOK * NH * DQK];
__device__ hf g_kv16[T_TOK * NH * KV_OUT];           // kv GEMM out, fp16 direct
__device__ hf g_kpe[T_TOK * DR];                     // roped k_pe, fp16
// head-major Q for flash
__device__ hf g_qh[NH * T_TOK * DQK], g_ql[NH * T_TOK * DQK];
__device__ hf g_attn_h[T_TOK * NH * DV], g_attn_l[T_TOK * NH * DV];

// ---------------------------------------------------------------------------
// PTX helpers
// ---------------------------------------------------------------------------
__device__ __forceinline__ unsigned smem_u32(const void* p) {
    return (unsigned)__cvta_generic_to_shared(p);
}
__device__ __forceinline__ void cp16(unsigned s, const void* g, int srcsz) {
    asm volatile("cp.async.cg.shared.global [%0], [%1], 16, %2;\n"
                 :: "r"(s), "l"(g), "r"(srcsz));
}
__device__ __forceinline__ void cp_commit() {
    asm volatile("cp.async.commit_group;\n" ::);
}
template<int N> __device__ __forceinline__ void cp_wait() {
    asm volatile("cp.async.wait_group %0;\n" :: "n"(N));
}
__device__ __forceinline__ void ldm4(unsigned* d, unsigned a) {
    asm volatile("ldmatrix.sync.aligned.m8n8.x4.shared.b16 {%0,%1,%2,%3}, [%4];\n"
                 : "=r"(d[0]), "=r"(d[1]), "=r"(d[2]), "=r"(d[3]) : "r"(a));
}
__device__ __forceinline__ void ldm4t(unsigned* d, unsigned a) {
    asm volatile("ldmatrix.sync.aligned.m8n8.x4.trans.shared.b16 {%0,%1,%2,%3}, [%4];\n"
                 : "=r"(d[0]), "=r"(d[1]), "=r"(d[2]), "=r"(d[3]) : "r"(a));
}
__device__ __forceinline__ void mma16816(float* c, const unsigned* a, const unsigned* b) {
    asm volatile(
        "mma.sync.aligned.m16n8k16.row.col.f32.f16.f16.f32 "
        "{%0,%1,%2,%3}, {%4,%5,%6,%7}, {%8,%9}, {%0,%1,%2,%3};\n"
        : "+f"(c[0]), "+f"(c[1]), "+f"(c[2]), "+f"(c[3])
        : "r"(a[0]), "r"(a[1]), "r"(a[2]), "r"(a[3]), "r"(b[0]), "r"(b[1]));
}
__device__ __forceinline__ void split1(float x, hf& h, hf& l) {
    h = __float2half_rn(x);
    l = __float2half_rn(x - __half2float(h));
}
__device__ __forceinline__ unsigned packhf(hf a, hf b) {
    __half2 t(a, b);
    return *(unsigned*)&t;
}

// ---------------------------------------------------------------------------
// Split-convert: fp32 -> (hi, lo) fp16. n multiple of 4.
// ---------------------------------------------------------------------------
__global__ void split_kernel(const float* __restrict__ x,
                             hf* __restrict__ hi, hf* __restrict__ lo, int n4)
{
    int i = blockIdx.x * blockDim.x + threadIdx.x;
    if (i >= n4) return;
    float4 v = ((const float4*)x)[i];
    hf h0, h1, h2, h3, l0, l1, l2, l3;
    split1(v.x, h0, l0); split1(v.y, h1, l1); split1(v.z, h2, l2); split1(v.w, h3, l3);
    __half2* H = (__half2*)hi;
    __half2* L = (__half2*)lo;
    H[i * 2]     = __half2(h0, h1);
    H[i * 2 + 1] = __half2(h2, h3);
    L[i * 2]     = __half2(l0, l1);
    L[i * 2 + 1] = __half2(l2, l3);
}

// fp32 -> fp16 hi only (B-side weights)
__global__ void split_h_kernel(const float* __restrict__ x,
                               hf* __restrict__ hi, int n4)
{
    int i = blockIdx.x * blockDim.x + threadIdx.x;
    if (i >= n4) return;
    float4 v = ((const float4*)x)[i];
    __half2* H = (__half2*)hi;
    H[i * 2]     = __half2(__float2half_rn(v.x), __float2half_rn(v.y));
    H[i * 2 + 1] = __half2(__float2half_rn(v.z), __float2half_rn(v.w));
}

// Fused-weight hi split: w_q_a [5120,1536] | w_kv_a [5120,576] -> [5120,2112]
__global__ void split_fuse_kernel(const float* __restrict__ wqa,
                                  const float* __restrict__ wkva,
                                  hf* __restrict__ hi)
{
    int i = blockIdx.x * blockDim.x + threadIdx.x;
    int total4 = HID * FUSED_N / 4;
    if (i >= total4) return;
    int e0 = i * 4;
    int k = e0 / FUSED_N, n = e0 % FUSED_N;
    float v[4];
    if (n + 3 < Q_RANK) {
        const float* src = wqa + (size_t)k * Q_RANK + n;
        v[0] = src[0]; v[1] = src[1]; v[2] = src[2]; v[3] = src[3];
    } else if (n >= Q_RANK) {
        const float* src = wkva + (size_t)k * KV_A_OUT + (n - Q_RANK);
        v[0] = src[0]; v[1] = src[1]; v[2] = src[2]; v[3] = src[3];
    } else {
#pragma unroll
        for (int j = 0; j < 4; j++) {
            int nn = n + j;
            v[j] = (nn < Q_RANK) ? wqa[(size_t)k * Q_RANK + nn]
                                 : wkva[(size_t)k * KV_A_OUT + (nn - Q_RANK)];
        }
    }
    hf h[4];
#pragma unroll
    for (int j = 0; j < 4; j++) h[j] = __float2half_rn(v[j]);
    *(uint2*)(hi + e0) = *(uint2*)h;
}

// ---------------------------------------------------------------------------
// fp16 2-term tensor-core GEMM:  C = (Ah+Al) @ Bh.
// CTA 128x128, BK=32, 256 threads, 3-stage cp.async, XOR-swizzled smem.
// OUT16: write C as fp16 (rounded) instead of fp32.
// ---------------------------------------------------------------------------
#define CBM 128
#define CBN 128
#define CBK 32
#define A_TILE_B 8192
#define B_TILE_B 8192
#define STAGE_B  (2 * A_TILE_B + B_TILE_B)   // 24576
#define NSTAGE 3
#define GEMM_SMEM (NSTAGE * STAGE_B)         // 73728

template<bool OUT16>
__device__ __forceinline__ void gemm_cta(
    char* smem, int tid,
    const hf* __restrict__ Ah, const hf* __restrict__ Al,
    const hf* __restrict__ Bh,
    void* __restrict__ Cv, int m0, int n0, int N, int K)
{
    const int lane = tid & 31;
    const int warp = tid >> 5;
    const int wm0 = (warp >> 2) * 64;
    const int wn0 = (warp & 3) * 32;

    float acc[16][4];
#pragma unroll
    for (int i = 0; i < 16; i++)
#pragma unroll
        for (int j = 0; j < 4; j++) acc[i][j] = 0.f;

    auto load_stage = [&](int k0, int s) {
        char* base = smem + s * STAGE_B;
#pragma unroll
        for (int i = 0; i < 2; i++) {
            int ch = tid + i * 256;
            int r = ch >> 2, c = ch & 3;
            int pc = c ^ ((r >> 1) & 3);
            size_t goff = (size_t)(m0 + r) * K + k0 + c * 8;
            cp16(smem_u32(base + r * 64 + pc * 16), Ah + goff, 16);
            cp16(smem_u32(base + A_TILE_B + r * 64 + pc * 16), Al + goff, 16);
        }
#pragma unroll
        for (int i = 0; i < 2; i++) {
            int ch = tid + i * 256;
            int r = ch >> 4, c = ch & 15;
            int pc = c ^ (r & 7);
            int gn = n0 + c * 8;
            int sz = (gn < N) ? 16 : 0;
            size_t goff = (size_t)(k0 + r) * N + (gn < N ? gn : 0);
            cp16(smem_u32(base + 2 * A_TILE_B + r * 256 + pc * 16), Bh + goff, sz);
        }
    };

    auto compute_stage = [&](int s) {
        char* base = smem + s * STAGE_B;
        unsigned aH = smem_u32(base);
        unsigned aL = aH + A_TILE_B;
        unsigned bH = aH + 2 * A_TILE_B;
#pragma unroll
        for (int kk = 0; kk < 2; kk++) {
            unsigned ah[4][4], al[4][4], bh[4][2];
            const int r_lo = lane & 15;
            const int cch = kk * 2 + (lane >> 4);
#pragma unroll
            for (int mi = 0; mi < 4; mi++) {
                int r = wm0 + mi * 16 + r_lo;
                int pc = cch ^ ((r >> 1) & 3);
                unsigned off = (unsigned)(r * 64 + pc * 16);
                ldm4(ah[mi], aH + off);
                ldm4(al[mi], aL + off);
            }
            {
                int r = kk * 16 + (lane & 15);
#pragma unroll
                for (int ni = 0; ni < 2; ni++) {
                    int cc = ((wn0 + ni * 16) >> 3) + ((lane >> 4) & 1);
                    int pc = cc ^ (r & 7);
                    unsigned off = (unsigned)(r * 256 + pc * 16);
                    unsigned t[4];
                    ldm4t(t, bH + off);
                    bh[ni * 2][0] = t[0]; bh[ni * 2][1] = t[1];
                    bh[ni * 2 + 1][0] = t[2]; bh[ni * 2 + 1][1] = t[3];
                }
            }
#pragma unroll
            for (int mi = 0; mi < 4; mi++)
#pragma unroll
                for (int nj = 0; nj < 4; nj++) {
                    mma16816(acc[mi * 4 + nj], ah[mi], bh[nj]);
                    mma16816(acc[mi * 4 + nj], al[mi], bh[nj]);
                }
        }
    };

    const int KT = K / CBK;
    load_stage(0, 0); cp_commit();
    load_stage(CBK, 1); cp_commit();
    for (int kt = 0; kt < KT; kt++) {
        cp_wait<1>();
        __syncthreads();
        if (kt + 2 < KT) load_stage((kt + 2) * CBK, (kt + 2) % NSTAGE);
        cp_commit();
        compute_stage(kt % NSTAGE);
    }

#pragma unroll
    for (int mi = 0; mi < 4; mi++) {
        int row = m0 + wm0 + mi * 16 + (lane >> 2);
#pragma unroll
        for (int nj = 0; nj < 4; nj++) {
            int col = n0 + wn0 + nj * 8 + (lane & 3) * 2;
            if (col < N) {
                float* a = acc[mi * 4 + nj];
                if (OUT16) {
                    hf* C = (hf*)Cv;
                    *(__half2*)(C + (size_t)row * N + col) =
                        __half2(__float2half_rn(a[0]), __float2half_rn(a[1]));
                    *(__half2*)(C + (size_t)(row + 8) * N + col) =
                        __half2(__float2half_rn(a[2]), __float2half_rn(a[3]));
                } else {
                    float* C = (float*)Cv;
                    *(float2*)(C + (size_t)row * N + col)       = make_float2(a[0], a[1]);
                    *(float2*)(C + (size_t)(row + 8) * N + col) = make_float2(a[2], a[3]);
                }
            }
        }
    }
}

__global__ __launch_bounds__(256) void mma_gemm_kernel(
    const hf* __restrict__ Ah, const hf* __restrict__ Al,
    const hf* __restrict__ Bh,
    float* __restrict__ C, int M, int N, int K)
{
    extern __shared__ char smem[];
    gemm_cta<false>(smem, threadIdx.x, Ah, Al, Bh, C,
                    blockIdx.y * CBM, blockIdx.x * CBN, N, K);
}

// Dual GEMM: problem 1 (fp32 out) on first nblk1 n-tiles; problem 2 (fp16 out).
__global__ __launch_bounds__(256) void mma_gemm_dual_kernel(
    const hf* __restrict__ Ah1, const hf* __restrict__ Al1,
    const hf* __restrict__ Bh1,
    float* __restrict__ C1, int N1, int K1, int nblk1,
    const hf* __restrict__ Ah2, const hf* __restrict__ Al2,
    const hf* __restrict__ Bh2,
    hf* __restrict__ C2, int N2, int K2)
{
    extern __shared__ char smem[];
    const int m0 = blockIdx.y * CBM;
    if ((int)blockIdx.x < nblk1) {
        gemm_cta<false>(smem, threadIdx.x, Ah1, Al1, Bh1, C1,
                        m0, blockIdx.x * CBN, N1, K1);
    } else {
        gemm_cta<true>(smem, threadIdx.x, Ah2, Al2, Bh2, C2,
                       m0, (blockIdx.x - nblk1) * CBN, N2, K2);
    }
}

// ---------------------------------------------------------------------------
// RMSNorm + split (input row stride decoupled from width)
// ---------------------------------------------------------------------------
__global__ void rmsnorm_split_kernel(const float* __restrict__ in,
                                     const float* __restrict__ w,
                                     hf* __restrict__ ohi, hf* __restrict__ olo,
                                     int W, int in_stride)
{
    const int t = blockIdx.x;
    const float* row = in + (size_t)t * in_stride;

    float ss = 0.f;
    for (int i = threadIdx.x; i < W; i += blockDim.x) {
        float v = row[i];
        ss += v * v;
    }
    __shared__ float red[32];
#pragma unroll
    for (int o = 16; o; o >>= 1) ss += __shfl_xor_sync(0xffffffffu, ss, o);
    if ((threadIdx.x & 31) == 0) red[threadIdx.x >> 5] = ss;
    __syncthreads();
    if (threadIdx.x < 32) {
        float v = (threadIdx.x < (blockDim.x >> 5)) ? red[threadIdx.x] : 0.f;
#pragma unroll
        for (int o = 16; o; o >>= 1) v += __shfl_xor_sync(0xffffffffu, v, o);
        if (threadIdx.x == 0) red[0] = v;
    }
    __syncthreads();
    const float inv = rsqrtf(red[0] / (float)W + 1e-6f);
    for (int i = threadIdx.x; i < W; i += blockDim.x) {
        float y = row[i] * inv * w[i];
        hf h, l;
        split1(y, h, l);
        ohi[(size_t)t * W + i] = h;
        olo[(size_t)t * W + i] = l;
    }
}

// ---------------------------------------------------------------------------
// Prep: RoPE q_pe (in place) + k_pe (-> fp16 kpe), fold (scaling / sqrt(192))
// into q, emit head-major Q hi/lo (fp16). No K/V materialization.
// ---------------------------------------------------------------------------
__global__ void prep_kernel(const int* __restrict__ positions,
                            const float* __restrict__ cs_cache,
                            const float* __restrict__ scaling,
                            const float* __restrict__ latent, int lat_stride,
                            float* __restrict__ qb,          // [T,16,192] in/out
                            hf* __restrict__ qh, hf* __restrict__ ql,
                            hf* __restrict__ kpe)            // [T,64] fp16
{
    const int t = blockIdx.x;
    const int pos = positions[t];
    const float* cs = cs_cache + (size_t)pos * DR;
    const float qsc = scaling[t] * 0.07216878364870322f;  // llama4 * 1/sqrt(192)
    float* qrow = qb + (size_t)t * (NH * DQK);

    for (int idx = threadIdx.x; idx < NH * 32; idx += blockDim.x) {
        int hh = idx >> 5, i = idx & 31;
        float c = cs[i], s = cs[32 + i];
        float x1 = qrow[hh * DQK + DN + i];
        float x2 = qrow[hh * DQK + DN + 32 + i];
        qrow[hh * DQK + DN + i]      = x1 * c - x2 * s;
        qrow[hh * DQK + DN + 32 + i] = x2 * c + x1 * s;
    }
    if (threadIdx.x < 32) {
        int i = threadIdx.x;
        float c = cs[i], s = cs[32 + i];
        float x1 = latent[(size_t)t * lat_stride + KV_RANK + i];
        float x2 = latent[(size_t)t * lat_stride + KV_RANK + 32 + i];
        kpe[t * DR + i]      = __float2half_rn(x1 * c - x2 * s);
        kpe[t * DR + 32 + i] = __float2half_rn(x2 * c + x1 * s);
    }
    __syncthreads();
    for (int idx = threadIdx.x; idx < NH * DQK; idx += blockDim.x) {
        int hh = idx / DQK, d = idx % DQK;
        size_t o = ((size_t)hh * T_TOK + t) * DQK + d;
        hf hi, lo;
        split1(qrow[idx] * qsc, hi, lo);
        qh[o] = hi; ql[o] = lo;
    }
}

// ---------------------------------------------------------------------------
// Tensor-core flash attention (fp16 2-term, causal).
// Q exact (hi+lo) head-major; K nope + V read DIRECTLY from fp16 kv buffer
// [T,16,256]; k_pe from [T,64] (shared across heads). P exact (hi+lo).
// ---------------------------------------------------------------------------
#define AM 128
#define AN 64
#define FQH 0
#define FQL (FQH + AM*384)
#define FKH (FQL + AM*384)
#define FVH (FKH + AN*384)
#define FLASH_SMEM (FVH + AN*256)    // 139264 B

__global__ __launch_bounds__(256) void flash_mma_kernel(
    const hf* __restrict__ qh, const hf* __restrict__ ql,
    const hf* __restrict__ kv16,   // [T, 16*256]
    const hf* __restrict__ kpe,    // [T, 64]
    hf* __restrict__ attn_h, hf* __restrict__ attn_l)
{
    extern __shared__ char smem[];
    const int m0 = blockIdx.x * AM;
    const int h  = blockIdx.y;
    const int tid = threadIdx.x, lane = tid & 31, warp = tid >> 5;
    const int wm = warp * 16;
    const float L2E = 1.4426950408889634f;

    {
        const hf* qh_g = qh + ((size_t)h * T_TOK + m0) * DQK;
        const hf* ql_g = ql + ((size_t)h * T_TOK + m0) * DQK;
        for (int i = tid; i < AM * 24; i += 256) {
            int r = i / 24, c = i % 24, pc = c ^ (r & 7);
            cp16(smem_u32(smem + FQH + r * 384 + pc * 16), qh_g + (size_t)r * DQK + c * 8, 16);
            cp16(smem_u32(smem + FQL + r * 384 + pc * 16), ql_g + (size_t)r * DQK + c * 8, 16);
        }
        cp_commit();
    }

    float o[16][4];
#pragma unroll
    for (int i = 0; i < 16; i++)
#pragma unroll
        for (int j = 0; j < 4; j++) o[i][j] = 0.f;
    float m0r = -1e30f, m1r = -1e30f, l0 = 0.f, l1 = 0.f;

    const unsigned aQh = smem_u32(smem + FQH), aQl = smem_u32(smem + FQL);
    const unsigned aKh = smem_u32(smem + FKH);
    const unsigned aVh = smem_u32(smem + FVH);

    const int ntiles = 2 * blockIdx.x + 2;
    for (int nt = 0; nt < ntiles; nt++) {
        const int n0 = nt * AN;
        __syncthreads();
        {
            // K: nope (16 chunks/row) from kv16, pe (8 chunks/row) from kpe
            const hf* kv_g = kv16 + (size_t)n0 * (NH * KV_OUT) + h * KV_OUT;
            const hf* pe_g = kpe + (size_t)n0 * DR;
            for (int i = tid; i < AN * 24; i += 256) {
                int r = i / 24, c = i % 24, pc = c ^ (r & 7);
                const hf* src = (c < 16)
                    ? kv_g + (size_t)r * (NH * KV_OUT) + c * 8
                    : pe_g + (size_t)r * DR + (c - 16) * 8;
                cp16(smem_u32(smem + FKH + r * 384 + pc * 16), src, 16);
            }
            // V: 16 chunks/row from kv16 (+DN offset)
            const hf* v_g = kv_g + DN;
            for (int i = tid; i < AN * 16; i += 256) {
                int r = i >> 4, c = i & 15, pc = c ^ (r & 7);
                cp16(smem_u32(smem + FVH + r * 256 + pc * 16),
                     v_g + (size_t)r * (NH * KV_OUT) + c * 8, 16);
            }
        }
        cp_commit();
        cp_wait<0>();
        __syncthreads();

        float s[8][4];
#pragma unroll
        for (int j = 0; j < 8; j++)
#pragma unroll
            for (int c = 0; c < 4; c++) s[j][c] = 0.f;

#pragma unroll
        for (int kt = 0; kt < 12; kt++) {
            unsigned ah[4], al[4];
            {
                int r = wm + (lane & 15), c = kt * 2 + (lane >> 4);
                int pc = c ^ (r & 7);
                unsigned off = (unsigned)(r * 384 + pc * 16);
                ldm4(ah, aQh + off);
                ldm4(al, aQl + off);
            }
#pragma unroll
            for (int kb = 0; kb < 4; kb++) {
                int r = kb * 16 + (lane & 15), c = kt * 2 + (lane >> 4);
                int pc = c ^ (r & 7);
                unsigned off = (unsigned)(r * 384 + pc * 16);
                unsigned tb[4];
                ldm4(tb, aKh + off);
                unsigned bh0[2] = {tb[0], tb[2]}, bh1[2] = {tb[1], tb[3]};
                mma16816(s[kb * 2], ah, bh0);
                mma16816(s[kb * 2], al, bh0);
                mma16816(s[kb * 2 + 1], ah, bh1);
                mma16816(s[kb * 2 + 1], al, bh1);
            }
        }

        if (n0 + AN > m0) {
            int q0 = m0 + wm + (lane >> 2);
#pragma unroll
            for (int j = 0; j < 8; j++) {
                int k0 = n0 + j * 8 + (lane & 3) * 2;
                if (k0     > q0)     s[j][0] = -1e30f;
                if (k0 + 1 > q0)     s[j][1] = -1e30f;
                if (k0     > q0 + 8) s[j][2] = -1e30f;
                if (k0 + 1 > q0 + 8) s[j][3] = -1e30f;
            }
        }

        float mx0 = -1e30f, mx1 = -1e30f;
#pragma unroll
        for (int j = 0; j < 8; j++) {
            mx0 = fmaxf(mx0, fmaxf(s[j][0], s[j][1]));
            mx1 = fmaxf(mx1, fmaxf(s[j][2], s[j][3]));
        }
        mx0 = fmaxf(mx0, __shfl_xor_sync(0xffffffffu, mx0, 1));
        mx0 = fmaxf(mx0, __shfl_xor_sync(0xffffffffu, mx0, 2));
        mx1 = fmaxf(mx1, __shfl_xor_sync(0xffffffffu, mx1, 1));
        mx1 = fmaxf(mx1, __shfl_xor_sync(0xffffffffu, mx1, 2));
        float mn0 = fmaxf(m0r, mx0), mn1 = fmaxf(m1r, mx1);
        float f0 = exp2f((m0r - mn0) * L2E), f1 = exp2f((m1r - mn1) * L2E);
        m0r = mn0; m1r = mn1;

        unsigned ph[8], ph2[8], pl[8], pl2[8];
        float sum0 = 0.f, sum1 = 0.f;
#pragma unroll
        for (int j = 0; j < 8; j++) {
            float p0 = exp2f((s[j][0] - mn0) * L2E);
            float p1 = exp2f((s[j][1] - mn0) * L2E);
            float p2 = exp2f((s[j][2] - mn1) * L2E);
            float p3 = exp2f((s[j][3] - mn1) * L2E);
            sum0 += p0 + p1; sum1 += p2 + p3;
            hf a, b, c, d;
            split1(p0, a, c); split1(p1, b, d);
            ph[j] = packhf(a, b); pl[j] = packhf(c, d);
            split1(p2, a, c); split1(p3, b, d);
            ph2[j] = packhf(a, b); pl2[j] = packhf(c, d);
        }
        sum0 += __shfl_xor_sync(0xffffffffu, sum0, 1);
        sum0 += __shfl_xor_sync(0xffffffffu, sum0, 2);
        sum1 += __shfl_xor_sync(0xffffffffu, sum1, 1);
        sum1 += __shfl_xor_sync(0xffffffffu, sum1, 2);
        l0 = l0 * f0 + sum0;
        l1 = l1 * f1 + sum1;
#pragma unroll
        for (int j = 0; j < 16; j++) {
            o[j][0] *= f0; o[j][1] *= f0; o[j][2] *= f1; o[j][3] *= f1;
        }

#pragma unroll
        for (int kt = 0; kt < 4; kt++) {
            unsigned ahp[4] = {ph[2 * kt], ph2[2 * kt], ph[2 * kt + 1], ph2[2 * kt + 1]};
            unsigned alp[4] = {pl[2 * kt], pl2[2 * kt], pl[2 * kt + 1], pl2[2 * kt + 1]};
#pragma unroll
            for (int nv = 0; nv < 8; nv++) {
                int r = kt * 16 + (lane & 15), c = nv * 2 + (lane >> 4);
                int pc = c ^ (r & 7);
                unsigned off = (unsigned)(r * 256 + pc * 16);
                unsigned tb[4];
                ldm4t(tb, aVh + off);
                unsigned bh0[2] = {tb[0], tb[1]}, bh1[2] = {tb[2], tb[3]};
                mma16816(o[nv * 2], ahp, bh0);
                mma16816(o[nv * 2], alp, bh0);
                mma16816(o[nv * 2 + 1], ahp, bh1);
                mma16816(o[nv * 2 + 1], alp, bh1);
            }
        }
    }

    float il0 = 1.f / l0, il1 = 1.f / l1;
    int r0 = m0 + wm + (lane >> 2);
#pragma unroll
    for (int j = 0; j < 16; j++) {
        int dv = j * 8 + (lane & 3) * 2;
        hf a, b, c, d;
        split1(o[j][0] * il0, a, c);
        split1(o[j][1] * il0, b, d);
        size_t off = (size_t)r0 * (NH * DV) + h * DV + dv;
        *(__half2*)(attn_h + off) = __half2(a, b);
        *(__half2*)(attn_l + off) = __half2(c, d);
        split1(o[j][2] * il1, a, c);
        split1(o[j][3] * il1, b, d);
        off += (size_t)8 * (NH * DV);
        *(__half2*)(attn_h + off) = __half2(a, b);
        *(__half2*)(attn_l + off) = __half2(c, d);
    }
}

// ---------------------------------------------------------------------------
// Launch
// ---------------------------------------------------------------------------
static inline void launch_split(const float* x, hf* hi, hf* lo, int n) {
    int n4 = n / 4;
    split_kernel<<<(n4 + 255) / 256, 256>>>(x, hi, lo, n4);
}
static inline void launch_split_h(const float* x, hf* hi, int n) {
    int n4 = n / 4;
    split_h_kernel<<<(n4 + 255) / 256, 256>>>(x, hi, n4);
}

extern "C" void kernel_launch(void* const* d_in, const int* in_sizes, int n_in,
                              void* d_out, int out_size)
{
    const int*   positions = (const int*)  d_in[0];
    const float* hidden    = (const float*)d_in[1];
    const float* scaling   = (const float*)d_in[2];
    const float* w_q_a     = (const float*)d_in[3];
    const float* q_a_ln_w  = (const float*)d_in[4];
    const float* w_q_b     = (const float*)d_in[5];
    const float* w_kv_a    = (const float*)d_in[6];
    const float* kv_a_ln_w = (const float*)d_in[7];
    const float* w_kv_b    = (const float*)d_in[8];
    const float* w_o       = (const float*)d_in[9];
    const float* cs_cache  = (const float*)d_in[10];
    float* out = (float*)d_out;

    hf *Hh, *Hl, *Wa_h, *Wqb_h, *Wkvb_h, *Wo_h;
    hf *qa_h, *qa_l, *kvan_h, *kvan_l;
    hf *qhp, *qlp, *kv16, *kpe, *attn_h, *attn_l;
    float *qalat, *qb;
    cudaGetSymbolAddress((void**)&Hh, g_Hh);       cudaGetSymbolAddress((void**)&Hl, g_Hl);
    cudaGetSymbolAddress((void**)&Wa_h, g_Wa_h);
    cudaGetSymbolAddress((void**)&Wqb_h, g_Wqb_h);
    cudaGetSymbolAddress((void**)&Wkvb_h, g_Wkvb_h);
    cudaGetSymbolAddress((void**)&Wo_h, g_Wo_h);
    cudaGetSymbolAddress((void**)&qa_h, g_qa_h);   cudaGetSymbolAddress((void**)&qa_l, g_qa_l);
    cudaGetSymbolAddress((void**)&kvan_h, g_kvan_h); cudaGetSymbolAddress((void**)&kvan_l, g_kvan_l);
    cudaGetSymbolAddress((void**)&qhp, g_qh); cudaGetSymbolAddress((void**)&qlp, g_ql);
    cudaGetSymbolAddress((void**)&kv16, g_kv16);
    cudaGetSymbolAddress((void**)&kpe, g_kpe);
    cudaGetSymbolAddress((void**)&attn_h, g_attn_h); cudaGetSymbolAddress((void**)&attn_l, g_attn_l);
    cudaGetSymbolAddress((void**)&qalat, g_qalat);
    cudaGetSymbolAddress((void**)&qb, g_q);

    cudaFuncSetAttribute(mma_gemm_kernel, cudaFuncAttributeMaxDynamicSharedMemorySize,
                         GEMM_SMEM);
    cudaFuncSetAttribute(mma_gemm_dual_kernel, cudaFuncAttributeMaxDynamicSharedMemorySize,
                         GEMM_SMEM);
    cudaFuncSetAttribute(flash_mma_kernel, cudaFuncAttributeMaxDynamicSharedMemorySize,
                         FLASH_SMEM);

    // 1. splits: hidden hi/lo; weights hi only (fused w_q_a|w_kv_a)
    launch_split(hidden, Hh, Hl, T_TOK * HID);
    {
        int total4 = HID * FUSED_N / 4;
        split_fuse_kernel<<<(total4 + 255) / 256, 256>>>(w_q_a, w_kv_a, Wa_h);
    }
    launch_split_h(w_q_b, Wqb_h, Q_RANK * NH * DQK);
    launch_split_h(w_kv_b, Wkvb_h, KV_RANK * NH * KV_OUT);
    launch_split_h(w_o, Wo_h, NH * DV * HID);

    const dim3 blk(256);
    const int MT = T_TOK / CBM;  // 24

    // 2. [qa | latent] = hidden @ [w_q_a | w_kv_a]
    mma_gemm_kernel<<<dim3((FUSED_N + CBN - 1) / CBN, MT), blk, GEMM_SMEM>>>(
        Hh, Hl, Wa_h, qalat, T_TOK, FUSED_N, HID);
    // 3. rmsnorm + split
    rmsnorm_split_kernel<<<T_TOK, 256>>>(qalat, q_a_ln_w, qa_h, qa_l, Q_RANK, FUSED_N);
    rmsnorm_split_kernel<<<T_TOK, 256>>>(qalat + Q_RANK, kv_a_ln_w, kvan_h, kvan_l,
                                         KV_RANK, FUSED_N);
    // 4+5 fused: q (fp32 out) AND kv (fp16 out, consumed directly by flash)
    {
        const int nblk_q  = (NH * DQK) / CBN;    // 24
        const int nblk_kv = (NH * KV_OUT) / CBN; // 32
        mma_gemm_dual_kernel<<<dim3(nblk_q + nblk_kv, MT), blk, GEMM_SMEM>>>(
            qa_h, qa_l, Wqb_h, qb, NH * DQK, Q_RANK, nblk_q,
            kvan_h, kvan_l, Wkvb_h, kv16, NH * KV_OUT, KV_RANK);
    }
    // 6. rope + scale + head-major Q; k_pe -> fp16
    prep_kernel<<<T_TOK, 256>>>(positions, cs_cache, scaling,
                                qalat + Q_RANK, FUSED_N, qb, qhp, qlp, kpe);
    // 7. flash attention (K/V direct from fp16 kv buffer)
    flash_mma_kernel<<<dim3(T_TOK / AM, NH), 256, FLASH_SMEM>>>(
        qhp, qlp, kv16, kpe, attn_h, attn_l);
    // 8. out = attn @ w_o
    mma_gemm_kernel<<<dim3(HID / CBN, MT), blk, GEMM_SMEM>>>(
        attn_h, attn_l, Wo_h, out, T_TOK, HID, NH * DV);
}

// round 11
// speedup vs baseline: 1.1120x; 1.1120x over previous
#include <cuda_runtime.h>
#include <cuda_fp16.h>
#include <math.h>

// Problem constants
#define T_TOK 3072
#define HID 5120
#define NH 16
#define DN 128
#define DR 64
#define DQK 192       // DN + DR
#define DV 128
#define Q_RANK 1536
#define KV_RANK 512
#define KV_A_OUT (KV_RANK + DR)   // 576
#define KV_OUT (DN + DV)          // 256
#define FUSED_N (Q_RANK + KV_A_OUT)   // 2112

typedef __half hf;

// ---------------------------------------------------------------------------
// Scratch (allocation-free: __device__ globals)
// ---------------------------------------------------------------------------
__device__ hf g_Hh[T_TOK * HID], g_Hl[T_TOK * HID];
__device__ hf g_Wa_h[HID * FUSED_N];                 // fused [5120,2112] hi
__device__ hf g_Wqb_h[Q_RANK * NH * DQK];
__device__ hf g_Wkvb_h[KV_RANK * NH * KV_OUT];
__device__ hf g_Wo_h[NH * DV * HID];
__device__ float g_qalat[T_TOK * FUSED_N];           // fused qa | latent (fp32)
__device__ hf g_qa_h[T_TOK * Q_RANK], g_qa_l[T_TOK * Q_RANK];
__device__ hf g_kvan_h[T_TOK * KV_RANK], g_kvan_l[T_TOK * KV_RANK];
__device__ float g_q[T_TOK * NH * DQK];
__device__ hf g_kv16[T_TOK * NH * KV_OUT];           // kv GEMM out, fp16 direct
__device__ hf g_kpe[T_TOK * DR];                     // roped k_pe, fp16
// head-major Q for flash
__device__ hf g_qh[NH * T_TOK * DQK], g_ql[NH * T_TOK * DQK];
__device__ hf g_attn[T_TOK * NH * DV];               // attn out, fp16 single

// ---------------------------------------------------------------------------
// PTX helpers
// ---------------------------------------------------------------------------
__device__ __forceinline__ unsigned smem_u32(const void* p) {
    return (unsigned)__cvta_generic_to_shared(p);
}
__device__ __forceinline__ void cp16(unsigned s, const void* g, int srcsz) {
    asm volatile("cp.async.cg.shared.global [%0], [%1], 16, %2;\n"
                 :: "r"(s), "l"(g), "r"(srcsz));
}
__device__ __forceinline__ void cp_commit() {
    asm volatile("cp.async.commit_group;\n" ::);
}
template<int N> __device__ __forceinline__ void cp_wait() {
    asm volatile("cp.async.wait_group %0;\n" :: "n"(N));
}
__device__ __forceinline__ void ldm4(unsigned* d, unsigned a) {
    asm volatile("ldmatrix.sync.aligned.m8n8.x4.shared.b16 {%0,%1,%2,%3}, [%4];\n"
                 : "=r"(d[0]), "=r"(d[1]), "=r"(d[2]), "=r"(d[3]) : "r"(a));
}
__device__ __forceinline__ void ldm4t(unsigned* d, unsigned a) {
    asm volatile("ldmatrix.sync.aligned.m8n8.x4.trans.shared.b16 {%0,%1,%2,%3}, [%4];\n"
                 : "=r"(d[0]), "=r"(d[1]), "=r"(d[2]), "=r"(d[3]) : "r"(a));
}
__device__ __forceinline__ void mma16816(float* c, const unsigned* a, const unsigned* b) {
    asm volatile(
        "mma.sync.aligned.m16n8k16.row.col.f32.f16.f16.f32 "
        "{%0,%1,%2,%3}, {%4,%5,%6,%7}, {%8,%9}, {%0,%1,%2,%3};\n"
        : "+f"(c[0]), "+f"(c[1]), "+f"(c[2]), "+f"(c[3])
        : "r"(a[0]), "r"(a[1]), "r"(a[2]), "r"(a[3]), "r"(b[0]), "r"(b[1]));
}
__device__ __forceinline__ void split1(float x, hf& h, hf& l) {
    h = __float2half_rn(x);
    l = __float2half_rn(x - __half2float(h));
}
__device__ __forceinline__ unsigned packhf(hf a, hf b) {
    __half2 t(a, b);
    return *(unsigned*)&t;
}

// ---------------------------------------------------------------------------
// Split-convert: fp32 -> (hi, lo) fp16. n multiple of 4.
// ---------------------------------------------------------------------------
__global__ void split_kernel(const float* __restrict__ x,
                             hf* __restrict__ hi, hf* __restrict__ lo, int n4)
{
    int i = blockIdx.x * blockDim.x + threadIdx.x;
    if (i >= n4) return;
    float4 v = ((const float4*)x)[i];
    hf h0, h1, h2, h3, l0, l1, l2, l3;
    split1(v.x, h0, l0); split1(v.y, h1, l1); split1(v.z, h2, l2); split1(v.w, h3, l3);
    __half2* H = (__half2*)hi;
    __half2* L = (__half2*)lo;
    H[i * 2]     = __half2(h0, h1);
    H[i * 2 + 1] = __half2(h2, h3);
    L[i * 2]     = __half2(l0, l1);
    L[i * 2 + 1] = __half2(l2, l3);
}

// fp32 -> fp16 hi only (B-side weights)
__global__ void split_h_kernel(const float* __restrict__ x,
                               hf* __restrict__ hi, int n4)
{
    int i = blockIdx.x * blockDim.x + threadIdx.x;
    if (i >= n4) return;
    float4 v = ((const float4*)x)[i];
    __half2* H = (__half2*)hi;
    H[i * 2]     = __half2(__float2half_rn(v.x), __float2half_rn(v.y));
    H[i * 2 + 1] = __half2(__float2half_rn(v.z), __float2half_rn(v.w));
}

// Fused-weight hi split: w_q_a [5120,1536] | w_kv_a [5120,576] -> [5120,2112]
__global__ void split_fuse_kernel(const float* __restrict__ wqa,
                                  const float* __restrict__ wkva,
                                  hf* __restrict__ hi)
{
    int i = blockIdx.x * blockDim.x + threadIdx.x;
    int total4 = HID * FUSED_N / 4;
    if (i >= total4) return;
    int e0 = i * 4;
    int k = e0 / FUSED_N, n = e0 % FUSED_N;
    float v[4];
    if (n + 3 < Q_RANK) {
        const float* src = wqa + (size_t)k * Q_RANK + n;
        v[0] = src[0]; v[1] = src[1]; v[2] = src[2]; v[3] = src[3];
    } else if (n >= Q_RANK) {
        const float* src = wkva + (size_t)k * KV_A_OUT + (n - Q_RANK);
        v[0] = src[0]; v[1] = src[1]; v[2] = src[2]; v[3] = src[3];
    } else {
#pragma unroll
        for (int j = 0; j < 4; j++) {
            int nn = n + j;
            v[j] = (nn < Q_RANK) ? wqa[(size_t)k * Q_RANK + nn]
                                 : wkva[(size_t)k * KV_A_OUT + (nn - Q_RANK)];
        }
    }
    hf h[4];
#pragma unroll
    for (int j = 0; j < 4; j++) h[j] = __float2half_rn(v[j]);
    *(uint2*)(hi + e0) = *(uint2*)h;
}

// ---------------------------------------------------------------------------
// fp16 tensor-core GEMM:  C = (Ah [+ Al]) @ Bh.
// CTA 128x128, BK=32, 256 threads, 3-stage cp.async, XOR-swizzled smem.
// TWO_TERM: include Al (A exact to 2^-22). OUT16: fp16 output.
// ---------------------------------------------------------------------------
#define CBM 128
#define CBN 128
#define CBK 32
#define A_TILE_B 8192
#define B_TILE_B 8192
#define STAGE_B  (2 * A_TILE_B + B_TILE_B)   // 24576
#define NSTAGE 3
#define GEMM_SMEM (NSTAGE * STAGE_B)         // 73728

template<bool OUT16, bool TWO_TERM>
__device__ __forceinline__ void gemm_cta(
    char* smem, int tid,
    const hf* __restrict__ Ah, const hf* __restrict__ Al,
    const hf* __restrict__ Bh,
    void* __restrict__ Cv, int m0, int n0, int N, int K)
{
    const int lane = tid & 31;
    const int warp = tid >> 5;
    const int wm0 = (warp >> 2) * 64;
    const int wn0 = (warp & 3) * 32;

    float acc[16][4];
#pragma unroll
    for (int i = 0; i < 16; i++)
#pragma unroll
        for (int j = 0; j < 4; j++) acc[i][j] = 0.f;

    auto load_stage = [&](int k0, int s) {
        char* base = smem + s * STAGE_B;
#pragma unroll
        for (int i = 0; i < 2; i++) {
            int ch = tid + i * 256;
            int r = ch >> 2, c = ch & 3;
            int pc = c ^ ((r >> 1) & 3);
            size_t goff = (size_t)(m0 + r) * K + k0 + c * 8;
            cp16(smem_u32(base + r * 64 + pc * 16), Ah + goff, 16);
            if (TWO_TERM)
                cp16(smem_u32(base + A_TILE_B + r * 64 + pc * 16), Al + goff, 16);
        }
#pragma unroll
        for (int i = 0; i < 2; i++) {
            int ch = tid + i * 256;
            int r = ch >> 4, c = ch & 15;
            int pc = c ^ (r & 7);
            int gn = n0 + c * 8;
            int sz = (gn < N) ? 16 : 0;
            size_t goff = (size_t)(k0 + r) * N + (gn < N ? gn : 0);
            cp16(smem_u32(base + 2 * A_TILE_B + r * 256 + pc * 16), Bh + goff, sz);
        }
    };

    auto compute_stage = [&](int s) {
        char* base = smem + s * STAGE_B;
        unsigned aH = smem_u32(base);
        unsigned aL = aH + A_TILE_B;
        unsigned bH = aH + 2 * A_TILE_B;
#pragma unroll
        for (int kk = 0; kk < 2; kk++) {
            unsigned ah[4][4], al[4][4], bh[4][2];
            const int r_lo = lane & 15;
            const int cch = kk * 2 + (lane >> 4);
#pragma unroll
            for (int mi = 0; mi < 4; mi++) {
                int r = wm0 + mi * 16 + r_lo;
                int pc = cch ^ ((r >> 1) & 3);
                unsigned off = (unsigned)(r * 64 + pc * 16);
                ldm4(ah[mi], aH + off);
                if (TWO_TERM) ldm4(al[mi], aL + off);
            }
            {
                int r = kk * 16 + (lane & 15);
#pragma unroll
                for (int ni = 0; ni < 2; ni++) {
                    int cc = ((wn0 + ni * 16) >> 3) + ((lane >> 4) & 1);
                    int pc = cc ^ (r & 7);
                    unsigned off = (unsigned)(r * 256 + pc * 16);
                    unsigned t[4];
                    ldm4t(t, bH + off);
                    bh[ni * 2][0] = t[0]; bh[ni * 2][1] = t[1];
                    bh[ni * 2 + 1][0] = t[2]; bh[ni * 2 + 1][1] = t[3];
                }
            }
#pragma unroll
            for (int mi = 0; mi < 4; mi++)
#pragma unroll
                for (int nj = 0; nj < 4; nj++) {
                    mma16816(acc[mi * 4 + nj], ah[mi], bh[nj]);
                    if (TWO_TERM) mma16816(acc[mi * 4 + nj], al[mi], bh[nj]);
                }
        }
    };

    const int KT = K / CBK;
    load_stage(0, 0); cp_commit();
    load_stage(CBK, 1); cp_commit();
    for (int kt = 0; kt < KT; kt++) {
        cp_wait<1>();
        __syncthreads();
        if (kt + 2 < KT) load_stage((kt + 2) * CBK, (kt + 2) % NSTAGE);
        cp_commit();
        compute_stage(kt % NSTAGE);
    }

#pragma unroll
    for (int mi = 0; mi < 4; mi++) {
        int row = m0 + wm0 + mi * 16 + (lane >> 2);
#pragma unroll
        for (int nj = 0; nj < 4; nj++) {
            int col = n0 + wn0 + nj * 8 + (lane & 3) * 2;
            if (col < N) {
                float* a = acc[mi * 4 + nj];
                if (OUT16) {
                    hf* C = (hf*)Cv;
                    *(__half2*)(C + (size_t)row * N + col) =
                        __half2(__float2half_rn(a[0]), __float2half_rn(a[1]));
                    *(__half2*)(C + (size_t)(row + 8) * N + col) =
                        __half2(__float2half_rn(a[2]), __float2half_rn(a[3]));
                } else {
                    float* C = (float*)Cv;
                    *(float2*)(C + (size_t)row * N + col)       = make_float2(a[0], a[1]);
                    *(float2*)(C + (size_t)(row + 8) * N + col) = make_float2(a[2], a[3]);
                }
            }
        }
    }
}

__global__ __launch_bounds__(256) void mma_gemm_kernel(
    const hf* __restrict__ Ah, const hf* __restrict__ Al,
    const hf* __restrict__ Bh,
    float* __restrict__ C, int M, int N, int K)
{
    extern __shared__ char smem[];
    gemm_cta<false, true>(smem, threadIdx.x, Ah, Al, Bh, C,
                          blockIdx.y * CBM, blockIdx.x * CBN, N, K);
}

// Single-term GEMM (A hi only), fp32 out — used for out = attn @ w_o.
__global__ __launch_bounds__(256) void mma_gemm1_kernel(
    const hf* __restrict__ Ah,
    const hf* __restrict__ Bh,
    float* __restrict__ C, int M, int N, int K)
{
    extern __shared__ char smem[];
    gemm_cta<false, false>(smem, threadIdx.x, Ah, nullptr, Bh, C,
                           blockIdx.y * CBM, blockIdx.x * CBN, N, K);
}

// Dual GEMM: problem 1 (fp32 out) on first nblk1 n-tiles; problem 2 (fp16 out).
__global__ __launch_bounds__(256) void mma_gemm_dual_kernel(
    const hf* __restrict__ Ah1, const hf* __restrict__ Al1,
    const hf* __restrict__ Bh1,
    float* __restrict__ C1, int N1, int K1, int nblk1,
    const hf* __restrict__ Ah2, const hf* __restrict__ Al2,
    const hf* __restrict__ Bh2,
    hf* __restrict__ C2, int N2, int K2)
{
    extern __shared__ char smem[];
    const int m0 = blockIdx.y * CBM;
    if ((int)blockIdx.x < nblk1) {
        gemm_cta<false, true>(smem, threadIdx.x, Ah1, Al1, Bh1, C1,
                              m0, blockIdx.x * CBN, N1, K1);
    } else {
        gemm_cta<true, true>(smem, threadIdx.x, Ah2, Al2, Bh2, C2,
                             m0, (blockIdx.x - nblk1) * CBN, N2, K2);
    }
}

// ---------------------------------------------------------------------------
// RMSNorm + split (input row stride decoupled from width)
// ---------------------------------------------------------------------------
__global__ void rmsnorm_split_kernel(const float* __restrict__ in,
                                     const float* __restrict__ w,
                                     hf* __restrict__ ohi, hf* __restrict__ olo,
                                     int W, int in_stride)
{
    const int t = blockIdx.x;
    const float* row = in + (size_t)t * in_stride;

    float ss = 0.f;
    for (int i = threadIdx.x; i < W; i += blockDim.x) {
        float v = row[i];
        ss += v * v;
    }
    __shared__ float red[32];
#pragma unroll
    for (int o = 16; o; o >>= 1) ss += __shfl_xor_sync(0xffffffffu, ss, o);
    if ((threadIdx.x & 31) == 0) red[threadIdx.x >> 5] = ss;
    __syncthreads();
    if (threadIdx.x < 32) {
        float v = (threadIdx.x < (blockDim.x >> 5)) ? red[threadIdx.x] : 0.f;
#pragma unroll
        for (int o = 16; o; o >>= 1) v += __shfl_xor_sync(0xffffffffu, v, o);
        if (threadIdx.x == 0) red[0] = v;
    }
    __syncthreads();
    const float inv = rsqrtf(red[0] / (float)W + 1e-6f);
    for (int i = threadIdx.x; i < W; i += blockDim.x) {
        float y = row[i] * inv * w[i];
        hf h, l;
        split1(y, h, l);
        ohi[(size_t)t * W + i] = h;
        olo[(size_t)t * W + i] = l;
    }
}

// ---------------------------------------------------------------------------
// Prep: RoPE q_pe (in place) + k_pe (-> fp16 kpe), fold (scaling / sqrt(192))
// into q, emit head-major Q hi/lo (fp16).
// ---------------------------------------------------------------------------
__global__ void prep_kernel(const int* __restrict__ positions,
                            const float* __restrict__ cs_cache,
                            const float* __restrict__ scaling,
                            const float* __restrict__ latent, int lat_stride,
                            float* __restrict__ qb,          // [T,16,192] in/out
                            hf* __restrict__ qh, hf* __restrict__ ql,
                            hf* __restrict__ kpe)            // [T,64] fp16
{
    const int t = blockIdx.x;
    const int pos = positions[t];
    const float* cs = cs_cache + (size_t)pos * DR;
    const float qsc = scaling[t] * 0.07216878364870322f;  // llama4 * 1/sqrt(192)
    float* qrow = qb + (size_t)t * (NH * DQK);

    for (int idx = threadIdx.x; idx < NH * 32; idx += blockDim.x) {
        int hh = idx >> 5, i = idx & 31;
        float c = cs[i], s = cs[32 + i];
        float x1 = qrow[hh * DQK + DN + i];
        float x2 = qrow[hh * DQK + DN + 32 + i];
        qrow[hh * DQK + DN + i]      = x1 * c - x2 * s;
        qrow[hh * DQK + DN + 32 + i] = x2 * c + x1 * s;
    }
    if (threadIdx.x < 32) {
        int i = threadIdx.x;
        float c = cs[i], s = cs[32 + i];
        float x1 = latent[(size_t)t * lat_stride + KV_RANK + i];
        float x2 = latent[(size_t)t * lat_stride + KV_RANK + 32 + i];
        kpe[t * DR + i]      = __float2half_rn(x1 * c - x2 * s);
        kpe[t * DR + 32 + i] = __float2half_rn(x2 * c + x1 * s);
    }
    __syncthreads();
    for (int idx = threadIdx.x; idx < NH * DQK; idx += blockDim.x) {
        int hh = idx / DQK, d = idx % DQK;
        size_t o = ((size_t)hh * T_TOK + t) * DQK + d;
        hf hi, lo;
        split1(qrow[idx] * qsc, hi, lo);
        qh[o] = hi; ql[o] = lo;
    }
}

// ---------------------------------------------------------------------------
// Tensor-core flash attention (fp16 2-term, causal).
// Q exact (hi+lo); K nope + V direct from fp16 kv buffer [T,16,256];
// k_pe from [T,64]. P exact (hi+lo). Output: plain fp16.
// ---------------------------------------------------------------------------
#define AM 128
#define AN 64
#define FQH 0
#define FQL (FQH + AM*384)
#define FKH (FQL + AM*384)
#define FVH (FKH + AN*384)
#define FLASH_SMEM (FVH + AN*256)    // 139264 B

__global__ __launch_bounds__(256) void flash_mma_kernel(
    const hf* __restrict__ qh, const hf* __restrict__ ql,
    const hf* __restrict__ kv16,   // [T, 16*256]
    const hf* __restrict__ kpe,    // [T, 64]
    hf* __restrict__ attn)
{
    extern __shared__ char smem[];
    const int m0 = blockIdx.x * AM;
    const int h  = blockIdx.y;
    const int tid = threadIdx.x, lane = tid & 31, warp = tid >> 5;
    const int wm = warp * 16;
    const float L2E = 1.4426950408889634f;

    {
        const hf* qh_g = qh + ((size_t)h * T_TOK + m0) * DQK;
        const hf* ql_g = ql + ((size_t)h * T_TOK + m0) * DQK;
        for (int i = tid; i < AM * 24; i += 256) {
            int r = i / 24, c = i % 24, pc = c ^ (r & 7);
            cp16(smem_u32(smem + FQH + r * 384 + pc * 16), qh_g + (size_t)r * DQK + c * 8, 16);
            cp16(smem_u32(smem + FQL + r * 384 + pc * 16), ql_g + (size_t)r * DQK + c * 8, 16);
        }
        cp_commit();
    }

    float o[16][4];
#pragma unroll
    for (int i = 0; i < 16; i++)
#pragma unroll
        for (int j = 0; j < 4; j++) o[i][j] = 0.f;
    float m0r = -1e30f, m1r = -1e30f, l0 = 0.f, l1 = 0.f;

    const unsigned aQh = smem_u32(smem + FQH), aQl = smem_u32(smem + FQL);
    const unsigned aKh = smem_u32(smem + FKH);
    const unsigned aVh = smem_u32(smem + FVH);

    const int ntiles = 2 * blockIdx.x + 2;
    for (int nt = 0; nt < ntiles; nt++) {
        const int n0 = nt * AN;
        __syncthreads();
        {
            const hf* kv_g = kv16 + (size_t)n0 * (NH * KV_OUT) + h * KV_OUT;
            const hf* pe_g = kpe + (size_t)n0 * DR;
            for (int i = tid; i < AN * 24; i += 256) {
                int r = i / 24, c = i % 24, pc = c ^ (r & 7);
                const hf* src = (c < 16)
                    ? kv_g + (size_t)r * (NH * KV_OUT) + c * 8
                    : pe_g + (size_t)r * DR + (c - 16) * 8;
                cp16(smem_u32(smem + FKH + r * 384 + pc * 16), src, 16);
            }
            const hf* v_g = kv_g + DN;
            for (int i = tid; i < AN * 16; i += 256) {
                int r = i >> 4, c = i & 15, pc = c ^ (r & 7);
                cp16(smem_u32(smem + FVH + r * 256 + pc * 16),
                     v_g + (size_t)r * (NH * KV_OUT) + c * 8, 16);
            }
        }
        cp_commit();
        cp_wait<0>();
        __syncthreads();

        float s[8][4];
#pragma unroll
        for (int j = 0; j < 8; j++)
#pragma unroll
            for (int c = 0; c < 4; c++) s[j][c] = 0.f;

#pragma unroll
        for (int kt = 0; kt < 12; kt++) {
            unsigned ah[4], al[4];
            {
                int r = wm + (lane & 15), c = kt * 2 + (lane >> 4);
                int pc = c ^ (r & 7);
                unsigned off = (unsigned)(r * 384 + pc * 16);
                ldm4(ah, aQh + off);
                ldm4(al, aQl + off);
            }
#pragma unroll
            for (int kb = 0; kb < 4; kb++) {
                int r = kb * 16 + (lane & 15), c = kt * 2 + (lane >> 4);
                int pc = c ^ (r & 7);
                unsigned off = (unsigned)(r * 384 + pc * 16);
                unsigned tb[4];
                ldm4(tb, aKh + off);
                unsigned bh0[2] = {tb[0], tb[2]}, bh1[2] = {tb[1], tb[3]};
                mma16816(s[kb * 2], ah, bh0);
                mma16816(s[kb * 2], al, bh0);
                mma16816(s[kb * 2 + 1], ah, bh1);
                mma16816(s[kb * 2 + 1], al, bh1);
            }
        }

        if (n0 + AN > m0) {
            int q0 = m0 + wm + (lane >> 2);
#pragma unroll
            for (int j = 0; j < 8; j++) {
                int k0 = n0 + j * 8 + (lane & 3) * 2;
                if (k0     > q0)     s[j][0] = -1e30f;
                if (k0 + 1 > q0)     s[j][1] = -1e30f;
                if (k0     > q0 + 8) s[j][2] = -1e30f;
                if (k0 + 1 > q0 + 8) s[j][3] = -1e30f;
            }
        }

        float mx0 = -1e30f, mx1 = -1e30f;
#pragma unroll
        for (int j = 0; j < 8; j++) {
            mx0 = fmaxf(mx0, fmaxf(s[j][0], s[j][1]));
            mx1 = fmaxf(mx1, fmaxf(s[j][2], s[j][3]));
        }
        mx0 = fmaxf(mx0, __shfl_xor_sync(0xffffffffu, mx0, 1));
        mx0 = fmaxf(mx0, __shfl_xor_sync(0xffffffffu, mx0, 2));
        mx1 = fmaxf(mx1, __shfl_xor_sync(0xffffffffu, mx1, 1));
        mx1 = fmaxf(mx1, __shfl_xor_sync(0xffffffffu, mx1, 2));
        float mn0 = fmaxf(m0r, mx0), mn1 = fmaxf(m1r, mx1);
        float f0 = exp2f((m0r - mn0) * L2E), f1 = exp2f((m1r - mn1) * L2E);
        m0r = mn0; m1r = mn1;

        unsigned ph[8], ph2[8], pl[8], pl2[8];
        float sum0 = 0.f, sum1 = 0.f;
#pragma unroll
        for (int j = 0; j < 8; j++) {
            float p0 = exp2f((s[j][0] - mn0) * L2E);
            float p1 = exp2f((s[j][1] - mn0) * L2E);
            float p2 = exp2f((s[j][2] - mn1) * L2E);
            float p3 = exp2f((s[j][3] - mn1) * L2E);
            sum0 += p0 + p1; sum1 += p2 + p3;
            hf a, b, c, d;
            split1(p0, a, c); split1(p1, b, d);
            ph[j] = packhf(a, b); pl[j] = packhf(c, d);
            split1(p2, a, c); split1(p3, b, d);
            ph2[j] = packhf(a, b); pl2[j] = packhf(c, d);
        }
        sum0 += __shfl_xor_sync(0xffffffffu, sum0, 1);
        sum0 += __shfl_xor_sync(0xffffffffu, sum0, 2);
        sum1 += __shfl_xor_sync(0xffffffffu, sum1, 1);
        sum1 += __shfl_xor_sync(0xffffffffu, sum1, 2);
        l0 = l0 * f0 + sum0;
        l1 = l1 * f1 + sum1;
#pragma unroll
        for (int j = 0; j < 16; j++) {
            o[j][0] *= f0; o[j][1] *= f0; o[j][2] *= f1; o[j][3] *= f1;
        }

#pragma unroll
        for (int kt = 0; kt < 4; kt++) {
            unsigned ahp[4] = {ph[2 * kt], ph2[2 * kt], ph[2 * kt + 1], ph2[2 * kt + 1]};
            unsigned alp[4] = {pl[2 * kt], pl2[2 * kt], pl[2 * kt + 1], pl2[2 * kt + 1]};
#pragma unroll
            for (int nv = 0; nv < 8; nv++) {
                int r = kt * 16 + (lane & 15), c = nv * 2 + (lane >> 4);
                int pc = c ^ (r & 7);
                unsigned off = (unsigned)(r * 256 + pc * 16);
                unsigned tb[4];
                ldm4t(tb, aVh + off);
                unsigned bh0[2] = {tb[0], tb[1]}, bh1[2] = {tb[2], tb[3]};
                mma16816(o[nv * 2], ahp, bh0);
                mma16816(o[nv * 2], alp, bh0);
                mma16816(o[nv * 2 + 1], ahp, bh1);
                mma16816(o[nv * 2 + 1], alp, bh1);
            }
        }
    }

    float il0 = 1.f / l0, il1 = 1.f / l1;
    int r0 = m0 + wm + (lane >> 2);
#pragma unroll
    for (int j = 0; j < 16; j++) {
        int dv = j * 8 + (lane & 3) * 2;
        size_t off = (size_t)r0 * (NH * DV) + h * DV + dv;
        *(__half2*)(attn + off) =
            __half2(__float2half_rn(o[j][0] * il0), __float2half_rn(o[j][1] * il0));
        off += (size_t)8 * (NH * DV);
        *(__half2*)(attn + off) =
            __half2(__float2half_rn(o[j][2] * il1), __float2half_rn(o[j][3] * il1));
    }
}

// ---------------------------------------------------------------------------
// Launch
// ---------------------------------------------------------------------------
static inline void launch_split(const float* x, hf* hi, hf* lo, int n) {
    int n4 = n / 4;
    split_kernel<<<(n4 + 255) / 256, 256>>>(x, hi, lo, n4);
}
static inline void launch_split_h(const float* x, hf* hi, int n) {
    int n4 = n / 4;
    split_h_kernel<<<(n4 + 255) / 256, 256>>>(x, hi, n4);
}

extern "C" void kernel_launch(void* const* d_in, const int* in_sizes, int n_in,
                              void* d_out, int out_size)
{
    const int*   positions = (const int*)  d_in[0];
    const float* hidden    = (const float*)d_in[1];
    const float* scaling   = (const float*)d_in[2];
    const float* w_q_a     = (const float*)d_in[3];
    const float* q_a_ln_w  = (const float*)d_in[4];
    const float* w_q_b     = (const float*)d_in[5];
    const float* w_kv_a    = (const float*)d_in[6];
    const float* kv_a_ln_w = (const float*)d_in[7];
    const float* w_kv_b    = (const float*)d_in[8];
    const float* w_o       = (const float*)d_in[9];
    const float* cs_cache  = (const float*)d_in[10];
    float* out = (float*)d_out;

    hf *Hh, *Hl, *Wa_h, *Wqb_h, *Wkvb_h, *Wo_h;
    hf *qa_h, *qa_l, *kvan_h, *kvan_l;
    hf *qhp, *qlp, *kv16, *kpe, *attn;
    float *qalat, *qb;
    cudaGetSymbolAddress((void**)&Hh, g_Hh);       cudaGetSymbolAddress((void**)&Hl, g_Hl);
    cudaGetSymbolAddress((void**)&Wa_h, g_Wa_h);
    cudaGetSymbolAddress((void**)&Wqb_h, g_Wqb_h);
    cudaGetSymbolAddress((void**)&Wkvb_h, g_Wkvb_h);
    cudaGetSymbolAddress((void**)&Wo_h, g_Wo_h);
    cudaGetSymbolAddress((void**)&qa_h, g_qa_h);   cudaGetSymbolAddress((void**)&qa_l, g_qa_l);
    cudaGetSymbolAddress((void**)&kvan_h, g_kvan_h); cudaGetSymbolAddress((void**)&kvan_l, g_kvan_l);
    cudaGetSymbolAddress((void**)&qhp, g_qh); cudaGetSymbolAddress((void**)&qlp, g_ql);
    cudaGetSymbolAddress((void**)&kv16, g_kv16);
    cudaGetSymbolAddress((void**)&kpe, g_kpe);
    cudaGetSymbolAddress((void**)&attn, g_attn);
    cudaGetSymbolAddress((void**)&qalat, g_qalat);
    cudaGetSymbolAddress((void**)&qb, g_q);

    cudaFuncSetAttribute(mma_gemm_kernel, cudaFuncAttributeMaxDynamicSharedMemorySize,
                         GEMM_SMEM);
    cudaFuncSetAttribute(mma_gemm1_kernel, cudaFuncAttributeMaxDynamicSharedMemorySize,
                         GEMM_SMEM);
    cudaFuncSetAttribute(mma_gemm_dual_kernel, cudaFuncAttributeMaxDynamicSharedMemorySize,
                         GEMM_SMEM);
    cudaFuncSetAttribute(flash_mma_kernel, cudaFuncAttributeMaxDynamicSharedMemorySize,
                         FLASH_SMEM);

    // 1. splits: hidden hi/lo; weights hi only (fused w_q_a|w_kv_a)
    launch_split(hidden, Hh, Hl, T_TOK * HID);
    {
        int total4 = HID * FUSED_N / 4;
        split_fuse_kernel<<<(total4 + 255) / 256, 256>>>(w_q_a, w_kv_a, Wa_h);
    }
    launch_split_h(w_q_b, Wqb_h, Q_RANK * NH * DQK);
    launch_split_h(w_kv_b, Wkvb_h, KV_RANK * NH * KV_OUT);
    launch_split_h(w_o, Wo_h, NH * DV * HID);

    const dim3 blk(256);
    const int MT = T_TOK / CBM;  // 24

    // 2. [qa | latent] = hidden @ [w_q_a | w_kv_a]
    mma_gemm_kernel<<<dim3((FUSED_N + CBN - 1) / CBN, MT), blk, GEMM_SMEM>>>(
        Hh, Hl, Wa_h, qalat, T_TOK, FUSED_N, HID);
    // 3. rmsnorm + split
    rmsnorm_split_kernel<<<T_TOK, 256>>>(qalat, q_a_ln_w, qa_h, qa_l, Q_RANK, FUSED_N);
    rmsnorm_split_kernel<<<T_TOK, 256>>>(qalat + Q_RANK, kv_a_ln_w, kvan_h, kvan_l,
                                         KV_RANK, FUSED_N);
    // 4+5 fused: q (fp32 out) AND kv (fp16 out, consumed directly by flash)
    {
        const int nblk_q  = (NH * DQK) / CBN;    // 24
        const int nblk_kv = (NH * KV_OUT) / CBN; // 32
        mma_gemm_dual_kernel<<<dim3(nblk_q + nblk_kv, MT), blk, GEMM_SMEM>>>(
            qa_h, qa_l, Wqb_h, qb, NH * DQK, Q_RANK, nblk_q,
            kvan_h, kvan_l, Wkvb_h, kv16, NH * KV_OUT, KV_RANK);
    }
    // 6. rope + scale + head-major Q; k_pe -> fp16
    prep_kernel<<<T_TOK, 256>>>(positions, cs_cache, scaling,
                                qalat + Q_RANK, FUSED_N, qb, qhp, qlp, kpe);
    // 7. flash attention (fp16 output, single buffer)
    flash_mma_kernel<<<dim3(T_TOK / AM, NH), 256, FLASH_SMEM>>>(
        qhp, qlp, kv16, kpe, attn);
    // 8. out = attn @ w_o  (single-term: attn hi only)
    mma_gemm1_kernel<<<dim3(HID / CBN, MT), blk, GEMM_SMEM>>>(
        attn, Wo_h, out, T_TOK, HID, NH * DV);
}

// round 12
// speedup vs baseline: 1.2780x; 1.1494x over previous
#include <cuda_runtime.h>
#include <cuda_fp16.h>
#include <math.h>

// Problem constants
#define T_TOK 3072
#define HID 5120
#define NH 16
#define DN 128
#define DR 64
#define DQK 192       // DN + DR
#define DV 128
#define Q_RANK 1536
#define KV_RANK 512
#define KV_A_OUT (KV_RANK + DR)   // 576
#define KV_OUT (DN + DV)          // 256
#define FUSED_N (Q_RANK + KV_A_OUT)   // 2112

typedef __half hf;

// ---------------------------------------------------------------------------
// Scratch (allocation-free: __device__ globals)
// ---------------------------------------------------------------------------
__device__ hf g_Hh[T_TOK * HID];                     // hidden hi only
__device__ hf g_Wa_h[HID * FUSED_N];                 // fused [5120,2112] hi
__device__ hf g_Wqb_h[Q_RANK * NH * DQK];
__device__ hf g_Wkvb_h[KV_RANK * NH * KV_OUT];
__device__ hf g_Wo_h[NH * DV * HID];
__device__ float g_qalat[T_TOK * FUSED_N];           // fused qa | latent (fp32)
__device__ hf g_qa_h[T_TOK * Q_RANK], g_qa_l[T_TOK * Q_RANK];
__device__ hf g_kvan_h[T_TOK * KV_RANK], g_kvan_l[T_TOK * KV_RANK];
__device__ float g_q[T_TOK * NH * DQK];
__device__ hf g_kv16[T_TOK * NH * KV_OUT];           // kv GEMM out, fp16 direct
__device__ hf g_kpe[T_TOK * DR];                     // roped k_pe, fp16
// head-major Q for flash
__device__ hf g_qh[NH * T_TOK * DQK], g_ql[NH * T_TOK * DQK];
__device__ hf g_attn[T_TOK * NH * DV];               // attn out, fp16 single

// ---------------------------------------------------------------------------
// PTX helpers
// ---------------------------------------------------------------------------
__device__ __forceinline__ unsigned smem_u32(const void* p) {
    return (unsigned)__cvta_generic_to_shared(p);
}
__device__ __forceinline__ void cp16(unsigned s, const void* g, int srcsz) {
    asm volatile("cp.async.cg.shared.global [%0], [%1], 16, %2;\n"
                 :: "r"(s), "l"(g), "r"(srcsz));
}
__device__ __forceinline__ void cp_commit() {
    asm volatile("cp.async.commit_group;\n" ::);
}
template<int N> __device__ __forceinline__ void cp_wait() {
    asm volatile("cp.async.wait_group %0;\n" :: "n"(N));
}
__device__ __forceinline__ void ldm4(unsigned* d, unsigned a) {
    asm volatile("ldmatrix.sync.aligned.m8n8.x4.shared.b16 {%0,%1,%2,%3}, [%4];\n"
                 : "=r"(d[0]), "=r"(d[1]), "=r"(d[2]), "=r"(d[3]) : "r"(a));
}
__device__ __forceinline__ void ldm4t(unsigned* d, unsigned a) {
    asm volatile("ldmatrix.sync.aligned.m8n8.x4.trans.shared.b16 {%0,%1,%2,%3}, [%4];\n"
                 : "=r"(d[0]), "=r"(d[1]), "=r"(d[2]), "=r"(d[3]) : "r"(a));
}
__device__ __forceinline__ void mma16816(float* c, const unsigned* a, const unsigned* b) {
    asm volatile(
        "mma.sync.aligned.m16n8k16.row.col.f32.f16.f16.f32 "
        "{%0,%1,%2,%3}, {%4,%5,%6,%7}, {%8,%9}, {%0,%1,%2,%3};\n"
        : "+f"(c[0]), "+f"(c[1]), "+f"(c[2]), "+f"(c[3])
        : "r"(a[0]), "r"(a[1]), "r"(a[2]), "r"(a[3]), "r"(b[0]), "r"(b[1]));
}
__device__ __forceinline__ void split1(float x, hf& h, hf& l) {
    h = __float2half_rn(x);
    l = __float2half_rn(x - __half2float(h));
}
__device__ __forceinline__ unsigned packhf(hf a, hf b) {
    __half2 t(a, b);
    return *(unsigned*)&t;
}

// ---------------------------------------------------------------------------
// fp32 -> fp16 hi only
// ---------------------------------------------------------------------------
__global__ void split_h_kernel(const float* __restrict__ x,
                               hf* __restrict__ hi, int n4)
{
    int i = blockIdx.x * blockDim.x + threadIdx.x;
    if (i >= n4) return;
    float4 v = ((const float4*)x)[i];
    __half2* H = (__half2*)hi;
    H[i * 2]     = __half2(__float2half_rn(v.x), __float2half_rn(v.y));
    H[i * 2 + 1] = __half2(__float2half_rn(v.z), __float2half_rn(v.w));
}

// Fused-weight hi split: w_q_a [5120,1536] | w_kv_a [5120,576] -> [5120,2112]
__global__ void split_fuse_kernel(const float* __restrict__ wqa,
                                  const float* __restrict__ wkva,
                                  hf* __restrict__ hi)
{
    int i = blockIdx.x * blockDim.x + threadIdx.x;
    int total4 = HID * FUSED_N / 4;
    if (i >= total4) return;
    int e0 = i * 4;
    int k = e0 / FUSED_N, n = e0 % FUSED_N;
    float v[4];
    if (n + 3 < Q_RANK) {
        const float* src = wqa + (size_t)k * Q_RANK + n;
        v[0] = src[0]; v[1] = src[1]; v[2] = src[2]; v[3] = src[3];
    } else if (n >= Q_RANK) {
        const float* src = wkva + (size_t)k * KV_A_OUT + (n - Q_RANK);
        v[0] = src[0]; v[1] = src[1]; v[2] = src[2]; v[3] = src[3];
    } else {
#pragma unroll
        for (int j = 0; j < 4; j++) {
            int nn = n + j;
            v[j] = (nn < Q_RANK) ? wqa[(size_t)k * Q_RANK + nn]
                                 : wkva[(size_t)k * KV_A_OUT + (nn - Q_RANK)];
        }
    }
    hf h[4];
#pragma unroll
    for (int j = 0; j < 4; j++) h[j] = __float2half_rn(v[j]);
    *(uint2*)(hi + e0) = *(uint2*)h;
}

// ---------------------------------------------------------------------------
// fp16 tensor-core GEMM:  C = (Ah [+ Al]) @ Bh.
// CTA 128x128, BK=32, 256 threads, 3-stage cp.async, XOR-swizzled smem.
// TWO_TERM: include Al (A exact to 2^-22). OUT16: fp16 output.
// ---------------------------------------------------------------------------
#define CBM 128
#define CBN 128
#define CBK 32
#define A_TILE_B 8192
#define B_TILE_B 8192
#define STAGE_B  (2 * A_TILE_B + B_TILE_B)   // 24576
#define NSTAGE 3
#define GEMM_SMEM (NSTAGE * STAGE_B)         // 73728

template<bool OUT16, bool TWO_TERM>
__device__ __forceinline__ void gemm_cta(
    char* smem, int tid,
    const hf* __restrict__ Ah, const hf* __restrict__ Al,
    const hf* __restrict__ Bh,
    void* __restrict__ Cv, int m0, int n0, int N, int K)
{
    const int lane = tid & 31;
    const int warp = tid >> 5;
    const int wm0 = (warp >> 2) * 64;
    const int wn0 = (warp & 3) * 32;

    float acc[16][4];
#pragma unroll
    for (int i = 0; i < 16; i++)
#pragma unroll
        for (int j = 0; j < 4; j++) acc[i][j] = 0.f;

    auto load_stage = [&](int k0, int s) {
        char* base = smem + s * STAGE_B;
#pragma unroll
        for (int i = 0; i < 2; i++) {
            int ch = tid + i * 256;
            int r = ch >> 2, c = ch & 3;
            int pc = c ^ ((r >> 1) & 3);
            size_t goff = (size_t)(m0 + r) * K + k0 + c * 8;
            cp16(smem_u32(base + r * 64 + pc * 16), Ah + goff, 16);
            if (TWO_TERM)
                cp16(smem_u32(base + A_TILE_B + r * 64 + pc * 16), Al + goff, 16);
        }
#pragma unroll
        for (int i = 0; i < 2; i++) {
            int ch = tid + i * 256;
            int r = ch >> 4, c = ch & 15;
            int pc = c ^ (r & 7);
            int gn = n0 + c * 8;
            int sz = (gn < N) ? 16 : 0;
            size_t goff = (size_t)(k0 + r) * N + (gn < N ? gn : 0);
            cp16(smem_u32(base + 2 * A_TILE_B + r * 256 + pc * 16), Bh + goff, sz);
        }
    };

    auto compute_stage = [&](int s) {
        char* base = smem + s * STAGE_B;
        unsigned aH = smem_u32(base);
        unsigned aL = aH + A_TILE_B;
        unsigned bH = aH + 2 * A_TILE_B;
#pragma unroll
        for (int kk = 0; kk < 2; kk++) {
            unsigned ah[4][4], al[4][4], bh[4][2];
            const int r_lo = lane & 15;
            const int cch = kk * 2 + (lane >> 4);
#pragma unroll
            for (int mi = 0; mi < 4; mi++) {
                int r = wm0 + mi * 16 + r_lo;
                int pc = cch ^ ((r >> 1) & 3);
                unsigned off = (unsigned)(r * 64 + pc * 16);
                ldm4(ah[mi], aH + off);
                if (TWO_TERM) ldm4(al[mi], aL + off);
            }
            {
                int r = kk * 16 + (lane & 15);
#pragma unroll
                for (int ni = 0; ni < 2; ni++) {
                    int cc = ((wn0 + ni * 16) >> 3) + ((lane >> 4) & 1);
                    int pc = cc ^ (r & 7);
                    unsigned off = (unsigned)(r * 256 + pc * 16);
                    unsigned t[4];
                    ldm4t(t, bH + off);
                    bh[ni * 2][0] = t[0]; bh[ni * 2][1] = t[1];
                    bh[ni * 2 + 1][0] = t[2]; bh[ni * 2 + 1][1] = t[3];
                }
            }
#pragma unroll
            for (int mi = 0; mi < 4; mi++)
#pragma unroll
                for (int nj = 0; nj < 4; nj++) {
                    mma16816(acc[mi * 4 + nj], ah[mi], bh[nj]);
                    if (TWO_TERM) mma16816(acc[mi * 4 + nj], al[mi], bh[nj]);
                }
        }
    };

    const int KT = K / CBK;
    load_stage(0, 0); cp_commit();
    load_stage(CBK, 1); cp_commit();
    for (int kt = 0; kt < KT; kt++) {
        cp_wait<1>();
        __syncthreads();
        if (kt + 2 < KT) load_stage((kt + 2) * CBK, (kt + 2) % NSTAGE);
        cp_commit();
        compute_stage(kt % NSTAGE);
    }

#pragma unroll
    for (int mi = 0; mi < 4; mi++) {
        int row = m0 + wm0 + mi * 16 + (lane >> 2);
#pragma unroll
        for (int nj = 0; nj < 4; nj++) {
            int col = n0 + wn0 + nj * 8 + (lane & 3) * 2;
            if (col < N) {
                float* a = acc[mi * 4 + nj];
                if (OUT16) {
                    hf* C = (hf*)Cv;
                    *(__half2*)(C + (size_t)row * N + col) =
                        __half2(__float2half_rn(a[0]), __float2half_rn(a[1]));
                    *(__half2*)(C + (size_t)(row + 8) * N + col) =
                        __half2(__float2half_rn(a[2]), __float2half_rn(a[3]));
                } else {
                    float* C = (float*)Cv;
                    *(float2*)(C + (size_t)row * N + col)       = make_float2(a[0], a[1]);
                    *(float2*)(C + (size_t)(row + 8) * N + col) = make_float2(a[2], a[3]);
                }
            }
        }
    }
}

// Single-term GEMM (A hi only), fp32 out.
__global__ __launch_bounds__(256) void mma_gemm1_kernel(
    const hf* __restrict__ Ah,
    const hf* __restrict__ Bh,
    float* __restrict__ C, int M, int N, int K)
{
    extern __shared__ char smem[];
    gemm_cta<false, false>(smem, threadIdx.x, Ah, nullptr, Bh, C,
                           blockIdx.y * CBM, blockIdx.x * CBN, N, K);
}

// Dual GEMM: problem 1 (fp32 out) on first nblk1 n-tiles; problem 2 (fp16 out).
__global__ __launch_bounds__(256) void mma_gemm_dual_kernel(
    const hf* __restrict__ Ah1, const hf* __restrict__ Al1,
    const hf* __restrict__ Bh1,
    float* __restrict__ C1, int N1, int K1, int nblk1,
    const hf* __restrict__ Ah2, const hf* __restrict__ Al2,
    const hf* __restrict__ Bh2,
    hf* __restrict__ C2, int N2, int K2)
{
    extern __shared__ char smem[];
    const int m0 = blockIdx.y * CBM;
    if ((int)blockIdx.x < nblk1) {
        gemm_cta<false, true>(smem, threadIdx.x, Ah1, Al1, Bh1, C1,
                              m0, blockIdx.x * CBN, N1, K1);
    } else {
        gemm_cta<true, true>(smem, threadIdx.x, Ah2, Al2, Bh2, C2,
                             m0, (blockIdx.x - nblk1) * CBN, N2, K2);
    }
}

// ---------------------------------------------------------------------------
// RMSNorm + split (input row stride decoupled from width)
// ---------------------------------------------------------------------------
__global__ void rmsnorm_split_kernel(const float* __restrict__ in,
                                     const float* __restrict__ w,
                                     hf* __restrict__ ohi, hf* __restrict__ olo,
                                     int W, int in_stride)
{
    const int t = blockIdx.x;
    const float* row = in + (size_t)t * in_stride;

    float ss = 0.f;
    for (int i = threadIdx.x; i < W; i += blockDim.x) {
        float v = row[i];
        ss += v * v;
    }
    __shared__ float red[32];
#pragma unroll
    for (int o = 16; o; o >>= 1) ss += __shfl_xor_sync(0xffffffffu, ss, o);
    if ((threadIdx.x & 31) == 0) red[threadIdx.x >> 5] = ss;
    __syncthreads();
    if (threadIdx.x < 32) {
        float v = (threadIdx.x < (blockDim.x >> 5)) ? red[threadIdx.x] : 0.f;
#pragma unroll
        for (int o = 16; o; o >>= 1) v += __shfl_xor_sync(0xffffffffu, v, o);
        if (threadIdx.x == 0) red[0] = v;
    }
    __syncthreads();
    const float inv = rsqrtf(red[0] / (float)W + 1e-6f);
    for (int i = threadIdx.x; i < W; i += blockDim.x) {
        float y = row[i] * inv * w[i];
        hf h, l;
        split1(y, h, l);
        ohi[(size_t)t * W + i] = h;
        olo[(size_t)t * W + i] = l;
    }
}

// ---------------------------------------------------------------------------
// Prep: RoPE q_pe (in place) + k_pe (-> fp16 kpe), fold (scaling / sqrt(192))
// into q, emit head-major Q hi/lo (fp16).
// ---------------------------------------------------------------------------
__global__ void prep_kernel(const int* __restrict__ positions,
                            const float* __restrict__ cs_cache,
                            const float* __restrict__ scaling,
                            const float* __restrict__ latent, int lat_stride,
                            float* __restrict__ qb,          // [T,16,192] in/out
                            hf* __restrict__ qh, hf* __restrict__ ql,
                            hf* __restrict__ kpe)            // [T,64] fp16
{
    const int t = blockIdx.x;
    const int pos = positions[t];
    const float* cs = cs_cache + (size_t)pos * DR;
    const float qsc = scaling[t] * 0.07216878364870322f;  // llama4 * 1/sqrt(192)
    float* qrow = qb + (size_t)t * (NH * DQK);

    for (int idx = threadIdx.x; idx < NH * 32; idx += blockDim.x) {
        int hh = idx >> 5, i = idx & 31;
        float c = cs[i], s = cs[32 + i];
        float x1 = qrow[hh * DQK + DN + i];
        float x2 = qrow[hh * DQK + DN + 32 + i];
        qrow[hh * DQK + DN + i]      = x1 * c - x2 * s;
        qrow[hh * DQK + DN + 32 + i] = x2 * c + x1 * s;
    }
    if (threadIdx.x < 32) {
        int i = threadIdx.x;
        float c = cs[i], s = cs[32 + i];
        float x1 = latent[(size_t)t * lat_stride + KV_RANK + i];
        float x2 = latent[(size_t)t * lat_stride + KV_RANK + 32 + i];
        kpe[t * DR + i]      = __float2half_rn(x1 * c - x2 * s);
        kpe[t * DR + 32 + i] = __float2half_rn(x2 * c + x1 * s);
    }
    __syncthreads();
    for (int idx = threadIdx.x; idx < NH * DQK; idx += blockDim.x) {
        int hh = idx / DQK, d = idx % DQK;
        size_t o = ((size_t)hh * T_TOK + t) * DQK + d;
        hf hi, lo;
        split1(qrow[idx] * qsc, hi, lo);
        qh[o] = hi; ql[o] = lo;
    }
}

// ---------------------------------------------------------------------------
// Tensor-core flash attention (fp16 2-term, causal).
// Q exact (hi+lo); K nope + V direct from fp16 kv buffer [T,16,256];
// k_pe from [T,64]. P exact (hi+lo). Output: plain fp16.
// ---------------------------------------------------------------------------
#define AM 128
#define AN 64
#define FQH 0
#define FQL (FQH + AM*384)
#define FKH (FQL + AM*384)
#define FVH (FKH + AN*384)
#define FLASH_SMEM (FVH + AN*256)    // 139264 B

__global__ __launch_bounds__(256) void flash_mma_kernel(
    const hf* __restrict__ qh, const hf* __restrict__ ql,
    const hf* __restrict__ kv16,   // [T, 16*256]
    const hf* __restrict__ kpe,    // [T, 64]
    hf* __restrict__ attn)
{
    extern __shared__ char smem[];
    const int m0 = blockIdx.x * AM;
    const int h  = blockIdx.y;
    const int tid = threadIdx.x, lane = tid & 31, warp = tid >> 5;
    const int wm = warp * 16;
    const float L2E = 1.4426950408889634f;

    {
        const hf* qh_g = qh + ((size_t)h * T_TOK + m0) * DQK;
        const hf* ql_g = ql + ((size_t)h * T_TOK + m0) * DQK;
        for (int i = tid; i < AM * 24; i += 256) {
            int r = i / 24, c = i % 24, pc = c ^ (r & 7);
            cp16(smem_u32(smem + FQH + r * 384 + pc * 16), qh_g + (size_t)r * DQK + c * 8, 16);
            cp16(smem_u32(smem + FQL + r * 384 + pc * 16), ql_g + (size_t)r * DQK + c * 8, 16);
        }
        cp_commit();
    }

    float o[16][4];
#pragma unroll
    for (int i = 0; i < 16; i++)
#pragma unroll
        for (int j = 0; j < 4; j++) o[i][j] = 0.f;
    float m0r = -1e30f, m1r = -1e30f, l0 = 0.f, l1 = 0.f;

    const unsigned aQh = smem_u32(smem + FQH), aQl = smem_u32(smem + FQL);
    const unsigned aKh = smem_u32(smem + FKH);
    const unsigned aVh = smem_u32(smem + FVH);

    const int ntiles = 2 * blockIdx.x + 2;
    for (int nt = 0; nt < ntiles; nt++) {
        const int n0 = nt * AN;
        __syncthreads();
        {
            const hf* kv_g = kv16 + (size_t)n0 * (NH * KV_OUT) + h * KV_OUT;
            const hf* pe_g = kpe + (size_t)n0 * DR;
            for (int i = tid; i < AN * 24; i += 256) {
                int r = i / 24, c = i % 24, pc = c ^ (r & 7);
                const hf* src = (c < 16)
                    ? kv_g + (size_t)r * (NH * KV_OUT) + c * 8
                    : pe_g + (size_t)r * DR + (c - 16) * 8;
                cp16(smem_u32(smem + FKH + r * 384 + pc * 16), src, 16);
            }
            const hf* v_g = kv_g + DN;
            for (int i = tid; i < AN * 16; i += 256) {
                int r = i >> 4, c = i & 15, pc = c ^ (r & 7);
                cp16(smem_u32(smem + FVH + r * 256 + pc * 16),
                     v_g + (size_t)r * (NH * KV_OUT) + c * 8, 16);
            }
        }
        cp_commit();
        cp_wait<0>();
        __syncthreads();

        float s[8][4];
#pragma unroll
        for (int j = 0; j < 8; j++)
#pragma unroll
            for (int c = 0; c < 4; c++) s[j][c] = 0.f;

#pragma unroll
        for (int kt = 0; kt < 12; kt++) {
            unsigned ah[4], al[4];
            {
                int r = wm + (lane & 15), c = kt * 2 + (lane >> 4);
                int pc = c ^ (r & 7);
                unsigned off = (unsigned)(r * 384 + pc * 16);
                ldm4(ah, aQh + off);
                ldm4(al, aQl + off);
            }
#pragma unroll
            for (int kb = 0; kb < 4; kb++) {
                int r = kb * 16 + (lane & 15), c = kt * 2 + (lane >> 4);
                int pc = c ^ (r & 7);
                unsigned off = (unsigned)(r * 384 + pc * 16);
                unsigned tb[4];
                ldm4(tb, aKh + off);
                unsigned bh0[2] = {tb[0], tb[2]}, bh1[2] = {tb[1], tb[3]};
                mma16816(s[kb * 2], ah, bh0);
                mma16816(s[kb * 2], al, bh0);
                mma16816(s[kb * 2 + 1], ah, bh1);
                mma16816(s[kb * 2 + 1], al, bh1);
            }
        }

        if (n0 + AN > m0) {
            int q0 = m0 + wm + (lane >> 2);
#pragma unroll
            for (int j = 0; j < 8; j++) {
                int k0 = n0 + j * 8 + (lane & 3) * 2;
                if (k0     > q0)     s[j][0] = -1e30f;
                if (k0 + 1 > q0)     s[j][1] = -1e30f;
                if (k0     > q0 + 8) s[j][2] = -1e30f;
                if (k0 + 1 > q0 + 8) s[j][3] = -1e30f;
            }
        }

        float mx0 = -1e30f, mx1 = -1e30f;
#pragma unroll
        for (int j = 0; j < 8; j++) {
            mx0 = fmaxf(mx0, fmaxf(s[j][0], s[j][1]));
            mx1 = fmaxf(mx1, fmaxf(s[j][2], s[j][3]));
        }
        mx0 = fmaxf(mx0, __shfl_xor_sync(0xffffffffu, mx0, 1));
        mx0 = fmaxf(mx0, __shfl_xor_sync(0xffffffffu, mx0, 2));
        mx1 = fmaxf(mx1, __shfl_xor_sync(0xffffffffu, mx1, 1));
        mx1 = fmaxf(mx1, __shfl_xor_sync(0xffffffffu, mx1, 2));
        float mn0 = fmaxf(m0r, mx0), mn1 = fmaxf(m1r, mx1);
        float f0 = exp2f((m0r - mn0) * L2E), f1 = exp2f((m1r - mn1) * L2E);
        m0r = mn0; m1r = mn1;

        unsigned ph[8], ph2[8], pl[8], pl2[8];
        float sum0 = 0.f, sum1 = 0.f;
#pragma unroll
        for (int j = 0; j < 8; j++) {
            float p0 = exp2f((s[j][0] - mn0) * L2E);
            float p1 = exp2f((s[j][1] - mn0) * L2E);
            float p2 = exp2f((s[j][2] - mn1) * L2E);
            float p3 = exp2f((s[j][3] - mn1) * L2E);
            sum0 += p0 + p1; sum1 += p2 + p3;
            hf a, b, c, d;
            split1(p0, a, c); split1(p1, b, d);
            ph[j] = packhf(a, b); pl[j] = packhf(c, d);
            split1(p2, a, c); split1(p3, b, d);
            ph2[j] = packhf(a, b); pl2[j] = packhf(c, d);
        }
        sum0 += __shfl_xor_sync(0xffffffffu, sum0, 1);
        sum0 += __shfl_xor_sync(0xffffffffu, sum0, 2);
        sum1 += __shfl_xor_sync(0xffffffffu, sum1, 1);
        sum1 += __shfl_xor_sync(0xffffffffu, sum1, 2);
        l0 = l0 * f0 + sum0;
        l1 = l1 * f1 + sum1;
#pragma unroll
        for (int j = 0; j < 16; j++) {
            o[j][0] *= f0; o[j][1] *= f0; o[j][2] *= f1; o[j][3] *= f1;
        }

#pragma unroll
        for (int kt = 0; kt < 4; kt++) {
            unsigned ahp[4] = {ph[2 * kt], ph2[2 * kt], ph[2 * kt + 1], ph2[2 * kt + 1]};
            unsigned alp[4] = {pl[2 * kt], pl2[2 * kt], pl[2 * kt + 1], pl2[2 * kt + 1]};
#pragma unroll
            for (int nv = 0; nv < 8; nv++) {
                int r = kt * 16 + (lane & 15), c = nv * 2 + (lane >> 4);
                int pc = c ^ (r & 7);
                unsigned off = (unsigned)(r * 256 + pc * 16);
                unsigned tb[4];
                ldm4t(tb, aVh + off);
                unsigned bh0[2] = {tb[0], tb[1]}, bh1[2] = {tb[2], tb[3]};
                mma16816(o[nv * 2], ahp, bh0);
                mma16816(o[nv * 2], alp, bh0);
                mma16816(o[nv * 2 + 1], ahp, bh1);
                mma16816(o[nv * 2 + 1], alp, bh1);
            }
        }
    }

    float il0 = 1.f / l0, il1 = 1.f / l1;
    int r0 = m0 + wm + (lane >> 2);
#pragma unroll
    for (int j = 0; j < 16; j++) {
        int dv = j * 8 + (lane & 3) * 2;
        size_t off = (size_t)r0 * (NH * DV) + h * DV + dv;
        *(__half2*)(attn + off) =
            __half2(__float2half_rn(o[j][0] * il0), __float2half_rn(o[j][1] * il0));
        off += (size_t)8 * (NH * DV);
        *(__half2*)(attn + off) =
            __half2(__float2half_rn(o[j][2] * il1), __float2half_rn(o[j][3] * il1));
    }
}

// ---------------------------------------------------------------------------
// Launch
// ---------------------------------------------------------------------------
static inline void launch_split_h(const float* x, hf* hi, int n) {
    int n4 = n / 4;
    split_h_kernel<<<(n4 + 255) / 256, 256>>>(x, hi, n4);
}

extern "C" void kernel_launch(void* const* d_in, const int* in_sizes, int n_in,
                              void* d_out, int out_size)
{
    const int*   positions = (const int*)  d_in[0];
    const float* hidden    = (const float*)d_in[1];
    const float* scaling   = (const float*)d_in[2];
    const float* w_q_a     = (const float*)d_in[3];
    const float* q_a_ln_w  = (const float*)d_in[4];
    const float* w_q_b     = (const float*)d_in[5];
    const float* w_kv_a    = (const float*)d_in[6];
    const float* kv_a_ln_w = (const float*)d_in[7];
    const float* w_kv_b    = (const float*)d_in[8];
    const float* w_o       = (const float*)d_in[9];
    const float* cs_cache  = (const float*)d_in[10];
    float* out = (float*)d_out;

    hf *Hh, *Wa_h, *Wqb_h, *Wkvb_h, *Wo_h;
    hf *qa_h, *qa_l, *kvan_h, *kvan_l;
    hf *qhp, *qlp, *kv16, *kpe, *attn;
    float *qalat, *qb;
    cudaGetSymbolAddress((void**)&Hh, g_Hh);
    cudaGetSymbolAddress((void**)&Wa_h, g_Wa_h);
    cudaGetSymbolAddress((void**)&Wqb_h, g_Wqb_h);
    cudaGetSymbolAddress((void**)&Wkvb_h, g_Wkvb_h);
    cudaGetSymbolAddress((void**)&Wo_h, g_Wo_h);
    cudaGetSymbolAddress((void**)&qa_h, g_qa_h);   cudaGetSymbolAddress((void**)&qa_l, g_qa_l);
    cudaGetSymbolAddress((void**)&kvan_h, g_kvan_h); cudaGetSymbolAddress((void**)&kvan_l, g_kvan_l);
    cudaGetSymbolAddress((void**)&qhp, g_qh); cudaGetSymbolAddress((void**)&qlp, g_ql);
    cudaGetSymbolAddress((void**)&kv16, g_kv16);
    cudaGetSymbolAddress((void**)&kpe, g_kpe);
    cudaGetSymbolAddress((void**)&attn, g_attn);
    cudaGetSymbolAddress((void**)&qalat, g_qalat);
    cudaGetSymbolAddress((void**)&qb, g_q);

    cudaFuncSetAttribute(mma_gemm1_kernel, cudaFuncAttributeMaxDynamicSharedMemorySize,
                         GEMM_SMEM);
    cudaFuncSetAttribute(mma_gemm_dual_kernel, cudaFuncAttributeMaxDynamicSharedMemorySize,
                         GEMM_SMEM);
    cudaFuncSetAttribute(flash_mma_kernel, cudaFuncAttributeMaxDynamicSharedMemorySize,
                         FLASH_SMEM);

    // 1. splits: hidden hi only; weights hi only (fused w_q_a|w_kv_a)
    launch_split_h(hidden, Hh, T_TOK * HID);
    {
        int total4 = HID * FUSED_N / 4;
        split_fuse_kernel<<<(total4 + 255) / 256, 256>>>(w_q_a, w_kv_a, Wa_h);
    }
    launch_split_h(w_q_b, Wqb_h, Q_RANK * NH * DQK);
    launch_split_h(w_kv_b, Wkvb_h, KV_RANK * NH * KV_OUT);
    launch_split_h(w_o, Wo_h, NH * DV * HID);

    const dim3 blk(256);
    const int MT = T_TOK / CBM;  // 24

    // 2. [qa | latent] = hidden @ [w_q_a | w_kv_a]  (single-term, hi only)
    mma_gemm1_kernel<<<dim3((FUSED_N + CBN - 1) / CBN, MT), blk, GEMM_SMEM>>>(
        Hh, Wa_h, qalat, T_TOK, FUSED_N, HID);
    // 3. rmsnorm + split (exact hi/lo; feeds 2-term dual GEMM)
    rmsnorm_split_kernel<<<T_TOK, 256>>>(qalat, q_a_ln_w, qa_h, qa_l, Q_RANK, FUSED_N);
    rmsnorm_split_kernel<<<T_TOK, 256>>>(qalat + Q_RANK, kv_a_ln_w, kvan_h, kvan_l,
                                         KV_RANK, FUSED_N);
    // 4+5 fused: q (fp32 out) AND kv (fp16 out, consumed directly by flash)
    {
        const int nblk_q  = (NH * DQK) / CBN;    // 24
        const int nblk_kv = (NH * KV_OUT) / CBN; // 32
        mma_gemm_dual_kernel<<<dim3(nblk_q + nblk_kv, MT), blk, GEMM_SMEM>>>(
            qa_h, qa_l, Wqb_h, qb, NH * DQK, Q_RANK, nblk_q,
            kvan_h, kvan_l, Wkvb_h, kv16, NH * KV_OUT, KV_RANK);
    }
    // 6. rope + scale + head-major Q; k_pe -> fp16
    prep_kernel<<<T_TOK, 256>>>(positions, cs_cache, scaling,
                                qalat + Q_RANK, FUSED_N, qb, qhp, qlp, kpe);
    // 7. flash attention (fp16 output)
    flash_mma_kernel<<<dim3(T_TOK / AM, NH), 256, FLASH_SMEM>>>(
        qhp, qlp, kv16, kpe, attn);
    // 8. out = attn @ w_o  (single-term)
    mma_gemm1_kernel<<<dim3(HID / CBN, MT), blk, GEMM_SMEM>>>(
        attn, Wo_h, out, T_TOK, HID, NH * DV);
}

// round 13
// speedup vs baseline: 1.3921x; 1.0892x over previous
#include <cuda_runtime.h>
#include <cuda_fp16.h>
#include <math.h>

// Problem constants
#define T_TOK 3072
#define HID 5120
#define NH 16
#define DN 128
#define DR 64
#define DQK 192       // DN + DR
#define DV 128
#define Q_RANK 1536
#define KV_RANK 512
#define KV_A_OUT (KV_RANK + DR)   // 576
#define KV_OUT (DN + DV)          // 256
#define FUSED_N (Q_RANK + KV_A_OUT)   // 2112

typedef __half hf;

// ---------------------------------------------------------------------------
// Scratch (allocation-free: __device__ globals)
// ---------------------------------------------------------------------------
__device__ hf g_Hh[T_TOK * HID];                     // hidden hi only
__device__ hf g_Wa_h[HID * FUSED_N];                 // fused [5120,2112] hi
__device__ hf g_Wqb_h[Q_RANK * NH * DQK];
__device__ hf g_Wkvb_h[KV_RANK * NH * KV_OUT];
__device__ hf g_Wo_h[NH * DV * HID];
__device__ float g_qalat[T_TOK * FUSED_N];           // fused qa | latent (fp32)
__device__ hf g_qa_h[T_TOK * Q_RANK];
__device__ hf g_kvan_h[T_TOK * KV_RANK];
__device__ float g_q[T_TOK * NH * DQK];
__device__ hf g_kv16[T_TOK * NH * KV_OUT];           // kv GEMM out, fp16 direct
__device__ hf g_kpe[T_TOK * DR];                     // roped k_pe, fp16
// head-major Q for flash
__device__ hf g_qh[NH * T_TOK * DQK], g_ql[NH * T_TOK * DQK];
__device__ hf g_attn[T_TOK * NH * DV];               // attn out, fp16 single

// ---------------------------------------------------------------------------
// PTX helpers
// ---------------------------------------------------------------------------
__device__ __forceinline__ unsigned smem_u32(const void* p) {
    return (unsigned)__cvta_generic_to_shared(p);
}
__device__ __forceinline__ void cp16(unsigned s, const void* g, int srcsz) {
    asm volatile("cp.async.cg.shared.global [%0], [%1], 16, %2;\n"
                 :: "r"(s), "l"(g), "r"(srcsz));
}
__device__ __forceinline__ void cp_commit() {
    asm volatile("cp.async.commit_group;\n" ::);
}
template<int N> __device__ __forceinline__ void cp_wait() {
    asm volatile("cp.async.wait_group %0;\n" :: "n"(N));
}
__device__ __forceinline__ void ldm4(unsigned* d, unsigned a) {
    asm volatile("ldmatrix.sync.aligned.m8n8.x4.shared.b16 {%0,%1,%2,%3}, [%4];\n"
                 : "=r"(d[0]), "=r"(d[1]), "=r"(d[2]), "=r"(d[3]) : "r"(a));
}
__device__ __forceinline__ void ldm4t(unsigned* d, unsigned a) {
    asm volatile("ldmatrix.sync.aligned.m8n8.x4.trans.shared.b16 {%0,%1,%2,%3}, [%4];\n"
                 : "=r"(d[0]), "=r"(d[1]), "=r"(d[2]), "=r"(d[3]) : "r"(a));
}
__device__ __forceinline__ void mma16816(float* c, const unsigned* a, const unsigned* b) {
    asm volatile(
        "mma.sync.aligned.m16n8k16.row.col.f32.f16.f16.f32 "
        "{%0,%1,%2,%3}, {%4,%5,%6,%7}, {%8,%9}, {%0,%1,%2,%3};\n"
        : "+f"(c[0]), "+f"(c[1]), "+f"(c[2]), "+f"(c[3])
        : "r"(a[0]), "r"(a[1]), "r"(a[2]), "r"(a[3]), "r"(b[0]), "r"(b[1]));
}
__device__ __forceinline__ void split1(float x, hf& h, hf& l) {
    h = __float2half_rn(x);
    l = __float2half_rn(x - __half2float(h));
}
__device__ __forceinline__ unsigned packhf(hf a, hf b) {
    __half2 t(a, b);
    return *(unsigned*)&t;
}

// ---------------------------------------------------------------------------
// fp32 -> fp16 hi only
// ---------------------------------------------------------------------------
__global__ void split_h_kernel(const float* __restrict__ x,
                               hf* __restrict__ hi, int n4)
{
    int i = blockIdx.x * blockDim.x + threadIdx.x;
    if (i >= n4) return;
    float4 v = ((const float4*)x)[i];
    __half2* H = (__half2*)hi;
    H[i * 2]     = __half2(__float2half_rn(v.x), __float2half_rn(v.y));
    H[i * 2 + 1] = __half2(__float2half_rn(v.z), __float2half_rn(v.w));
}

// Fused-weight hi split: w_q_a [5120,1536] | w_kv_a [5120,576] -> [5120,2112]
__global__ void split_fuse_kernel(const float* __restrict__ wqa,
                                  const float* __restrict__ wkva,
                                  hf* __restrict__ hi)
{
    int i = blockIdx.x * blockDim.x + threadIdx.x;
    int total4 = HID * FUSED_N / 4;
    if (i >= total4) return;
    int e0 = i * 4;
    int k = e0 / FUSED_N, n = e0 % FUSED_N;
    float v[4];
    if (n + 3 < Q_RANK) {
        const float* src = wqa + (size_t)k * Q_RANK + n;
        v[0] = src[0]; v[1] = src[1]; v[2] = src[2]; v[3] = src[3];
    } else if (n >= Q_RANK) {
        const float* src = wkva + (size_t)k * KV_A_OUT + (n - Q_RANK);
        v[0] = src[0]; v[1] = src[1]; v[2] = src[2]; v[3] = src[3];
    } else {
#pragma unroll
        for (int j = 0; j < 4; j++) {
            int nn = n + j;
            v[j] = (nn < Q_RANK) ? wqa[(size_t)k * Q_RANK + nn]
                                 : wkva[(size_t)k * KV_A_OUT + (nn - Q_RANK)];
        }
    }
    hf h[4];
#pragma unroll
    for (int j = 0; j < 4; j++) h[j] = __float2half_rn(v[j]);
    *(uint2*)(hi + e0) = *(uint2*)h;
}

// ---------------------------------------------------------------------------
// fp16 tensor-core GEMM:  C = (Ah [+ Al]) @ Bh.
// CTA 128x128, BK=32, 256 threads, 3-stage cp.async, XOR-swizzled smem.
// ---------------------------------------------------------------------------
#define CBM 128
#define CBN 128
#define CBK 32
#define A_TILE_B 8192
#define B_TILE_B 8192
#define STAGE_B  (2 * A_TILE_B + B_TILE_B)   // 24576
#define NSTAGE 3
#define GEMM_SMEM (NSTAGE * STAGE_B)         // 73728

template<bool OUT16, bool TWO_TERM>
__device__ __forceinline__ void gemm_cta(
    char* smem, int tid,
    const hf* __restrict__ Ah, const hf* __restrict__ Al,
    const hf* __restrict__ Bh,
    void* __restrict__ Cv, int m0, int n0, int N, int K)
{
    const int lane = tid & 31;
    const int warp = tid >> 5;
    const int wm0 = (warp >> 2) * 64;
    const int wn0 = (warp & 3) * 32;

    float acc[16][4];
#pragma unroll
    for (int i = 0; i < 16; i++)
#pragma unroll
        for (int j = 0; j < 4; j++) acc[i][j] = 0.f;

    auto load_stage = [&](int k0, int s) {
        char* base = smem + s * STAGE_B;
#pragma unroll
        for (int i = 0; i < 2; i++) {
            int ch = tid + i * 256;
            int r = ch >> 2, c = ch & 3;
            int pc = c ^ ((r >> 1) & 3);
            size_t goff = (size_t)(m0 + r) * K + k0 + c * 8;
            cp16(smem_u32(base + r * 64 + pc * 16), Ah + goff, 16);
            if (TWO_TERM)
                cp16(smem_u32(base + A_TILE_B + r * 64 + pc * 16), Al + goff, 16);
        }
#pragma unroll
        for (int i = 0; i < 2; i++) {
            int ch = tid + i * 256;
            int r = ch >> 4, c = ch & 15;
            int pc = c ^ (r & 7);
            int gn = n0 + c * 8;
            int sz = (gn < N) ? 16 : 0;
            size_t goff = (size_t)(k0 + r) * N + (gn < N ? gn : 0);
            cp16(smem_u32(base + 2 * A_TILE_B + r * 256 + pc * 16), Bh + goff, sz);
        }
    };

    auto compute_stage = [&](int s) {
        char* base = smem + s * STAGE_B;
        unsigned aH = smem_u32(base);
        unsigned aL = aH + A_TILE_B;
        unsigned bH = aH + 2 * A_TILE_B;
#pragma unroll
        for (int kk = 0; kk < 2; kk++) {
            unsigned ah[4][4], al[4][4], bh[4][2];
            const int r_lo = lane & 15;
            const int cch = kk * 2 + (lane >> 4);
#pragma unroll
            for (int mi = 0; mi < 4; mi++) {
                int r = wm0 + mi * 16 + r_lo;
                int pc = cch ^ ((r >> 1) & 3);
                unsigned off = (unsigned)(r * 64 + pc * 16);
                ldm4(ah[mi], aH + off);
                if (TWO_TERM) ldm4(al[mi], aL + off);
            }
            {
                int r = kk * 16 + (lane & 15);
#pragma unroll
                for (int ni = 0; ni < 2; ni++) {
                    int cc = ((wn0 + ni * 16) >> 3) + ((lane >> 4) & 1);
                    int pc = cc ^ (r & 7);
                    unsigned off = (unsigned)(r * 256 + pc * 16);
                    unsigned t[4];
                    ldm4t(t, bH + off);
                    bh[ni * 2][0] = t[0]; bh[ni * 2][1] = t[1];
                    bh[ni * 2 + 1][0] = t[2]; bh[ni * 2 + 1][1] = t[3];
                }
            }
#pragma unroll
            for (int mi = 0; mi < 4; mi++)
#pragma unroll
                for (int nj = 0; nj < 4; nj++) {
                    mma16816(acc[mi * 4 + nj], ah[mi], bh[nj]);
                    if (TWO_TERM) mma16816(acc[mi * 4 + nj], al[mi], bh[nj]);
                }
        }
    };

    const int KT = K / CBK;
    load_stage(0, 0); cp_commit();
    load_stage(CBK, 1); cp_commit();
    for (int kt = 0; kt < KT; kt++) {
        cp_wait<1>();
        __syncthreads();
        if (kt + 2 < KT) load_stage((kt + 2) * CBK, (kt + 2) % NSTAGE);
        cp_commit();
        compute_stage(kt % NSTAGE);
    }

#pragma unroll
    for (int mi = 0; mi < 4; mi++) {
        int row = m0 + wm0 + mi * 16 + (lane >> 2);
#pragma unroll
        for (int nj = 0; nj < 4; nj++) {
            int col = n0 + wn0 + nj * 8 + (lane & 3) * 2;
            if (col < N) {
                float* a = acc[mi * 4 + nj];
                if (OUT16) {
                    hf* C = (hf*)Cv;
                    *(__half2*)(C + (size_t)row * N + col) =
                        __half2(__float2half_rn(a[0]), __float2half_rn(a[1]));
                    *(__half2*)(C + (size_t)(row + 8) * N + col) =
                        __half2(__float2half_rn(a[2]), __float2half_rn(a[3]));
                } else {
                    float* C = (float*)Cv;
                    *(float2*)(C + (size_t)row * N + col)       = make_float2(a[0], a[1]);
                    *(float2*)(C + (size_t)(row + 8) * N + col) = make_float2(a[2], a[3]);
                }
            }
        }
    }
}

// Single-term GEMM (A hi only), fp32 out.
__global__ __launch_bounds__(256) void mma_gemm1_kernel(
    const hf* __restrict__ Ah,
    const hf* __restrict__ Bh,
    float* __restrict__ C, int M, int N, int K)
{
    extern __shared__ char smem[];
    gemm_cta<false, false>(smem, threadIdx.x, Ah, nullptr, Bh, C,
                           blockIdx.y * CBM, blockIdx.x * CBN, N, K);
}

// Dual single-term GEMM: problem 1 (fp32 out) on first nblk1 n-tiles;
// problem 2 (fp16 out) on the rest.
__global__ __launch_bounds__(256) void mma_gemm_dual_kernel(
    const hf* __restrict__ Ah1, const hf* __restrict__ Bh1,
    float* __restrict__ C1, int N1, int K1, int nblk1,
    const hf* __restrict__ Ah2, const hf* __restrict__ Bh2,
    hf* __restrict__ C2, int N2, int K2)
{
    extern __shared__ char smem[];
    const int m0 = blockIdx.y * CBM;
    if ((int)blockIdx.x < nblk1) {
        gemm_cta<false, false>(smem, threadIdx.x, Ah1, nullptr, Bh1, C1,
                               m0, blockIdx.x * CBN, N1, K1);
    } else {
        gemm_cta<true, false>(smem, threadIdx.x, Ah2, nullptr, Bh2, C2,
                              m0, (blockIdx.x - nblk1) * CBN, N2, K2);
    }
}

// ---------------------------------------------------------------------------
// RMSNorm -> fp16 hi only (input row stride decoupled from width)
// ---------------------------------------------------------------------------
__global__ void rmsnorm_h_kernel(const float* __restrict__ in,
                                 const float* __restrict__ w,
                                 hf* __restrict__ ohi,
                                 int W, int in_stride)
{
    const int t = blockIdx.x;
    const float* row = in + (size_t)t * in_stride;

    float ss = 0.f;
    for (int i = threadIdx.x; i < W; i += blockDim.x) {
        float v = row[i];
        ss += v * v;
    }
    __shared__ float red[32];
#pragma unroll
    for (int o = 16; o; o >>= 1) ss += __shfl_xor_sync(0xffffffffu, ss, o);
    if ((threadIdx.x & 31) == 0) red[threadIdx.x >> 5] = ss;
    __syncthreads();
    if (threadIdx.x < 32) {
        float v = (threadIdx.x < (blockDim.x >> 5)) ? red[threadIdx.x] : 0.f;
#pragma unroll
        for (int o = 16; o; o >>= 1) v += __shfl_xor_sync(0xffffffffu, v, o);
        if (threadIdx.x == 0) red[0] = v;
    }
    __syncthreads();
    const float inv = rsqrtf(red[0] / (float)W + 1e-6f);
    for (int i = threadIdx.x; i < W; i += blockDim.x)
        ohi[(size_t)t * W + i] = __float2half_rn(row[i] * inv * w[i]);
}

// ---------------------------------------------------------------------------
// Prep: RoPE q_pe (in place) + k_pe (-> fp16 kpe), fold (scaling / sqrt(192))
// into q, emit head-major Q hi/lo (fp16).
// ---------------------------------------------------------------------------
__global__ void prep_kernel(const int* __restrict__ positions,
                            const float* __restrict__ cs_cache,
                            const float* __restrict__ scaling,
                            const float* __restrict__ latent, int lat_stride,
                            float* __restrict__ qb,          // [T,16,192] in/out
                            hf* __restrict__ qh, hf* __restrict__ ql,
                            hf* __restrict__ kpe)            // [T,64] fp16
{
    const int t = blockIdx.x;
    const int pos = positions[t];
    const float* cs = cs_cache + (size_t)pos * DR;
    const float qsc = scaling[t] * 0.07216878364870322f;  // llama4 * 1/sqrt(192)
    float* qrow = qb + (size_t)t * (NH * DQK);

    for (int idx = threadIdx.x; idx < NH * 32; idx += blockDim.x) {
        int hh = idx >> 5, i = idx & 31;
        float c = cs[i], s = cs[32 + i];
        float x1 = qrow[hh * DQK + DN + i];
        float x2 = qrow[hh * DQK + DN + 32 + i];
        qrow[hh * DQK + DN + i]      = x1 * c - x2 * s;
        qrow[hh * DQK + DN + 32 + i] = x2 * c + x1 * s;
    }
    if (threadIdx.x < 32) {
        int i = threadIdx.x;
        float c = cs[i], s = cs[32 + i];
        float x1 = latent[(size_t)t * lat_stride + KV_RANK + i];
        float x2 = latent[(size_t)t * lat_stride + KV_RANK + 32 + i];
        kpe[t * DR + i]      = __float2half_rn(x1 * c - x2 * s);
        kpe[t * DR + 32 + i] = __float2half_rn(x2 * c + x1 * s);
    }
    __syncthreads();
    for (int idx = threadIdx.x; idx < NH * DQK; idx += blockDim.x) {
        int hh = idx / DQK, d = idx % DQK;
        size_t o = ((size_t)hh * T_TOK + t) * DQK + d;
        hf hi, lo;
        split1(qrow[idx] * qsc, hi, lo);
        qh[o] = hi; ql[o] = lo;
    }
}

// ---------------------------------------------------------------------------
// Tensor-core flash attention (fp16 2-term, causal).
// Q exact (hi+lo); K nope + V direct from fp16 kv buffer [T,16,256];
// k_pe from [T,64]. P exact (hi+lo). Output: plain fp16.
// ---------------------------------------------------------------------------
#define AM 128
#define AN 64
#define FQH 0
#define FQL (FQH + AM*384)
#define FKH (FQL + AM*384)
#define FVH (FKH + AN*384)
#define FLASH_SMEM (FVH + AN*256)    // 139264 B

__global__ __launch_bounds__(256) void flash_mma_kernel(
    const hf* __restrict__ qh, const hf* __restrict__ ql,
    const hf* __restrict__ kv16,   // [T, 16*256]
    const hf* __restrict__ kpe,    // [T, 64]
    hf* __restrict__ attn)
{
    extern __shared__ char smem[];
    const int m0 = blockIdx.x * AM;
    const int h  = blockIdx.y;
    const int tid = threadIdx.x, lane = tid & 31, warp = tid >> 5;
    const int wm = warp * 16;
    const float L2E = 1.4426950408889634f;

    {
        const hf* qh_g = qh + ((size_t)h * T_TOK + m0) * DQK;
        const hf* ql_g = ql + ((size_t)h * T_TOK + m0) * DQK;
        for (int i = tid; i < AM * 24; i += 256) {
            int r = i / 24, c = i % 24, pc = c ^ (r & 7);
            cp16(smem_u32(smem + FQH + r * 384 + pc * 16), qh_g + (size_t)r * DQK + c * 8, 16);
            cp16(smem_u32(smem + FQL + r * 384 + pc * 16), ql_g + (size_t)r * DQK + c * 8, 16);
        }
        cp_commit();
    }

    float o[16][4];
#pragma unroll
    for (int i = 0; i < 16; i++)
#pragma unroll
        for (int j = 0; j < 4; j++) o[i][j] = 0.f;
    float m0r = -1e30f, m1r = -1e30f, l0 = 0.f, l1 = 0.f;

    const unsigned aQh = smem_u32(smem + FQH), aQl = smem_u32(smem + FQL);
    const unsigned aKh = smem_u32(smem + FKH);
    const unsigned aVh = smem_u32(smem + FVH);

    const int ntiles = 2 * blockIdx.x + 2;
    for (int nt = 0; nt < ntiles; nt++) {
        const int n0 = nt * AN;
        __syncthreads();
        {
            const hf* kv_g = kv16 + (size_t)n0 * (NH * KV_OUT) + h * KV_OUT;
            const hf* pe_g = kpe + (size_t)n0 * DR;
            for (int i = tid; i < AN * 24; i += 256) {
                int r = i / 24, c = i % 24, pc = c ^ (r & 7);
                const hf* src = (c < 16)
                    ? kv_g + (size_t)r * (NH * KV_OUT) + c * 8
                    : pe_g + (size_t)r * DR + (c - 16) * 8;
                cp16(smem_u32(smem + FKH + r * 384 + pc * 16), src, 16);
            }
            const hf* v_g = kv_g + DN;
            for (int i = tid; i < AN * 16; i += 256) {
                int r = i >> 4, c = i & 15, pc = c ^ (r & 7);
                cp16(smem_u32(smem + FVH + r * 256 + pc * 16),
                     v_g + (size_t)r * (NH * KV_OUT) + c * 8, 16);
            }
        }
        cp_commit();
        cp_wait<0>();
        __syncthreads();

        float s[8][4];
#pragma unroll
        for (int j = 0; j < 8; j++)
#pragma unroll
            for (int c = 0; c < 4; c++) s[j][c] = 0.f;

#pragma unroll
        for (int kt = 0; kt < 12; kt++) {
            unsigned ah[4], al[4];
            {
                int r = wm + (lane & 15), c = kt * 2 + (lane >> 4);
                int pc = c ^ (r & 7);
                unsigned off = (unsigned)(r * 384 + pc * 16);
                ldm4(ah, aQh + off);
                ldm4(al, aQl + off);
            }
#pragma unroll
            for (int kb = 0; kb < 4; kb++) {
                int r = kb * 16 + (lane & 15), c = kt * 2 + (lane >> 4);
                int pc = c ^ (r & 7);
                unsigned off = (unsigned)(r * 384 + pc * 16);
                unsigned tb[4];
                ldm4(tb, aKh + off);
                unsigned bh0[2] = {tb[0], tb[2]}, bh1[2] = {tb[1], tb[3]};
                mma16816(s[kb * 2], ah, bh0);
                mma16816(s[kb * 2], al, bh0);
                mma16816(s[kb * 2 + 1], ah, bh1);
                mma16816(s[kb * 2 + 1], al, bh1);
            }
        }

        if (n0 + AN > m0) {
            int q0 = m0 + wm + (lane >> 2);
#pragma unroll
            for (int j = 0; j < 8; j++) {
                int k0 = n0 + j * 8 + (lane & 3) * 2;
                if (k0     > q0)     s[j][0] = -1e30f;
                if (k0 + 1 > q0)     s[j][1] = -1e30f;
                if (k0     > q0 + 8) s[j][2] = -1e30f;
                if (k0 + 1 > q0 + 8) s[j][3] = -1e30f;
            }
        }

        float mx0 = -1e30f, mx1 = -1e30f;
#pragma unroll
        for (int j = 0; j < 8; j++) {
            mx0 = fmaxf(mx0, fmaxf(s[j][0], s[j][1]));
            mx1 = fmaxf(mx1, fmaxf(s[j][2], s[j][3]));
        }
        mx0 = fmaxf(mx0, __shfl_xor_sync(0xffffffffu, mx0, 1));
        mx0 = fmaxf(mx0, __shfl_xor_sync(0xffffffffu, mx0, 2));
        mx1 = fmaxf(mx1, __shfl_xor_sync(0xffffffffu, mx1, 1));
        mx1 = fmaxf(mx1, __shfl_xor_sync(0xffffffffu, mx1, 2));
        float mn0 = fmaxf(m0r, mx0), mn1 = fmaxf(m1r, mx1);
        float f0 = exp2f((m0r - mn0) * L2E), f1 = exp2f((m1r - mn1) * L2E);
        m0r = mn0; m1r = mn1;

        unsigned ph[8], ph2[8], pl[8], pl2[8];
        float sum0 = 0.f, sum1 = 0.f;
#pragma unroll
        for (int j = 0; j < 8; j++) {
            float p0 = exp2f((s[j][0] - mn0) * L2E);
            float p1 = exp2f((s[j][1] - mn0) * L2E);
            float p2 = exp2f((s[j][2] - mn1) * L2E);
            float p3 = exp2f((s[j][3] - mn1) * L2E);
            sum0 += p0 + p1; sum1 += p2 + p3;
            hf a, b, c, d;
            split1(p0, a, c); split1(p1, b, d);
            ph[j] = packhf(a, b); pl[j] = packhf(c, d);
            split1(p2, a, c); split1(p3, b, d);
            ph2[j] = packhf(a, b); pl2[j] = packhf(c, d);
        }
        sum0 += __shfl_xor_sync(0xffffffffu, sum0, 1);
        sum0 += __shfl_xor_sync(0xffffffffu, sum0, 2);
        sum1 += __shfl_xor_sync(0xffffffffu, sum1, 1);
        sum1 += __shfl_xor_sync(0xffffffffu, sum1, 2);
        l0 = l0 * f0 + sum0;
        l1 = l1 * f1 + sum1;
#pragma unroll
        for (int j = 0; j < 16; j++) {
            o[j][0] *= f0; o[j][1] *= f0; o[j][2] *= f1; o[j][3] *= f1;
        }

#pragma unroll
        for (int kt = 0; kt < 4; kt++) {
            unsigned ahp[4] = {ph[2 * kt], ph2[2 * kt], ph[2 * kt + 1], ph2[2 * kt + 1]};
            unsigned alp[4] = {pl[2 * kt], pl2[2 * kt], pl[2 * kt + 1], pl2[2 * kt + 1]};
#pragma unroll
            for (int nv = 0; nv < 8; nv++) {
                int r = kt * 16 + (lane & 15), c = nv * 2 + (lane >> 4);
                int pc = c ^ (r & 7);
                unsigned off = (unsigned)(r * 256 + pc * 16);
                unsigned tb[4];
                ldm4t(tb, aVh + off);
                unsigned bh0[2] = {tb[0], tb[1]}, bh1[2] = {tb[2], tb[3]};
                mma16816(o[nv * 2], ahp, bh0);
                mma16816(o[nv * 2], alp, bh0);
                mma16816(o[nv * 2 + 1], ahp, bh1);
                mma16816(o[nv * 2 + 1], alp, bh1);
            }
        }
    }

    float il0 = 1.f / l0, il1 = 1.f / l1;
    int r0 = m0 + wm + (lane >> 2);
#pragma unroll
    for (int j = 0; j < 16; j++) {
        int dv = j * 8 + (lane & 3) * 2;
        size_t off = (size_t)r0 * (NH * DV) + h * DV + dv;
        *(__half2*)(attn + off) =
            __half2(__float2half_rn(o[j][0] * il0), __float2half_rn(o[j][1] * il0));
        off += (size_t)8 * (NH * DV);
        *(__half2*)(attn + off) =
            __half2(__float2half_rn(o[j][2] * il1), __float2half_rn(o[j][3] * il1));
    }
}

// ---------------------------------------------------------------------------
// Launch
// ---------------------------------------------------------------------------
static inline void launch_split_h(const float* x, hf* hi, int n) {
    int n4 = n / 4;
    split_h_kernel<<<(n4 + 255) / 256, 256>>>(x, hi, n4);
}

extern "C" void kernel_launch(void* const* d_in, const int* in_sizes, int n_in,
                              void* d_out, int out_size)
{
    const int*   positions = (const int*)  d_in[0];
    const float* hidden    = (const float*)d_in[1];
    const float* scaling   = (const float*)d_in[2];
    const float* w_q_a     = (const float*)d_in[3];
    const float* q_a_ln_w  = (const float*)d_in[4];
    const float* w_q_b     = (const float*)d_in[5];
    const float* w_kv_a    = (const float*)d_in[6];
    const float* kv_a_ln_w = (const float*)d_in[7];
    const float* w_kv_b    = (const float*)d_in[8];
    const float* w_o       = (const float*)d_in[9];
    const float* cs_cache  = (const float*)d_in[10];
    float* out = (float*)d_out;

    hf *Hh, *Wa_h, *Wqb_h, *Wkvb_h, *Wo_h;
    hf *qa_h, *kvan_h;
    hf *qhp, *qlp, *kv16, *kpe, *attn;
    float *qalat, *qb;
    cudaGetSymbolAddress((void**)&Hh, g_Hh);
    cudaGetSymbolAddress((void**)&Wa_h, g_Wa_h);
    cudaGetSymbolAddress((void**)&Wqb_h, g_Wqb_h);
    cudaGetSymbolAddress((void**)&Wkvb_h, g_Wkvb_h);
    cudaGetSymbolAddress((void**)&Wo_h, g_Wo_h);
    cudaGetSymbolAddress((void**)&qa_h, g_qa_h);
    cudaGetSymbolAddress((void**)&kvan_h, g_kvan_h);
    cudaGetSymbolAddress((void**)&qhp, g_qh); cudaGetSymbolAddress((void**)&qlp, g_ql);
    cudaGetSymbolAddress((void**)&kv16, g_kv16);
    cudaGetSymbolAddress((void**)&kpe, g_kpe);
    cudaGetSymbolAddress((void**)&attn, g_attn);
    cudaGetSymbolAddress((void**)&qalat, g_qalat);
    cudaGetSymbolAddress((void**)&qb, g_q);

    cudaFuncSetAttribute(mma_gemm1_kernel, cudaFuncAttributeMaxDynamicSharedMemorySize,
                         GEMM_SMEM);
    cudaFuncSetAttribute(mma_gemm_dual_kernel, cudaFuncAttributeMaxDynamicSharedMemorySize,
                         GEMM_SMEM);
    cudaFuncSetAttribute(flash_mma_kernel, cudaFuncAttributeMaxDynamicSharedMemorySize,
                         FLASH_SMEM);

    // 1. splits: hidden hi only; weights hi only (fused w_q_a|w_kv_a)
    launch_split_h(hidden, Hh, T_TOK * HID);
    {
        int total4 = HID * FUSED_N / 4;
        split_fuse_kernel<<<(total4 + 255) / 256, 256>>>(w_q_a, w_kv_a, Wa_h);
    }
    launch_split_h(w_q_b, Wqb_h, Q_RANK * NH * DQK);
    launch_split_h(w_kv_b, Wkvb_h, KV_RANK * NH * KV_OUT);
    launch_split_h(w_o, Wo_h, NH * DV * HID);

    const dim3 blk(256);
    const int MT = T_TOK / CBM;  // 24

    // 2. [qa | latent] = hidden @ [w_q_a | w_kv_a]  (single-term)
    mma_gemm1_kernel<<<dim3((FUSED_N + CBN - 1) / CBN, MT), blk, GEMM_SMEM>>>(
        Hh, Wa_h, qalat, T_TOK, FUSED_N, HID);
    // 3. rmsnorm -> fp16 hi
    rmsnorm_h_kernel<<<T_TOK, 256>>>(qalat, q_a_ln_w, qa_h, Q_RANK, FUSED_N);
    rmsnorm_h_kernel<<<T_TOK, 256>>>(qalat + Q_RANK, kv_a_ln_w, kvan_h,
                                     KV_RANK, FUSED_N);
    // 4+5 fused single-term: q (fp32 out) AND kv (fp16 out)
    {
        const int nblk_q  = (NH * DQK) / CBN;    // 24
        const int nblk_kv = (NH * KV_OUT) / CBN; // 32
        mma_gemm_dual_kernel<<<dim3(nblk_q + nblk_kv, MT), blk, GEMM_SMEM>>>(
            qa_h, Wqb_h, qb, NH * DQK, Q_RANK, nblk_q,
            kvan_h, Wkvb_h, kv16, NH * KV_OUT, KV_RANK);
    }
    // 6. rope + scale + head-major Q; k_pe -> fp16
    prep_kernel<<<T_TOK, 256>>>(positions, cs_cache, scaling,
                                qalat + Q_RANK, FUSED_N, qb, qhp, qlp, kpe);
    // 7. flash attention (fp16 output)
    flash_mma_kernel<<<dim3(T_TOK / AM, NH), 256, FLASH_SMEM>>>(
        qhp, qlp, kv16, kpe, attn);
    // 8. out = attn @ w_o  (single-term)
    mma_gemm1_kernel<<<dim3(HID / CBN, MT), blk, GEMM_SMEM>>>(
        attn, Wo_h, out, T_TOK, HID, NH * DV);
}

// round 14
// speedup vs baseline: 1.4905x; 1.0707x over previous
#include <cuda_runtime.h>
#include <cuda_fp16.h>
#include <math.h>

// Problem constants
#define T_TOK 3072
#define HID 5120
#define NH 16
#define DN 128
#define DR 64
#define DQK 192       // DN + DR
#define DV 128
#define Q_RANK 1536
#define KV_RANK 512
#define KV_A_OUT (KV_RANK + DR)   // 576
#define KV_OUT (DN + DV)          // 256
#define FUSED_N (Q_RANK + KV_A_OUT)   // 2112

typedef __half hf;

// ---------------------------------------------------------------------------
// Scratch (allocation-free: __device__ globals)
// ---------------------------------------------------------------------------
__device__ hf g_Hh[T_TOK * HID];                     // hidden hi only
__device__ hf g_Wa_h[HID * FUSED_N];                 // fused [5120,2112] hi
__device__ hf g_Wqb_h[Q_RANK * NH * DQK];
__device__ hf g_Wkvb_h[KV_RANK * NH * KV_OUT];
__device__ hf g_Wo_h[NH * DV * HID];
__device__ float g_qalat[T_TOK * FUSED_N];           // fused qa | latent (fp32)
__device__ hf g_qa_h[T_TOK * Q_RANK];
__device__ hf g_kvan_h[T_TOK * KV_RANK];
__device__ float g_q[T_TOK * NH * DQK];
__device__ hf g_kv16[T_TOK * NH * KV_OUT];           // kv GEMM out, fp16 direct
__device__ hf g_kpe[T_TOK * DR];                     // roped k_pe, fp16
// head-major Q for flash
__device__ hf g_qh[NH * T_TOK * DQK], g_ql[NH * T_TOK * DQK];
__device__ hf g_attn[T_TOK * NH * DV];               // attn out, fp16 single

// ---------------------------------------------------------------------------
// PTX helpers
// ---------------------------------------------------------------------------
__device__ __forceinline__ unsigned smem_u32(const void* p) {
    return (unsigned)__cvta_generic_to_shared(p);
}
__device__ __forceinline__ void cp16(unsigned s, const void* g, int srcsz) {
    asm volatile("cp.async.cg.shared.global [%0], [%1], 16, %2;\n"
                 :: "r"(s), "l"(g), "r"(srcsz));
}
__device__ __forceinline__ void cp_commit() {
    asm volatile("cp.async.commit_group;\n" ::);
}
template<int N> __device__ __forceinline__ void cp_wait() {
    asm volatile("cp.async.wait_group %0;\n" :: "n"(N));
}
__device__ __forceinline__ void ldm4(unsigned* d, unsigned a) {
    asm volatile("ldmatrix.sync.aligned.m8n8.x4.shared.b16 {%0,%1,%2,%3}, [%4];\n"
                 : "=r"(d[0]), "=r"(d[1]), "=r"(d[2]), "=r"(d[3]) : "r"(a));
}
__device__ __forceinline__ void ldm4t(unsigned* d, unsigned a) {
    asm volatile("ldmatrix.sync.aligned.m8n8.x4.trans.shared.b16 {%0,%1,%2,%3}, [%4];\n"
                 : "=r"(d[0]), "=r"(d[1]), "=r"(d[2]), "=r"(d[3]) : "r"(a));
}
__device__ __forceinline__ void mma16816(float* c, const unsigned* a, const unsigned* b) {
    asm volatile(
        "mma.sync.aligned.m16n8k16.row.col.f32.f16.f16.f32 "
        "{%0,%1,%2,%3}, {%4,%5,%6,%7}, {%8,%9}, {%0,%1,%2,%3};\n"
        : "+f"(c[0]), "+f"(c[1]), "+f"(c[2]), "+f"(c[3])
        : "r"(a[0]), "r"(a[1]), "r"(a[2]), "r"(a[3]), "r"(b[0]), "r"(b[1]));
}
__device__ __forceinline__ void split1(float x, hf& h, hf& l) {
    h = __float2half_rn(x);
    l = __float2half_rn(x - __half2float(h));
}
__device__ __forceinline__ unsigned packhf(hf a, hf b) {
    __half2 t(a, b);
    return *(unsigned*)&t;
}

// ---------------------------------------------------------------------------
// fp32 -> fp16 hi only
// ---------------------------------------------------------------------------
__global__ void split_h_kernel(const float* __restrict__ x,
                               hf* __restrict__ hi, int n4)
{
    int i = blockIdx.x * blockDim.x + threadIdx.x;
    if (i >= n4) return;
    float4 v = ((const float4*)x)[i];
    __half2* H = (__half2*)hi;
    H[i * 2]     = __half2(__float2half_rn(v.x), __float2half_rn(v.y));
    H[i * 2 + 1] = __half2(__float2half_rn(v.z), __float2half_rn(v.w));
}

// Fused 3-tensor hi split (one launch for w_q_b, w_kv_b, w_o)
__global__ void split3_h_kernel(const float* __restrict__ x0, hf* __restrict__ y0, int n40,
                                const float* __restrict__ x1, hf* __restrict__ y1, int n41,
                                const float* __restrict__ x2, hf* __restrict__ y2, int n42)
{
    int i = blockIdx.x * blockDim.x + threadIdx.x;
    const float* x; hf* y; int li;
    if (i < n40)              { x = x0; y = y0; li = i; }
    else if (i < n40 + n41)   { x = x1; y = y1; li = i - n40; }
    else if (i < n40 + n41 + n42) { x = x2; y = y2; li = i - n40 - n41; }
    else return;
    float4 v = ((const float4*)x)[li];
    __half2* H = (__half2*)y;
    H[li * 2]     = __half2(__float2half_rn(v.x), __float2half_rn(v.y));
    H[li * 2 + 1] = __half2(__float2half_rn(v.z), __float2half_rn(v.w));
}

// Fused-weight hi split: w_q_a [5120,1536] | w_kv_a [5120,576] -> [5120,2112]
__global__ void split_fuse_kernel(const float* __restrict__ wqa,
                                  const float* __restrict__ wkva,
                                  hf* __restrict__ hi)
{
    int i = blockIdx.x * blockDim.x + threadIdx.x;
    int total4 = HID * FUSED_N / 4;
    if (i >= total4) return;
    int e0 = i * 4;
    int k = e0 / FUSED_N, n = e0 % FUSED_N;
    float v[4];
    if (n + 3 < Q_RANK) {
        const float* src = wqa + (size_t)k * Q_RANK + n;
        v[0] = src[0]; v[1] = src[1]; v[2] = src[2]; v[3] = src[3];
    } else if (n >= Q_RANK) {
        const float* src = wkva + (size_t)k * KV_A_OUT + (n - Q_RANK);
        v[0] = src[0]; v[1] = src[1]; v[2] = src[2]; v[3] = src[3];
    } else {
#pragma unroll
        for (int j = 0; j < 4; j++) {
            int nn = n + j;
            v[j] = (nn < Q_RANK) ? wqa[(size_t)k * Q_RANK + nn]
                                 : wkva[(size_t)k * KV_A_OUT + (nn - Q_RANK)];
        }
    }
    hf h[4];
#pragma unroll
    for (int j = 0; j < 4; j++) h[j] = __float2half_rn(v[j]);
    *(uint2*)(hi + e0) = *(uint2*)h;
}

// ---------------------------------------------------------------------------
// fp16 single-term tensor-core GEMM:  C = Ah @ Bh.
// CTA 128x128, BK=32, 256 threads, 3-stage cp.async, XOR-swizzled smem.
// ---------------------------------------------------------------------------
#define CBM 128
#define CBN 128
#define CBK 32
#define A_TILE_B 8192
#define B_TILE_B 8192
#define STAGE_B  (A_TILE_B + B_TILE_B)       // 16384
#define NSTAGE 3
#define GEMM_SMEM (NSTAGE * STAGE_B)         // 49152

template<bool OUT16>
__device__ __forceinline__ void gemm_cta(
    char* smem, int tid,
    const hf* __restrict__ Ah,
    const hf* __restrict__ Bh,
    void* __restrict__ Cv, int m0, int n0, int N, int K)
{
    const int lane = tid & 31;
    const int warp = tid >> 5;
    const int wm0 = (warp >> 2) * 64;
    const int wn0 = (warp & 3) * 32;

    float acc[16][4];
#pragma unroll
    for (int i = 0; i < 16; i++)
#pragma unroll
        for (int j = 0; j < 4; j++) acc[i][j] = 0.f;

    auto load_stage = [&](int k0, int s) {
        char* base = smem + s * STAGE_B;
#pragma unroll
        for (int i = 0; i < 2; i++) {
            int ch = tid + i * 256;
            int r = ch >> 2, c = ch & 3;
            int pc = c ^ ((r >> 1) & 3);
            size_t goff = (size_t)(m0 + r) * K + k0 + c * 8;
            cp16(smem_u32(base + r * 64 + pc * 16), Ah + goff, 16);
        }
#pragma unroll
        for (int i = 0; i < 2; i++) {
            int ch = tid + i * 256;
            int r = ch >> 4, c = ch & 15;
            int pc = c ^ (r & 7);
            int gn = n0 + c * 8;
            int sz = (gn < N) ? 16 : 0;
            size_t goff = (size_t)(k0 + r) * N + (gn < N ? gn : 0);
            cp16(smem_u32(base + A_TILE_B + r * 256 + pc * 16), Bh + goff, sz);
        }
    };

    auto compute_stage = [&](int s) {
        char* base = smem + s * STAGE_B;
        unsigned aH = smem_u32(base);
        unsigned bH = aH + A_TILE_B;
#pragma unroll
        for (int kk = 0; kk < 2; kk++) {
            unsigned ah[4][4], bh[4][2];
            const int r_lo = lane & 15;
            const int cch = kk * 2 + (lane >> 4);
#pragma unroll
            for (int mi = 0; mi < 4; mi++) {
                int r = wm0 + mi * 16 + r_lo;
                int pc = cch ^ ((r >> 1) & 3);
                unsigned off = (unsigned)(r * 64 + pc * 16);
                ldm4(ah[mi], aH + off);
            }
            {
                int r = kk * 16 + (lane & 15);
#pragma unroll
                for (int ni = 0; ni < 2; ni++) {
                    int cc = ((wn0 + ni * 16) >> 3) + ((lane >> 4) & 1);
                    int pc = cc ^ (r & 7);
                    unsigned off = (unsigned)(r * 256 + pc * 16);
                    unsigned t[4];
                    ldm4t(t, bH + off);
                    bh[ni * 2][0] = t[0]; bh[ni * 2][1] = t[1];
                    bh[ni * 2 + 1][0] = t[2]; bh[ni * 2 + 1][1] = t[3];
                }
            }
#pragma unroll
            for (int mi = 0; mi < 4; mi++)
#pragma unroll
                for (int nj = 0; nj < 4; nj++)
                    mma16816(acc[mi * 4 + nj], ah[mi], bh[nj]);
        }
    };

    const int KT = K / CBK;
    load_stage(0, 0); cp_commit();
    load_stage(CBK, 1); cp_commit();
    for (int kt = 0; kt < KT; kt++) {
        cp_wait<1>();
        __syncthreads();
        if (kt + 2 < KT) load_stage((kt + 2) * CBK, (kt + 2) % NSTAGE);
        cp_commit();
        compute_stage(kt % NSTAGE);
    }

#pragma unroll
    for (int mi = 0; mi < 4; mi++) {
        int row = m0 + wm0 + mi * 16 + (lane >> 2);
#pragma unroll
        for (int nj = 0; nj < 4; nj++) {
            int col = n0 + wn0 + nj * 8 + (lane & 3) * 2;
            if (col < N) {
                float* a = acc[mi * 4 + nj];
                if (OUT16) {
                    hf* C = (hf*)Cv;
                    *(__half2*)(C + (size_t)row * N + col) =
                        __half2(__float2half_rn(a[0]), __float2half_rn(a[1]));
                    *(__half2*)(C + (size_t)(row + 8) * N + col) =
                        __half2(__float2half_rn(a[2]), __float2half_rn(a[3]));
                } else {
                    float* C = (float*)Cv;
                    *(float2*)(C + (size_t)row * N + col)       = make_float2(a[0], a[1]);
                    *(float2*)(C + (size_t)(row + 8) * N + col) = make_float2(a[2], a[3]);
                }
            }
        }
    }
}

__global__ __launch_bounds__(256) void mma_gemm1_kernel(
    const hf* __restrict__ Ah,
    const hf* __restrict__ Bh,
    float* __restrict__ C, int M, int N, int K)
{
    extern __shared__ char smem[];
    gemm_cta<false>(smem, threadIdx.x, Ah, Bh, C,
                    blockIdx.y * CBM, blockIdx.x * CBN, N, K);
}

__global__ __launch_bounds__(256) void mma_gemm_dual_kernel(
    const hf* __restrict__ Ah1, const hf* __restrict__ Bh1,
    float* __restrict__ C1, int N1, int K1, int nblk1,
    const hf* __restrict__ Ah2, const hf* __restrict__ Bh2,
    hf* __restrict__ C2, int N2, int K2)
{
    extern __shared__ char smem[];
    const int m0 = blockIdx.y * CBM;
    if ((int)blockIdx.x < nblk1) {
        gemm_cta<false>(smem, threadIdx.x, Ah1, Bh1, C1,
                        m0, blockIdx.x * CBN, N1, K1);
    } else {
        gemm_cta<true>(smem, threadIdx.x, Ah2, Bh2, C2,
                       m0, (blockIdx.x - nblk1) * CBN, N2, K2);
    }
}

// ---------------------------------------------------------------------------
// RMSNorm -> fp16 hi only
// ---------------------------------------------------------------------------
__global__ void rmsnorm_h_kernel(const float* __restrict__ in,
                                 const float* __restrict__ w,
                                 hf* __restrict__ ohi,
                                 int W, int in_stride)
{
    const int t = blockIdx.x;
    const float* row = in + (size_t)t * in_stride;

    float ss = 0.f;
    for (int i = threadIdx.x; i < W; i += blockDim.x) {
        float v = row[i];
        ss += v * v;
    }
    __shared__ float red[32];
#pragma unroll
    for (int o = 16; o; o >>= 1) ss += __shfl_xor_sync(0xffffffffu, ss, o);
    if ((threadIdx.x & 31) == 0) red[threadIdx.x >> 5] = ss;
    __syncthreads();
    if (threadIdx.x < 32) {
        float v = (threadIdx.x < (blockDim.x >> 5)) ? red[threadIdx.x] : 0.f;
#pragma unroll
        for (int o = 16; o; o >>= 1) v += __shfl_xor_sync(0xffffffffu, v, o);
        if (threadIdx.x == 0) red[0] = v;
    }
    __syncthreads();
    const float inv = rsqrtf(red[0] / (float)W + 1e-6f);
    for (int i = threadIdx.x; i < W; i += blockDim.x)
        ohi[(size_t)t * W + i] = __float2half_rn(row[i] * inv * w[i]);
}

// ---------------------------------------------------------------------------
// Prep: RoPE q_pe (in place) + k_pe (-> fp16 kpe), fold (scaling / sqrt(192))
// into q, emit head-major Q hi/lo (fp16).
// ---------------------------------------------------------------------------
__global__ void prep_kernel(const int* __restrict__ positions,
                            const float* __restrict__ cs_cache,
                            const float* __restrict__ scaling,
                            const float* __restrict__ latent, int lat_stride,
                            float* __restrict__ qb,          // [T,16,192] in/out
                            hf* __restrict__ qh, hf* __restrict__ ql,
                            hf* __restrict__ kpe)            // [T,64] fp16
{
    const int t = blockIdx.x;
    const int pos = positions[t];
    const float* cs = cs_cache + (size_t)pos * DR;
    const float qsc = scaling[t] * 0.07216878364870322f;  // llama4 * 1/sqrt(192)
    float* qrow = qb + (size_t)t * (NH * DQK);

    for (int idx = threadIdx.x; idx < NH * 32; idx += blockDim.x) {
        int hh = idx >> 5, i = idx & 31;
        float c = cs[i], s = cs[32 + i];
        float x1 = qrow[hh * DQK + DN + i];
        float x2 = qrow[hh * DQK + DN + 32 + i];
        qrow[hh * DQK + DN + i]      = x1 * c - x2 * s;
        qrow[hh * DQK + DN + 32 + i] = x2 * c + x1 * s;
    }
    if (threadIdx.x < 32) {
        int i = threadIdx.x;
        float c = cs[i], s = cs[32 + i];
        float x1 = latent[(size_t)t * lat_stride + KV_RANK + i];
        float x2 = latent[(size_t)t * lat_stride + KV_RANK + 32 + i];
        kpe[t * DR + i]      = __float2half_rn(x1 * c - x2 * s);
        kpe[t * DR + 32 + i] = __float2half_rn(x2 * c + x1 * s);
    }
    __syncthreads();
    for (int idx = threadIdx.x; idx < NH * DQK; idx += blockDim.x) {
        int hh = idx / DQK, d = idx % DQK;
        size_t o = ((size_t)hh * T_TOK + t) * DQK + d;
        hf hi, lo;
        split1(qrow[idx] * qsc, hi, lo);
        qh[o] = hi; ql[o] = lo;
    }
}

// ---------------------------------------------------------------------------
// Tensor-core flash attention (causal).
// Q exact (hi+lo) for QK^T; P hi-only for PV; K/V direct from fp16 buffers.
// Output: plain fp16.
// ---------------------------------------------------------------------------
#define AM 128
#define AN 64
#define FQH 0
#define FQL (FQH + AM*384)
#define FKH (FQL + AM*384)
#define FVH (FKH + AN*384)
#define FLASH_SMEM (FVH + AN*256)    // 139264 B

__global__ __launch_bounds__(256) void flash_mma_kernel(
    const hf* __restrict__ qh, const hf* __restrict__ ql,
    const hf* __restrict__ kv16,   // [T, 16*256]
    const hf* __restrict__ kpe,    // [T, 64]
    hf* __restrict__ attn)
{
    extern __shared__ char smem[];
    const int m0 = blockIdx.x * AM;
    const int h  = blockIdx.y;
    const int tid = threadIdx.x, lane = tid & 31, warp = tid >> 5;
    const int wm = warp * 16;
    const float L2E = 1.4426950408889634f;

    {
        const hf* qh_g = qh + ((size_t)h * T_TOK + m0) * DQK;
        const hf* ql_g = ql + ((size_t)h * T_TOK + m0) * DQK;
        for (int i = tid; i < AM * 24; i += 256) {
            int r = i / 24, c = i % 24, pc = c ^ (r & 7);
            cp16(smem_u32(smem + FQH + r * 384 + pc * 16), qh_g + (size_t)r * DQK + c * 8, 16);
            cp16(smem_u32(smem + FQL + r * 384 + pc * 16), ql_g + (size_t)r * DQK + c * 8, 16);
        }
        cp_commit();
    }

    float o[16][4];
#pragma unroll
    for (int i = 0; i < 16; i++)
#pragma unroll
        for (int j = 0; j < 4; j++) o[i][j] = 0.f;
    float m0r = -1e30f, m1r = -1e30f, l0 = 0.f, l1 = 0.f;

    const unsigned aQh = smem_u32(smem + FQH), aQl = smem_u32(smem + FQL);
    const unsigned aKh = smem_u32(smem + FKH);
    const unsigned aVh = smem_u32(smem + FVH);

    const int ntiles = 2 * blockIdx.x + 2;
    for (int nt = 0; nt < ntiles; nt++) {
        const int n0 = nt * AN;
        __syncthreads();
        {
            const hf* kv_g = kv16 + (size_t)n0 * (NH * KV_OUT) + h * KV_OUT;
            const hf* pe_g = kpe + (size_t)n0 * DR;
            for (int i = tid; i < AN * 24; i += 256) {
                int r = i / 24, c = i % 24, pc = c ^ (r & 7);
                const hf* src = (c < 16)
                    ? kv_g + (size_t)r * (NH * KV_OUT) + c * 8
                    : pe_g + (size_t)r * DR + (c - 16) * 8;
                cp16(smem_u32(smem + FKH + r * 384 + pc * 16), src, 16);
            }
            const hf* v_g = kv_g + DN;
            for (int i = tid; i < AN * 16; i += 256) {
                int r = i >> 4, c = i & 15, pc = c ^ (r & 7);
                cp16(smem_u32(smem + FVH + r * 256 + pc * 16),
                     v_g + (size_t)r * (NH * KV_OUT) + c * 8, 16);
            }
        }
        cp_commit();
        cp_wait<0>();
        __syncthreads();

        float s[8][4];
#pragma unroll
        for (int j = 0; j < 8; j++)
#pragma unroll
            for (int c = 0; c < 4; c++) s[j][c] = 0.f;

#pragma unroll
        for (int kt = 0; kt < 12; kt++) {
            unsigned ah[4], al[4];
            {
                int r = wm + (lane & 15), c = kt * 2 + (lane >> 4);
                int pc = c ^ (r & 7);
                unsigned off = (unsigned)(r * 384 + pc * 16);
                ldm4(ah, aQh + off);
                ldm4(al, aQl + off);
            }
#pragma unroll
            for (int kb = 0; kb < 4; kb++) {
                int r = kb * 16 + (lane & 15), c = kt * 2 + (lane >> 4);
                int pc = c ^ (r & 7);
                unsigned off = (unsigned)(r * 384 + pc * 16);
                unsigned tb[4];
                ldm4(tb, aKh + off);
                unsigned bh0[2] = {tb[0], tb[2]}, bh1[2] = {tb[1], tb[3]};
                mma16816(s[kb * 2], ah, bh0);
                mma16816(s[kb * 2], al, bh0);
                mma16816(s[kb * 2 + 1], ah, bh1);
                mma16816(s[kb * 2 + 1], al, bh1);
            }
        }

        if (n0 + AN > m0) {
            int q0 = m0 + wm + (lane >> 2);
#pragma unroll
            for (int j = 0; j < 8; j++) {
                int k0 = n0 + j * 8 + (lane & 3) * 2;
                if (k0     > q0)     s[j][0] = -1e30f;
                if (k0 + 1 > q0)     s[j][1] = -1e30f;
                if (k0     > q0 + 8) s[j][2] = -1e30f;
                if (k0 + 1 > q0 + 8) s[j][3] = -1e30f;
            }
        }

        float mx0 = -1e30f, mx1 = -1e30f;
#pragma unroll
        for (int j = 0; j < 8; j++) {
            mx0 = fmaxf(mx0, fmaxf(s[j][0], s[j][1]));
            mx1 = fmaxf(mx1, fmaxf(s[j][2], s[j][3]));
        }
        mx0 = fmaxf(mx0, __shfl_xor_sync(0xffffffffu, mx0, 1));
        mx0 = fmaxf(mx0, __shfl_xor_sync(0xffffffffu, mx0, 2));
        mx1 = fmaxf(mx1, __shfl_xor_sync(0xffffffffu, mx1, 1));
        mx1 = fmaxf(mx1, __shfl_xor_sync(0xffffffffu, mx1, 2));
        float mn0 = fmaxf(m0r, mx0), mn1 = fmaxf(m1r, mx1);
        float f0 = exp2f((m0r - mn0) * L2E), f1 = exp2f((m1r - mn1) * L2E);
        m0r = mn0; m1r = mn1;

        unsigned ph[8], ph2[8];
        float sum0 = 0.f, sum1 = 0.f;
#pragma unroll
        for (int j = 0; j < 8; j++) {
            float p0 = exp2f((s[j][0] - mn0) * L2E);
            float p1 = exp2f((s[j][1] - mn0) * L2E);
            float p2 = exp2f((s[j][2] - mn1) * L2E);
            float p3 = exp2f((s[j][3] - mn1) * L2E);
            sum0 += p0 + p1; sum1 += p2 + p3;
            ph[j]  = packhf(__float2half_rn(p0), __float2half_rn(p1));
            ph2[j] = packhf(__float2half_rn(p2), __float2half_rn(p3));
        }
        sum0 += __shfl_xor_sync(0xffffffffu, sum0, 1);
        sum0 += __shfl_xor_sync(0xffffffffu, sum0, 2);
        sum1 += __shfl_xor_sync(0xffffffffu, sum1, 1);
        sum1 += __shfl_xor_sync(0xffffffffu, sum1, 2);
        l0 = l0 * f0 + sum0;
        l1 = l1 * f1 + sum1;
#pragma unroll
        for (int j = 0; j < 16; j++) {
            o[j][0] *= f0; o[j][1] *= f0; o[j][2] *= f1; o[j][3] *= f1;
        }

#pragma unroll
        for (int kt = 0; kt < 4; kt++) {
            unsigned ahp[4] = {ph[2 * kt], ph2[2 * kt], ph[2 * kt + 1], ph2[2 * kt + 1]};
#pragma unroll
            for (int nv = 0; nv < 8; nv++) {
                int r = kt * 16 + (lane & 15), c = nv * 2 + (lane >> 4);
                int pc = c ^ (r & 7);
                unsigned off = (unsigned)(r * 256 + pc * 16);
                unsigned tb[4];
                ldm4t(tb, aVh + off);
                unsigned bh0[2] = {tb[0], tb[1]}, bh1[2] = {tb[2], tb[3]};
                mma16816(o[nv * 2], ahp, bh0);
                mma16816(o[nv * 2 + 1], ahp, bh1);
            }
        }
    }

    float il0 = 1.f / l0, il1 = 1.f / l1;
    int r0 = m0 + wm + (lane >> 2);
#pragma unroll
    for (int j = 0; j < 16; j++) {
        int dv = j * 8 + (lane & 3) * 2;
        size_t off = (size_t)r0 * (NH * DV) + h * DV + dv;
        *(__half2*)(attn + off) =
            __half2(__float2half_rn(o[j][0] * il0), __float2half_rn(o[j][1] * il0));
        off += (size_t)8 * (NH * DV);
        *(__half2*)(attn + off) =
            __half2(__float2half_rn(o[j][2] * il1), __float2half_rn(o[j][3] * il1));
    }
}

// ---------------------------------------------------------------------------
// Launch
// ---------------------------------------------------------------------------
static inline void launch_split_h(const float* x, hf* hi, int n) {
    int n4 = n / 4;
    split_h_kernel<<<(n4 + 255) / 256, 256>>>(x, hi, n4);
}

extern "C" void kernel_launch(void* const* d_in, const int* in_sizes, int n_in,
                              void* d_out, int out_size)
{
    const int*   positions = (const int*)  d_in[0];
    const float* hidden    = (const float*)d_in[1];
    const float* scaling   = (const float*)d_in[2];
    const float* w_q_a     = (const float*)d_in[3];
    const float* q_a_ln_w  = (const float*)d_in[4];
    const float* w_q_b     = (const float*)d_in[5];
    const float* w_kv_a    = (const float*)d_in[6];
    const float* kv_a_ln_w = (const float*)d_in[7];
    const float* w_kv_b    = (const float*)d_in[8];
    const float* w_o       = (const float*)d_in[9];
    const float* cs_cache  = (const float*)d_in[10];
    float* out = (float*)d_out;

    hf *Hh, *Wa_h, *Wqb_h, *Wkvb_h, *Wo_h;
    hf *qa_h, *kvan_h;
    hf *qhp, *qlp, *kv16, *kpe, *attn;
    float *qalat, *qb;
    cudaGetSymbolAddress((void**)&Hh, g_Hh);
    cudaGetSymbolAddress((void**)&Wa_h, g_Wa_h);
    cudaGetSymbolAddress((void**)&Wqb_h, g_Wqb_h);
    cudaGetSymbolAddress((void**)&Wkvb_h, g_Wkvb_h);
    cudaGetSymbolAddress((void**)&Wo_h, g_Wo_h);
    cudaGetSymbolAddress((void**)&qa_h, g_qa_h);
    cudaGetSymbolAddress((void**)&kvan_h, g_kvan_h);
    cudaGetSymbolAddress((void**)&qhp, g_qh); cudaGetSymbolAddress((void**)&qlp, g_ql);
    cudaGetSymbolAddress((void**)&kv16, g_kv16);
    cudaGetSymbolAddress((void**)&kpe, g_kpe);
    cudaGetSymbolAddress((void**)&attn, g_attn);
    cudaGetSymbolAddress((void**)&qalat, g_qalat);
    cudaGetSymbolAddress((void**)&qb, g_q);

    cudaFuncSetAttribute(mma_gemm1_kernel, cudaFuncAttributeMaxDynamicSharedMemorySize,
                         GEMM_SMEM);
    cudaFuncSetAttribute(mma_gemm_dual_kernel, cudaFuncAttributeMaxDynamicSharedMemorySize,
                         GEMM_SMEM);
    cudaFuncSetAttribute(flash_mma_kernel, cudaFuncAttributeMaxDynamicSharedMemorySize,
                         FLASH_SMEM);

    // 1. splits: hidden; fused w_q_a|w_kv_a; fused (w_q_b, w_kv_b, w_o)
    launch_split_h(hidden, Hh, T_TOK * HID);
    {
        int total4 = HID * FUSED_N / 4;
        split_fuse_kernel<<<(total4 + 255) / 256, 256>>>(w_q_a, w_kv_a, Wa_h);
    }
    {
        int n40 = Q_RANK * NH * DQK / 4;
        int n41 = KV_RANK * NH * KV_OUT / 4;
        int n42 = NH * DV * HID / 4;
        int tot = n40 + n41 + n42;
        split3_h_kernel<<<(tot + 255) / 256, 256>>>(
            w_q_b, Wqb_h, n40, w_kv_b, Wkvb_h, n41, w_o, Wo_h, n42);
    }

    const dim3 blk(256);
    const int MT = T_TOK / CBM;  // 24

    // 2. [qa | latent] = hidden @ [w_q_a | w_kv_a]
    mma_gemm1_kernel<<<dim3((FUSED_N + CBN - 1) / CBN, MT), blk, GEMM_SMEM>>>(
        Hh, Wa_h, qalat, T_TOK, FUSED_N, HID);
    // 3. rmsnorm -> fp16 hi
    rmsnorm_h_kernel<<<T_TOK, 256>>>(qalat, q_a_ln_w, qa_h, Q_RANK, FUSED_N);
    rmsnorm_h_kernel<<<T_TOK, 256>>>(qalat + Q_RANK, kv_a_ln_w, kvan_h,
                                     KV_RANK, FUSED_N);
    // 4+5 fused: q (fp32 out) AND kv (fp16 out)
    {
        const int nblk_q  = (NH * DQK) / CBN;    // 24
        const int nblk_kv = (NH * KV_OUT) / CBN; // 32
        mma_gemm_dual_kernel<<<dim3(nblk_q + nblk_kv, MT), blk, GEMM_SMEM>>>(
            qa_h, Wqb_h, qb, NH * DQK, Q_RANK, nblk_q,
            kvan_h, Wkvb_h, kv16, NH * KV_OUT, KV_RANK);
    }
    // 6. rope + scale + head-major Q; k_pe -> fp16
    prep_kernel<<<T_TOK, 256>>>(positions, cs_cache, scaling,
                                qalat + Q_RANK, FUSED_N, qb, qhp, qlp, kpe);
    // 7. flash attention (P hi-only PV)
    flash_mma_kernel<<<dim3(T_TOK / AM, NH), 256, FLASH_SMEM>>>(
        qhp, qlp, kv16, kpe, attn);
    // 8. out = attn @ w_o
    mma_gemm1_kernel<<<dim3(HID / CBN, MT), blk, GEMM_SMEM>>>(
        attn, Wo_h, out, T_TOK, HID, NH * DV);
}

// round 15
// speedup vs baseline: 1.4961x; 1.0038x over previous
#include <cuda_runtime.h>
#include <cuda_fp16.h>
#include <math.h>

// Problem constants
#define T_TOK 3072
#define HID 5120
#define NH 16
#define DN 128
#define DR 64
#define DQK 192       // DN + DR
#define DV 128
#define Q_RANK 1536
#define KV_RANK 512
#define KV_A_OUT (KV_RANK + DR)   // 576
#define KV_OUT (DN + DV)          // 256
#define FUSED_N (Q_RANK + KV_A_OUT)   // 2112

typedef __half hf;

// ---------------------------------------------------------------------------
// Scratch (allocation-free: __device__ globals)
// ---------------------------------------------------------------------------
__device__ hf g_Hh[T_TOK * HID];                     // hidden hi only
__device__ hf g_Wa_h[HID * FUSED_N];                 // fused [5120,2112] hi
__device__ hf g_Wqb_h[Q_RANK * NH * DQK];
__device__ hf g_Wkvb_h[KV_RANK * NH * KV_OUT];
__device__ hf g_Wo_h[NH * DV * HID];
__device__ float g_qalat[T_TOK * FUSED_N];           // fused qa | latent (fp32)
__device__ hf g_qa_h[T_TOK * Q_RANK];
__device__ hf g_kvan_h[T_TOK * KV_RANK];
__device__ float g_q[T_TOK * NH * DQK];
__device__ hf g_kv16[T_TOK * NH * KV_OUT];           // kv GEMM out, fp16 direct
__device__ hf g_kpe[T_TOK * DR];                     // roped k_pe, fp16
// head-major Q for flash
__device__ hf g_qh[NH * T_TOK * DQK], g_ql[NH * T_TOK * DQK];
__device__ hf g_attn[T_TOK * NH * DV];               // attn out, fp16 single

// ---------------------------------------------------------------------------
// PTX helpers
// ---------------------------------------------------------------------------
__device__ __forceinline__ unsigned smem_u32(const void* p) {
    return (unsigned)__cvta_generic_to_shared(p);
}
__device__ __forceinline__ void cp16(unsigned s, const void* g, int srcsz) {
    asm volatile("cp.async.cg.shared.global [%0], [%1], 16, %2;\n"
                 :: "r"(s), "l"(g), "r"(srcsz));
}
__device__ __forceinline__ void cp_commit() {
    asm volatile("cp.async.commit_group;\n" ::);
}
template<int N> __device__ __forceinline__ void cp_wait() {
    asm volatile("cp.async.wait_group %0;\n" :: "n"(N));
}
__device__ __forceinline__ void ldm4(unsigned* d, unsigned a) {
    asm volatile("ldmatrix.sync.aligned.m8n8.x4.shared.b16 {%0,%1,%2,%3}, [%4];\n"
                 : "=r"(d[0]), "=r"(d[1]), "=r"(d[2]), "=r"(d[3]) : "r"(a));
}
__device__ __forceinline__ void ldm4t(unsigned* d, unsigned a) {
    asm volatile("ldmatrix.sync.aligned.m8n8.x4.trans.shared.b16 {%0,%1,%2,%3}, [%4];\n"
                 : "=r"(d[0]), "=r"(d[1]), "=r"(d[2]), "=r"(d[3]) : "r"(a));
}
__device__ __forceinline__ void mma16816(float* c, const unsigned* a, const unsigned* b) {
    asm volatile(
        "mma.sync.aligned.m16n8k16.row.col.f32.f16.f16.f32 "
        "{%0,%1,%2,%3}, {%4,%5,%6,%7}, {%8,%9}, {%0,%1,%2,%3};\n"
        : "+f"(c[0]), "+f"(c[1]), "+f"(c[2]), "+f"(c[3])
        : "r"(a[0]), "r"(a[1]), "r"(a[2]), "r"(a[3]), "r"(b[0]), "r"(b[1]));
}
__device__ __forceinline__ void split1(float x, hf& h, hf& l) {
    h = __float2half_rn(x);
    l = __float2half_rn(x - __half2float(h));
}
__device__ __forceinline__ unsigned packhf(hf a, hf b) {
    __half2 t(a, b);
    return *(unsigned*)&t;
}

// ---------------------------------------------------------------------------
// Fused 4-tensor hi split: hidden, w_q_b, w_kv_b, w_o in one launch.
// ---------------------------------------------------------------------------
__global__ void split4_h_kernel(const float* __restrict__ x0, hf* __restrict__ y0, int n40,
                                const float* __restrict__ x1, hf* __restrict__ y1, int n41,
                                const float* __restrict__ x2, hf* __restrict__ y2, int n42,
                                const float* __restrict__ x3, hf* __restrict__ y3, int n43)
{
    int i = blockIdx.x * blockDim.x + threadIdx.x;
    const float* x; hf* y; int li;
    if (i < n40)                         { x = x0; y = y0; li = i; }
    else if (i < n40 + n41)              { x = x1; y = y1; li = i - n40; }
    else if (i < n40 + n41 + n42)        { x = x2; y = y2; li = i - n40 - n41; }
    else if (i < n40 + n41 + n42 + n43)  { x = x3; y = y3; li = i - n40 - n41 - n42; }
    else return;
    float4 v = ((const float4*)x)[li];
    __half2* H = (__half2*)y;
    H[li * 2]     = __half2(__float2half_rn(v.x), __float2half_rn(v.y));
    H[li * 2 + 1] = __half2(__float2half_rn(v.z), __float2half_rn(v.w));
}

// Fused-weight hi split: w_q_a [5120,1536] | w_kv_a [5120,576] -> [5120,2112]
__global__ void split_fuse_kernel(const float* __restrict__ wqa,
                                  const float* __restrict__ wkva,
                                  hf* __restrict__ hi)
{
    int i = blockIdx.x * blockDim.x + threadIdx.x;
    int total4 = HID * FUSED_N / 4;
    if (i >= total4) return;
    int e0 = i * 4;
    int k = e0 / FUSED_N, n = e0 % FUSED_N;
    float v[4];
    if (n + 3 < Q_RANK) {
        const float* src = wqa + (size_t)k * Q_RANK + n;
        v[0] = src[0]; v[1] = src[1]; v[2] = src[2]; v[3] = src[3];
    } else if (n >= Q_RANK) {
        const float* src = wkva + (size_t)k * KV_A_OUT + (n - Q_RANK);
        v[0] = src[0]; v[1] = src[1]; v[2] = src[2]; v[3] = src[3];
    } else {
#pragma unroll
        for (int j = 0; j < 4; j++) {
            int nn = n + j;
            v[j] = (nn < Q_RANK) ? wqa[(size_t)k * Q_RANK + nn]
                                 : wkva[(size_t)k * KV_A_OUT + (nn - Q_RANK)];
        }
    }
    hf h[4];
#pragma unroll
    for (int j = 0; j < 4; j++) h[j] = __float2half_rn(v[j]);
    *(uint2*)(hi + e0) = *(uint2*)h;
}

// ---------------------------------------------------------------------------
// fp16 single-term tensor-core GEMM:  C = Ah @ Bh.
// CTA 128x128, BK=32, 256 threads, 5-stage cp.async (80KB, 2 CTA/SM),
// XOR-swizzled smem + ldmatrix. Requires K/CBK >= 4.
// ---------------------------------------------------------------------------
#define CBM 128
#define CBN 128
#define CBK 32
#define A_TILE_B 8192
#define B_TILE_B 8192
#define STAGE_B  (A_TILE_B + B_TILE_B)       // 16384
#define NSTAGE 5
#define GEMM_SMEM (NSTAGE * STAGE_B)         // 81920

template<bool OUT16>
__device__ __forceinline__ void gemm_cta(
    char* smem, int tid,
    const hf* __restrict__ Ah,
    const hf* __restrict__ Bh,
    void* __restrict__ Cv, int m0, int n0, int N, int K)
{
    const int lane = tid & 31;
    const int warp = tid >> 5;
    const int wm0 = (warp >> 2) * 64;
    const int wn0 = (warp & 3) * 32;

    float acc[16][4];
#pragma unroll
    for (int i = 0; i < 16; i++)
#pragma unroll
        for (int j = 0; j < 4; j++) acc[i][j] = 0.f;

    auto load_stage = [&](int k0, int s) {
        char* base = smem + s * STAGE_B;
#pragma unroll
        for (int i = 0; i < 2; i++) {
            int ch = tid + i * 256;
            int r = ch >> 2, c = ch & 3;
            int pc = c ^ ((r >> 1) & 3);
            size_t goff = (size_t)(m0 + r) * K + k0 + c * 8;
            cp16(smem_u32(base + r * 64 + pc * 16), Ah + goff, 16);
        }
#pragma unroll
        for (int i = 0; i < 2; i++) {
            int ch = tid + i * 256;
            int r = ch >> 4, c = ch & 15;
            int pc = c ^ (r & 7);
            int gn = n0 + c * 8;
            int sz = (gn < N) ? 16 : 0;
            size_t goff = (size_t)(k0 + r) * N + (gn < N ? gn : 0);
            cp16(smem_u32(base + A_TILE_B + r * 256 + pc * 16), Bh + goff, sz);
        }
    };

    auto compute_stage = [&](int s) {
        char* base = smem + s * STAGE_B;
        unsigned aH = smem_u32(base);
        unsigned bH = aH + A_TILE_B;
#pragma unroll
        for (int kk = 0; kk < 2; kk++) {
            unsigned ah[4][4], bh[4][2];
            const int r_lo = lane & 15;
            const int cch = kk * 2 + (lane >> 4);
#pragma unroll
            for (int mi = 0; mi < 4; mi++) {
                int r = wm0 + mi * 16 + r_lo;
                int pc = cch ^ ((r >> 1) & 3);
                unsigned off = (unsigned)(r * 64 + pc * 16);
                ldm4(ah[mi], aH + off);
            }
            {
                int r = kk * 16 + (lane & 15);
#pragma unroll
                for (int ni = 0; ni < 2; ni++) {
                    int cc = ((wn0 + ni * 16) >> 3) + ((lane >> 4) & 1);
                    int pc = cc ^ (r & 7);
                    unsigned off = (unsigned)(r * 256 + pc * 16);
                    unsigned t[4];
                    ldm4t(t, bH + off);
                    bh[ni * 2][0] = t[0]; bh[ni * 2][1] = t[1];
                    bh[ni * 2 + 1][0] = t[2]; bh[ni * 2 + 1][1] = t[3];
                }
            }
#pragma unroll
            for (int mi = 0; mi < 4; mi++)
#pragma unroll
                for (int nj = 0; nj < 4; nj++)
                    mma16816(acc[mi * 4 + nj], ah[mi], bh[nj]);
        }
    };

    const int KT = K / CBK;   // >= 16 for all shapes used
    load_stage(0, 0); cp_commit();
    load_stage(CBK, 1); cp_commit();
    load_stage(2 * CBK, 2); cp_commit();
    load_stage(3 * CBK, 3); cp_commit();
    for (int kt = 0; kt < KT; kt++) {
        cp_wait<3>();          // stage kt's group complete; 3 newest may be in flight
        __syncthreads();
        if (kt + 4 < KT) load_stage((kt + 4) * CBK, (kt + 4) % NSTAGE);
        cp_commit();           // one group per iteration
        compute_stage(kt % NSTAGE);
    }

#pragma unroll
    for (int mi = 0; mi < 4; mi++) {
        int row = m0 + wm0 + mi * 16 + (lane >> 2);
#pragma unroll
        for (int nj = 0; nj < 4; nj++) {
            int col = n0 + wn0 + nj * 8 + (lane & 3) * 2;
            if (col < N) {
                float* a = acc[mi * 4 + nj];
                if (OUT16) {
                    hf* C = (hf*)Cv;
                    *(__half2*)(C + (size_t)row * N + col) =
                        __half2(__float2half_rn(a[0]), __float2half_rn(a[1]));
                    *(__half2*)(C + (size_t)(row + 8) * N + col) =
                        __half2(__float2half_rn(a[2]), __float2half_rn(a[3]));
                } else {
                    float* C = (float*)Cv;
                    *(float2*)(C + (size_t)row * N + col)       = make_float2(a[0], a[1]);
                    *(float2*)(C + (size_t)(row + 8) * N + col) = make_float2(a[2], a[3]);
                }
            }
        }
    }
}

__global__ __launch_bounds__(256) void mma_gemm1_kernel(
    const hf* __restrict__ Ah,
    const hf* __restrict__ Bh,
    float* __restrict__ C, int M, int N, int K)
{
    extern __shared__ char smem[];
    gemm_cta<false>(smem, threadIdx.x, Ah, Bh, C,
                    blockIdx.y * CBM, blockIdx.x * CBN, N, K);
}

__global__ __launch_bounds__(256) void mma_gemm_dual_kernel(
    const hf* __restrict__ Ah1, const hf* __restrict__ Bh1,
    float* __restrict__ C1, int N1, int K1, int nblk1,
    const hf* __restrict__ Ah2, const hf* __restrict__ Bh2,
    hf* __restrict__ C2, int N2, int K2)
{
    extern __shared__ char smem[];
    const int m0 = blockIdx.y * CBM;
    if ((int)blockIdx.x < nblk1) {
        gemm_cta<false>(smem, threadIdx.x, Ah1, Bh1, C1,
                        m0, blockIdx.x * CBN, N1, K1);
    } else {
        gemm_cta<true>(smem, threadIdx.x, Ah2, Bh2, C2,
                       m0, (blockIdx.x - nblk1) * CBN, N2, K2);
    }
}

// ---------------------------------------------------------------------------
// Fused dual RMSNorm -> fp16 hi: blocks [0,T) do qa (W=1536), [T,2T) kvan (W=512)
// ---------------------------------------------------------------------------
__global__ void rmsnorm2_h_kernel(const float* __restrict__ qalat,
                                  const float* __restrict__ wq,
                                  const float* __restrict__ wkv,
                                  hf* __restrict__ qa_h,
                                  hf* __restrict__ kvan_h)
{
    const int blk = blockIdx.x;
    const bool is_q = blk < T_TOK;
    const int t = is_q ? blk : blk - T_TOK;
    const int W = is_q ? Q_RANK : KV_RANK;
    const float* row = qalat + (size_t)t * FUSED_N + (is_q ? 0 : Q_RANK);
    const float* w = is_q ? wq : wkv;
    hf* out = is_q ? (qa_h + (size_t)t * Q_RANK) : (kvan_h + (size_t)t * KV_RANK);

    float ss = 0.f;
    for (int i = threadIdx.x; i < W; i += blockDim.x) {
        float v = row[i];
        ss += v * v;
    }
    __shared__ float red[32];
#pragma unroll
    for (int o = 16; o; o >>= 1) ss += __shfl_xor_sync(0xffffffffu, ss, o);
    if ((threadIdx.x & 31) == 0) red[threadIdx.x >> 5] = ss;
    __syncthreads();
    if (threadIdx.x < 32) {
        float v = (threadIdx.x < (blockDim.x >> 5)) ? red[threadIdx.x] : 0.f;
#pragma unroll
        for (int o = 16; o; o >>= 1) v += __shfl_xor_sync(0xffffffffu, v, o);
        if (threadIdx.x == 0) red[0] = v;
    }
    __syncthreads();
    const float inv = rsqrtf(red[0] / (float)W + 1e-6f);
    for (int i = threadIdx.x; i < W; i += blockDim.x)
        out[i] = __float2half_rn(row[i] * inv * w[i]);
}

// ---------------------------------------------------------------------------
// Prep: RoPE q_pe (in place) + k_pe (-> fp16 kpe), fold (scaling / sqrt(192))
// into q, emit head-major Q hi/lo (fp16).
// ---------------------------------------------------------------------------
__global__ void prep_kernel(const int* __restrict__ positions,
                            const float* __restrict__ cs_cache,
                            const float* __restrict__ scaling,
                            const float* __restrict__ latent, int lat_stride,
                            float* __restrict__ qb,          // [T,16,192] in/out
                            hf* __restrict__ qh, hf* __restrict__ ql,
                            hf* __restrict__ kpe)            // [T,64] fp16
{
    const int t = blockIdx.x;
    const int pos = positions[t];
    const float* cs = cs_cache + (size_t)pos * DR;
    const float qsc = scaling[t] * 0.07216878364870322f;  // llama4 * 1/sqrt(192)
    float* qrow = qb + (size_t)t * (NH * DQK);

    for (int idx = threadIdx.x; idx < NH * 32; idx += blockDim.x) {
        int hh = idx >> 5, i = idx & 31;
        float c = cs[i], s = cs[32 + i];
        float x1 = qrow[hh * DQK + DN + i];
        float x2 = qrow[hh * DQK + DN + 32 + i];
        qrow[hh * DQK + DN + i]      = x1 * c - x2 * s;
        qrow[hh * DQK + DN + 32 + i] = x2 * c + x1 * s;
    }
    if (threadIdx.x < 32) {
        int i = threadIdx.x;
        float c = cs[i], s = cs[32 + i];
        float x1 = latent[(size_t)t * lat_stride + KV_RANK + i];
        float x2 = latent[(size_t)t * lat_stride + KV_RANK + 32 + i];
        kpe[t * DR + i]      = __float2half_rn(x1 * c - x2 * s);
        kpe[t * DR + 32 + i] = __float2half_rn(x2 * c + x1 * s);
    }
    __syncthreads();
    for (int idx = threadIdx.x; idx < NH * DQK; idx += blockDim.x) {
        int hh = idx / DQK, d = idx % DQK;
        size_t o = ((size_t)hh * T_TOK + t) * DQK + d;
        hf hi, lo;
        split1(qrow[idx] * qsc, hi, lo);
        qh[o] = hi; ql[o] = lo;
    }
}

// ---------------------------------------------------------------------------
// Tensor-core flash attention (causal).
// Q exact (hi+lo) for QK^T; P hi-only for PV; K/V direct from fp16 buffers.
// ---------------------------------------------------------------------------
#define AM 128
#define AN 64
#define FQH 0
#define FQL (FQH + AM*384)
#define FKH (FQL + AM*384)
#define FVH (FKH + AN*384)
#define FLASH_SMEM (FVH + AN*256)    // 139264 B

__global__ __launch_bounds__(256) void flash_mma_kernel(
    const hf* __restrict__ qh, const hf* __restrict__ ql,
    const hf* __restrict__ kv16,   // [T, 16*256]
    const hf* __restrict__ kpe,    // [T, 64]
    hf* __restrict__ attn)
{
    extern __shared__ char smem[];
    const int m0 = blockIdx.x * AM;
    const int h  = blockIdx.y;
    const int tid = threadIdx.x, lane = tid & 31, warp = tid >> 5;
    const int wm = warp * 16;
    const float L2E = 1.4426950408889634f;

    {
        const hf* qh_g = qh + ((size_t)h * T_TOK + m0) * DQK;
        const hf* ql_g = ql + ((size_t)h * T_TOK + m0) * DQK;
        for (int i = tid; i < AM * 24; i += 256) {
            int r = i / 24, c = i % 24, pc = c ^ (r & 7);
            cp16(smem_u32(smem + FQH + r * 384 + pc * 16), qh_g + (size_t)r * DQK + c * 8, 16);
            cp16(smem_u32(smem + FQL + r * 384 + pc * 16), ql_g + (size_t)r * DQK + c * 8, 16);
        }
        cp_commit();
    }

    float o[16][4];
#pragma unroll
    for (int i = 0; i < 16; i++)
#pragma unroll
        for (int j = 0; j < 4; j++) o[i][j] = 0.f;
    float m0r = -1e30f, m1r = -1e30f, l0 = 0.f, l1 = 0.f;

    const unsigned aQh = smem_u32(smem + FQH), aQl = smem_u32(smem + FQL);
    const unsigned aKh = smem_u32(smem + FKH);
    const unsigned aVh = smem_u32(smem + FVH);

    const int ntiles = 2 * blockIdx.x + 2;
    for (int nt = 0; nt < ntiles; nt++) {
        const int n0 = nt * AN;
        __syncthreads();
        {
            const hf* kv_g = kv16 + (size_t)n0 * (NH * KV_OUT) + h * KV_OUT;
            const hf* pe_g = kpe + (size_t)n0 * DR;
            for (int i = tid; i < AN * 24; i += 256) {
                int r = i / 24, c = i % 24, pc = c ^ (r & 7);
                const hf* src = (c < 16)
                    ? kv_g + (size_t)r * (NH * KV_OUT) + c * 8
                    : pe_g + (size_t)r * DR + (c - 16) * 8;
                cp16(smem_u32(smem + FKH + r * 384 + pc * 16), src, 16);
            }
            const hf* v_g = kv_g + DN;
            for (int i = tid; i < AN * 16; i += 256) {
                int r = i >> 4, c = i & 15, pc = c ^ (r & 7);
                cp16(smem_u32(smem + FVH + r * 256 + pc * 16),
                     v_g + (size_t)r * (NH * KV_OUT) + c * 8, 16);
            }
        }
        cp_commit();
        cp_wait<0>();
        __syncthreads();

        float s[8][4];
#pragma unroll
        for (int j = 0; j < 8; j++)
#pragma unroll
            for (int c = 0; c < 4; c++) s[j][c] = 0.f;

#pragma unroll
        for (int kt = 0; kt < 12; kt++) {
            unsigned ah[4], al[4];
            {
                int r = wm + (lane & 15), c = kt * 2 + (lane >> 4);
                int pc = c ^ (r & 7);
                unsigned off = (unsigned)(r * 384 + pc * 16);
                ldm4(ah, aQh + off);
                ldm4(al, aQl + off);
            }
#pragma unroll
            for (int kb = 0; kb < 4; kb++) {
                int r = kb * 16 + (lane & 15), c = kt * 2 + (lane >> 4);
                int pc = c ^ (r & 7);
                unsigned off = (unsigned)(r * 384 + pc * 16);
                unsigned tb[4];
                ldm4(tb, aKh + off);
                unsigned bh0[2] = {tb[0], tb[2]}, bh1[2] = {tb[1], tb[3]};
                mma16816(s[kb * 2], ah, bh0);
                mma16816(s[kb * 2], al, bh0);
                mma16816(s[kb * 2 + 1], ah, bh1);
                mma16816(s[kb * 2 + 1], al, bh1);
            }
        }

        if (n0 + AN > m0) {
            int q0 = m0 + wm + (lane >> 2);
#pragma unroll
            for (int j = 0; j < 8; j++) {
                int k0 = n0 + j * 8 + (lane & 3) * 2;
                if (k0     > q0)     s[j][0] = -1e30f;
                if (k0 + 1 > q0)     s[j][1] = -1e30f;
                if (k0     > q0 + 8) s[j][2] = -1e30f;
                if (k0 + 1 > q0 + 8) s[j][3] = -1e30f;
            }
        }

        float mx0 = -1e30f, mx1 = -1e30f;
#pragma unroll
        for (int j = 0; j < 8; j++) {
            mx0 = fmaxf(mx0, fmaxf(s[j][0], s[j][1]));
            mx1 = fmaxf(mx1, fmaxf(s[j][2], s[j][3]));
        }
        mx0 = fmaxf(mx0, __shfl_xor_sync(0xffffffffu, mx0, 1));
        mx0 = fmaxf(mx0, __shfl_xor_sync(0xffffffffu, mx0, 2));
        mx1 = fmaxf(mx1, __shfl_xor_sync(0xffffffffu, mx1, 1));
        mx1 = fmaxf(mx1, __shfl_xor_sync(0xffffffffu, mx1, 2));
        float mn0 = fmaxf(m0r, mx0), mn1 = fmaxf(m1r, mx1);
        float f0 = exp2f((m0r - mn0) * L2E), f1 = exp2f((m1r - mn1) * L2E);
        m0r = mn0; m1r = mn1;

        unsigned ph[8], ph2[8];
        float sum0 = 0.f, sum1 = 0.f;
#pragma unroll
        for (int j = 0; j < 8; j++) {
            float p0 = exp2f((s[j][0] - mn0) * L2E);
            float p1 = exp2f((s[j][1] - mn0) * L2E);
            float p2 = exp2f((s[j][2] - mn1) * L2E);
            float p3 = exp2f((s[j][3] - mn1) * L2E);
            sum0 += p0 + p1; sum1 += p2 + p3;
            ph[j]  = packhf(__float2half_rn(p0), __float2half_rn(p1));
            ph2[j] = packhf(__float2half_rn(p2), __float2half_rn(p3));
        }
        sum0 += __shfl_xor_sync(0xffffffffu, sum0, 1);
        sum0 += __shfl_xor_sync(0xffffffffu, sum0, 2);
        sum1 += __shfl_xor_sync(0xffffffffu, sum1, 1);
        sum1 += __shfl_xor_sync(0xffffffffu, sum1, 2);
        l0 = l0 * f0 + sum0;
        l1 = l1 * f1 + sum1;
#pragma unroll
        for (int j = 0; j < 16; j++) {
            o[j][0] *= f0; o[j][1] *= f0; o[j][2] *= f1; o[j][3] *= f1;
        }

#pragma unroll
        for (int kt = 0; kt < 4; kt++) {
            unsigned ahp[4] = {ph[2 * kt], ph2[2 * kt], ph[2 * kt + 1], ph2[2 * kt + 1]};
#pragma unroll
            for (int nv = 0; nv < 8; nv++) {
                int r = kt * 16 + (lane & 15), c = nv * 2 + (lane >> 4);
                int pc = c ^ (r & 7);
                unsigned off = (unsigned)(r * 256 + pc * 16);
                unsigned tb[4];
                ldm4t(tb, aVh + off);
                unsigned bh0[2] = {tb[0], tb[1]}, bh1[2] = {tb[2], tb[3]};
                mma16816(o[nv * 2], ahp, bh0);
                mma16816(o[nv * 2 + 1], ahp, bh1);
            }
        }
    }

    float il0 = 1.f / l0, il1 = 1.f / l1;
    int r0 = m0 + wm + (lane >> 2);
#pragma unroll
    for (int j = 0; j < 16; j++) {
        int dv = j * 8 + (lane & 3) * 2;
        size_t off = (size_t)r0 * (NH * DV) + h * DV + dv;
        *(__half2*)(attn + off) =
            __half2(__float2half_rn(o[j][0] * il0), __float2half_rn(o[j][1] * il0));
        off += (size_t)8 * (NH * DV);
        *(__half2*)(attn + off) =
            __half2(__float2half_rn(o[j][2] * il1), __float2half_rn(o[j][3] * il1));
    }
}

// ---------------------------------------------------------------------------
// Launch
// ---------------------------------------------------------------------------
extern "C" void kernel_launch(void* const* d_in, const int* in_sizes, int n_in,
                              void* d_out, int out_size)
{
    const int*   positions = (const int*)  d_in[0];
    const float* hidden    = (const float*)d_in[1];
    const float* scaling   = (const float*)d_in[2];
    const float* w_q_a     = (const float*)d_in[3];
    const float* q_a_ln_w  = (const float*)d_in[4];
    const float* w_q_b     = (const float*)d_in[5];
    const float* w_kv_a    = (const float*)d_in[6];
    const float* kv_a_ln_w = (const float*)d_in[7];
    const float* w_kv_b    = (const float*)d_in[8];
    const float* w_o       = (const float*)d_in[9];
    const float* cs_cache  = (const float*)d_in[10];
    float* out = (float*)d_out;

    hf *Hh, *Wa_h, *Wqb_h, *Wkvb_h, *Wo_h;
    hf *qa_h, *kvan_h;
    hf *qhp, *qlp, *kv16, *kpe, *attn;
    float *qalat, *qb;
    cudaGetSymbolAddress((void**)&Hh, g_Hh);
    cudaGetSymbolAddress((void**)&Wa_h, g_Wa_h);
    cudaGetSymbolAddress((void**)&Wqb_h, g_Wqb_h);
    cudaGetSymbolAddress((void**)&Wkvb_h, g_Wkvb_h);
    cudaGetSymbolAddress((void**)&Wo_h, g_Wo_h);
    cudaGetSymbolAddress((void**)&qa_h, g_qa_h);
    cudaGetSymbolAddress((void**)&kvan_h, g_kvan_h);
    cudaGetSymbolAddress((void**)&qhp, g_qh); cudaGetSymbolAddress((void**)&qlp, g_ql);
    cudaGetSymbolAddress((void**)&kv16, g_kv16);
    cudaGetSymbolAddress((void**)&kpe, g_kpe);
    cudaGetSymbolAddress((void**)&attn, g_attn);
    cudaGetSymbolAddress((void**)&qalat, g_qalat);
    cudaGetSymbolAddress((void**)&qb, g_q);

    cudaFuncSetAttribute(mma_gemm1_kernel, cudaFuncAttributeMaxDynamicSharedMemorySize,
                         GEMM_SMEM);
    cudaFuncSetAttribute(mma_gemm_dual_kernel, cudaFuncAttributeMaxDynamicSharedMemorySize,
                         GEMM_SMEM);
    cudaFuncSetAttribute(flash_mma_kernel, cudaFuncAttributeMaxDynamicSharedMemorySize,
                         FLASH_SMEM);

    // 1. splits: fused w_q_a|w_kv_a; fused (hidden, w_q_b, w_kv_b, w_o)
    {
        int total4 = HID * FUSED_N / 4;
        split_fuse_kernel<<<(total4 + 255) / 256, 256>>>(w_q_a, w_kv_a, Wa_h);
    }
    {
        int n40 = T_TOK * HID / 4;
        int n41 = Q_RANK * NH * DQK / 4;
        int n42 = KV_RANK * NH * KV_OUT / 4;
        int n43 = NH * DV * HID / 4;
        int tot = n40 + n41 + n42 + n43;
        split4_h_kernel<<<(tot + 255) / 256, 256>>>(
            hidden, Hh, n40, w_q_b, Wqb_h, n41, w_kv_b, Wkvb_h, n42, w_o, Wo_h, n43);
    }

    const dim3 blk(256);
    const int MT = T_TOK / CBM;  // 24

    // 2. [qa | latent] = hidden @ [w_q_a | w_kv_a]
    mma_gemm1_kernel<<<dim3((FUSED_N + CBN - 1) / CBN, MT), blk, GEMM_SMEM>>>(
        Hh, Wa_h, qalat, T_TOK, FUSED_N, HID);
    // 3. fused dual rmsnorm -> fp16 hi
    rmsnorm2_h_kernel<<<2 * T_TOK, 256>>>(qalat, q_a_ln_w, kv_a_ln_w, qa_h, kvan_h);
    // 4+5 fused: q (fp32 out) AND kv (fp16 out)
    {
        const int nblk_q  = (NH * DQK) / CBN;    // 24
        const int nblk_kv = (NH * KV_OUT) / CBN; // 32
        mma_gemm_dual_kernel<<<dim3(nblk_q + nblk_kv, MT), blk, GEMM_SMEM>>>(
            qa_h, Wqb_h, qb, NH * DQK, Q_RANK, nblk_q,
            kvan_h, Wkvb_h, kv16, NH * KV_OUT, KV_RANK);
    }
    // 6. rope + scale + head-major Q; k_pe -> fp16
    prep_kernel<<<T_TOK, 256>>>(positions, cs_cache, scaling,
                                qalat + Q_RANK, FUSED_N, qb, qhp, qlp, kpe);
    // 7. flash attention
    flash_mma_kernel<<<dim3(T_TOK / AM, NH), 256, FLASH_SMEM>>>(
        qhp, qlp, kv16, kpe, attn);
    // 8. out = attn @ w_o
    mma_gemm1_kernel<<<dim3(HID / CBN, MT), blk, GEMM_SMEM>>>(
        attn, Wo_h, out, T_TOK, HID, NH * DV);
}

// round 16
// speedup vs baseline: 1.5315x; 1.0236x over previous
#include <cuda_runtime.h>
#include <cuda_fp16.h>
#include <math.h>

// Problem constants
#define T_TOK 3072
#define HID 5120
#define NH 16
#define DN 128
#define DR 64
#define DQK 192       // DN + DR
#define DV 128
#define Q_RANK 1536
#define KV_RANK 512
#define KV_A_OUT (KV_RANK + DR)   // 576
#define KV_OUT (DN + DV)          // 256
#define FUSED_N (Q_RANK + KV_A_OUT)   // 2112

typedef __half hf;

// ---------------------------------------------------------------------------
// Scratch (allocation-free: __device__ globals)
// ---------------------------------------------------------------------------
__device__ hf g_Hh[T_TOK * HID];                     // hidden hi only
__device__ hf g_Wa_h[HID * FUSED_N];                 // fused [5120,2112] hi
__device__ hf g_Wqb_h[Q_RANK * NH * DQK];
__device__ hf g_Wkvb_h[KV_RANK * NH * KV_OUT];
__device__ hf g_Wo_h[NH * DV * HID];
__device__ float g_qalat[T_TOK * FUSED_N];           // fused qa | latent (fp32)
__device__ hf g_qa_h[T_TOK * Q_RANK];
__device__ hf g_kvan_h[T_TOK * KV_RANK];
__device__ float g_q[T_TOK * NH * DQK];
__device__ hf g_kv16[T_TOK * NH * KV_OUT];           // kv GEMM out, fp16 direct
__device__ hf g_kpe[T_TOK * DR];                     // roped k_pe, fp16
// head-major Q for flash
__device__ hf g_qh[NH * T_TOK * DQK], g_ql[NH * T_TOK * DQK];
__device__ hf g_attn[T_TOK * NH * DV];               // attn out, fp16 single

// ---------------------------------------------------------------------------
// PTX helpers
// ---------------------------------------------------------------------------
__device__ __forceinline__ unsigned smem_u32(const void* p) {
    return (unsigned)__cvta_generic_to_shared(p);
}
__device__ __forceinline__ void cp16(unsigned s, const void* g, int srcsz) {
    asm volatile("cp.async.cg.shared.global [%0], [%1], 16, %2;\n"
                 :: "r"(s), "l"(g), "r"(srcsz));
}
__device__ __forceinline__ void cp_commit() {
    asm volatile("cp.async.commit_group;\n" ::);
}
template<int N> __device__ __forceinline__ void cp_wait() {
    asm volatile("cp.async.wait_group %0;\n" :: "n"(N));
}
__device__ __forceinline__ void ldm4(unsigned* d, unsigned a) {
    asm volatile("ldmatrix.sync.aligned.m8n8.x4.shared.b16 {%0,%1,%2,%3}, [%4];\n"
                 : "=r"(d[0]), "=r"(d[1]), "=r"(d[2]), "=r"(d[3]) : "r"(a));
}
__device__ __forceinline__ void ldm4t(unsigned* d, unsigned a) {
    asm volatile("ldmatrix.sync.aligned.m8n8.x4.trans.shared.b16 {%0,%1,%2,%3}, [%4];\n"
                 : "=r"(d[0]), "=r"(d[1]), "=r"(d[2]), "=r"(d[3]) : "r"(a));
}
__device__ __forceinline__ void mma16816(float* c, const unsigned* a, const unsigned* b) {
    asm volatile(
        "mma.sync.aligned.m16n8k16.row.col.f32.f16.f16.f32 "
        "{%0,%1,%2,%3}, {%4,%5,%6,%7}, {%8,%9}, {%0,%1,%2,%3};\n"
        : "+f"(c[0]), "+f"(c[1]), "+f"(c[2]), "+f"(c[3])
        : "r"(a[0]), "r"(a[1]), "r"(a[2]), "r"(a[3]), "r"(b[0]), "r"(b[1]));
}
__device__ __forceinline__ void split1(float x, hf& h, hf& l) {
    h = __float2half_rn(x);
    l = __float2half_rn(x - __half2float(h));
}
__device__ __forceinline__ unsigned packhf(hf a, hf b) {
    __half2 t(a, b);
    return *(unsigned*)&t;
}

// ---------------------------------------------------------------------------
// Fused 4-tensor hi split with 4x batched loads (MLP=4 per thread).
// ---------------------------------------------------------------------------
__global__ void split4_h_kernel(const float* __restrict__ x0, hf* __restrict__ y0, int n40,
                                const float* __restrict__ x1, hf* __restrict__ y1, int n41,
                                const float* __restrict__ x2, hf* __restrict__ y2, int n42,
                                const float* __restrict__ x3, hf* __restrict__ y3, int n43)
{
    const int base = blockIdx.x * 1024 + threadIdx.x;   // 4 chunks per thread
    const int tot = n40 + n41 + n42 + n43;
    const float* xs[4]; __half2* ys[4]; int lis[4]; bool ok[4];
#pragma unroll
    for (int j = 0; j < 4; j++) {
        int i = base + j * 256;
        ok[j] = i < tot;
        int li = i;
        const float* x = x0; hf* y = y0;
        if (ok[j]) {
            if (i < n40)                   { x = x0; y = y0; li = i; }
            else if (i < n40 + n41)        { x = x1; y = y1; li = i - n40; }
            else if (i < n40 + n41 + n42)  { x = x2; y = y2; li = i - n40 - n41; }
            else                           { x = x3; y = y3; li = i - n40 - n41 - n42; }
        }
        xs[j] = x; ys[j] = (__half2*)y; lis[j] = li;
    }
    float4 v[4];
#pragma unroll
    for (int j = 0; j < 4; j++)
        if (ok[j]) v[j] = ((const float4*)xs[j])[lis[j]];
#pragma unroll
    for (int j = 0; j < 4; j++)
        if (ok[j]) {
            ys[j][lis[j] * 2]     = __half2(__float2half_rn(v[j].x), __float2half_rn(v[j].y));
            ys[j][lis[j] * 2 + 1] = __half2(__float2half_rn(v[j].z), __float2half_rn(v[j].w));
        }
}

// Fused-weight hi split: w_q_a [5120,1536] | w_kv_a [5120,576] -> [5120,2112]
// 4x batched loads.
__global__ void split_fuse_kernel(const float* __restrict__ wqa,
                                  const float* __restrict__ wkva,
                                  hf* __restrict__ hi)
{
    const int total4 = HID * FUSED_N / 4;
    const int base = blockIdx.x * 1024 + threadIdx.x;
    const float* srcs[4]; bool ok[4], straddle[4]; int e0s[4];
#pragma unroll
    for (int j = 0; j < 4; j++) {
        int i = base + j * 256;
        ok[j] = i < total4;
        int e0 = i * 4;
        e0s[j] = e0;
        int k = e0 / FUSED_N, n = e0 % FUSED_N;
        straddle[j] = false;
        srcs[j] = wqa;
        if (ok[j]) {
            if (n + 3 < Q_RANK)      srcs[j] = wqa + (size_t)k * Q_RANK + n;
            else if (n >= Q_RANK)    srcs[j] = wkva + (size_t)k * KV_A_OUT + (n - Q_RANK);
            else                     straddle[j] = true;
        }
    }
    float4 v[4];
#pragma unroll
    for (int j = 0; j < 4; j++) {
        if (!ok[j]) continue;
        if (!straddle[j]) {
            v[j] = make_float4(srcs[j][0], srcs[j][1], srcs[j][2], srcs[j][3]);
        } else {
            int e0 = e0s[j];
            int k = e0 / FUSED_N, n = e0 % FUSED_N;
            float t[4];
#pragma unroll
            for (int q = 0; q < 4; q++) {
                int nn = n + q;
                t[q] = (nn < Q_RANK) ? wqa[(size_t)k * Q_RANK + nn]
                                     : wkva[(size_t)k * KV_A_OUT + (nn - Q_RANK)];
            }
            v[j] = make_float4(t[0], t[1], t[2], t[3]);
        }
    }
#pragma unroll
    for (int j = 0; j < 4; j++) {
        if (!ok[j]) continue;
        hf h[4];
        h[0] = __float2half_rn(v[j].x); h[1] = __float2half_rn(v[j].y);
        h[2] = __float2half_rn(v[j].z); h[3] = __float2half_rn(v[j].w);
        *(uint2*)(hi + e0s[j]) = *(uint2*)h;
    }
}

// ---------------------------------------------------------------------------
// fp16 single-term tensor-core GEMM:  C = Ah @ Bh.
// CTA 128x128, BK=32, 256 threads, 5-stage cp.async, XOR-swizzled smem.
// ---------------------------------------------------------------------------
#define CBM 128
#define CBN 128
#define CBK 32
#define A_TILE_B 8192
#define B_TILE_B 8192
#define STAGE_B  (A_TILE_B + B_TILE_B)       // 16384
#define NSTAGE 5
#define GEMM_SMEM (NSTAGE * STAGE_B)         // 81920

template<bool OUT16>
__device__ __forceinline__ void gemm_cta(
    char* smem, int tid,
    const hf* __restrict__ Ah,
    const hf* __restrict__ Bh,
    void* __restrict__ Cv, int m0, int n0, int N, int K)
{
    const int lane = tid & 31;
    const int warp = tid >> 5;
    const int wm0 = (warp >> 2) * 64;
    const int wn0 = (warp & 3) * 32;

    float acc[16][4];
#pragma unroll
    for (int i = 0; i < 16; i++)
#pragma unroll
        for (int j = 0; j < 4; j++) acc[i][j] = 0.f;

    auto load_stage = [&](int k0, int s) {
        char* base = smem + s * STAGE_B;
#pragma unroll
        for (int i = 0; i < 2; i++) {
            int ch = tid + i * 256;
            int r = ch >> 2, c = ch & 3;
            int pc = c ^ ((r >> 1) & 3);
            size_t goff = (size_t)(m0 + r) * K + k0 + c * 8;
            cp16(smem_u32(base + r * 64 + pc * 16), Ah + goff, 16);
        }
#pragma unroll
        for (int i = 0; i < 2; i++) {
            int ch = tid + i * 256;
            int r = ch >> 4, c = ch & 15;
            int pc = c ^ (r & 7);
            int gn = n0 + c * 8;
            int sz = (gn < N) ? 16 : 0;
            size_t goff = (size_t)(k0 + r) * N + (gn < N ? gn : 0);
            cp16(smem_u32(base + A_TILE_B + r * 256 + pc * 16), Bh + goff, sz);
        }
    };

    auto compute_stage = [&](int s) {
        char* base = smem + s * STAGE_B;
        unsigned aH = smem_u32(base);
        unsigned bH = aH + A_TILE_B;
#pragma unroll
        for (int kk = 0; kk < 2; kk++) {
            unsigned ah[4][4], bh[4][2];
            const int r_lo = lane & 15;
            const int cch = kk * 2 + (lane >> 4);
#pragma unroll
            for (int mi = 0; mi < 4; mi++) {
                int r = wm0 + mi * 16 + r_lo;
                int pc = cch ^ ((r >> 1) & 3);
                unsigned off = (unsigned)(r * 64 + pc * 16);
                ldm4(ah[mi], aH + off);
            }
            {
                int r = kk * 16 + (lane & 15);
#pragma unroll
                for (int ni = 0; ni < 2; ni++) {
                    int cc = ((wn0 + ni * 16) >> 3) + ((lane >> 4) & 1);
                    int pc = cc ^ (r & 7);
                    unsigned off = (unsigned)(r * 256 + pc * 16);
                    unsigned t[4];
                    ldm4t(t, bH + off);
                    bh[ni * 2][0] = t[0]; bh[ni * 2][1] = t[1];
                    bh[ni * 2 + 1][0] = t[2]; bh[ni * 2 + 1][1] = t[3];
                }
            }
#pragma unroll
            for (int mi = 0; mi < 4; mi++)
#pragma unroll
                for (int nj = 0; nj < 4; nj++)
                    mma16816(acc[mi * 4 + nj], ah[mi], bh[nj]);
        }
    };

    const int KT = K / CBK;
    load_stage(0, 0); cp_commit();
    load_stage(CBK, 1); cp_commit();
    load_stage(2 * CBK, 2); cp_commit();
    load_stage(3 * CBK, 3); cp_commit();
    for (int kt = 0; kt < KT; kt++) {
        cp_wait<3>();
        __syncthreads();
        if (kt + 4 < KT) load_stage((kt + 4) * CBK, (kt + 4) % NSTAGE);
        cp_commit();
        compute_stage(kt % NSTAGE);
    }

#pragma unroll
    for (int mi = 0; mi < 4; mi++) {
        int row = m0 + wm0 + mi * 16 + (lane >> 2);
#pragma unroll
        for (int nj = 0; nj < 4; nj++) {
            int col = n0 + wn0 + nj * 8 + (lane & 3) * 2;
            if (col < N) {
                float* a = acc[mi * 4 + nj];
                if (OUT16) {
                    hf* C = (hf*)Cv;
                    *(__half2*)(C + (size_t)row * N + col) =
                        __half2(__float2half_rn(a[0]), __float2half_rn(a[1]));
                    *(__half2*)(C + (size_t)(row + 8) * N + col) =
                        __half2(__float2half_rn(a[2]), __float2half_rn(a[3]));
                } else {
                    float* C = (float*)Cv;
                    *(float2*)(C + (size_t)row * N + col)       = make_float2(a[0], a[1]);
                    *(float2*)(C + (size_t)(row + 8) * N + col) = make_float2(a[2], a[3]);
                }
            }
        }
    }
}

__global__ __launch_bounds__(256) void mma_gemm1_kernel(
    const hf* __restrict__ Ah,
    const hf* __restrict__ Bh,
    float* __restrict__ C, int M, int N, int K)
{
    extern __shared__ char smem[];
    gemm_cta<false>(smem, threadIdx.x, Ah, Bh, C,
                    blockIdx.y * CBM, blockIdx.x * CBN, N, K);
}

__global__ __launch_bounds__(256) void mma_gemm_dual_kernel(
    const hf* __restrict__ Ah1, const hf* __restrict__ Bh1,
    float* __restrict__ C1, int N1, int K1, int nblk1,
    const hf* __restrict__ Ah2, const hf* __restrict__ Bh2,
    hf* __restrict__ C2, int N2, int K2)
{
    extern __shared__ char smem[];
    const int m0 = blockIdx.y * CBM;
    if ((int)blockIdx.x < nblk1) {
        gemm_cta<false>(smem, threadIdx.x, Ah1, Bh1, C1,
                        m0, blockIdx.x * CBN, N1, K1);
    } else {
        gemm_cta<true>(smem, threadIdx.x, Ah2, Bh2, C2,
                       m0, (blockIdx.x - nblk1) * CBN, N2, K2);
    }
}

// ---------------------------------------------------------------------------
// Fused dual RMSNorm -> fp16 hi
// ---------------------------------------------------------------------------
__global__ void rmsnorm2_h_kernel(const float* __restrict__ qalat,
                                  const float* __restrict__ wq,
                                  const float* __restrict__ wkv,
                                  hf* __restrict__ qa_h,
                                  hf* __restrict__ kvan_h)
{
    const int blk = blockIdx.x;
    const bool is_q = blk < T_TOK;
    const int t = is_q ? blk : blk - T_TOK;
    const int W = is_q ? Q_RANK : KV_RANK;
    const float* row = qalat + (size_t)t * FUSED_N + (is_q ? 0 : Q_RANK);
    const float* w = is_q ? wq : wkv;
    hf* out = is_q ? (qa_h + (size_t)t * Q_RANK) : (kvan_h + (size_t)t * KV_RANK);

    float ss = 0.f;
    for (int i = threadIdx.x; i < W; i += blockDim.x) {
        float v = row[i];
        ss += v * v;
    }
    __shared__ float red[32];
#pragma unroll
    for (int o = 16; o; o >>= 1) ss += __shfl_xor_sync(0xffffffffu, ss, o);
    if ((threadIdx.x & 31) == 0) red[threadIdx.x >> 5] = ss;
    __syncthreads();
    if (threadIdx.x < 32) {
        float v = (threadIdx.x < (blockDim.x >> 5)) ? red[threadIdx.x] : 0.f;
#pragma unroll
        for (int o = 16; o; o >>= 1) v += __shfl_xor_sync(0xffffffffu, v, o);
        if (threadIdx.x == 0) red[0] = v;
    }
    __syncthreads();
    const float inv = rsqrtf(red[0] / (float)W + 1e-6f);
    for (int i = threadIdx.x; i < W; i += blockDim.x)
        out[i] = __float2half_rn(row[i] * inv * w[i]);
}

// ---------------------------------------------------------------------------
// Prep: RoPE q_pe (in place) + k_pe (-> fp16 kpe), fold scale into q,
// emit head-major Q hi/lo (fp16).
// ---------------------------------------------------------------------------
__global__ void prep_kernel(const int* __restrict__ positions,
                            const float* __restrict__ cs_cache,
                            const float* __restrict__ scaling,
                            const float* __restrict__ latent, int lat_stride,
                            float* __restrict__ qb,          // [T,16,192] in/out
                            hf* __restrict__ qh, hf* __restrict__ ql,
                            hf* __restrict__ kpe)            // [T,64] fp16
{
    const int t = blockIdx.x;
    const int pos = positions[t];
    const float* cs = cs_cache + (size_t)pos * DR;
    const float qsc = scaling[t] * 0.07216878364870322f;  // llama4 * 1/sqrt(192)
    float* qrow = qb + (size_t)t * (NH * DQK);

    for (int idx = threadIdx.x; idx < NH * 32; idx += blockDim.x) {
        int hh = idx >> 5, i = idx & 31;
        float c = cs[i], s = cs[32 + i];
        float x1 = qrow[hh * DQK + DN + i];
        float x2 = qrow[hh * DQK + DN + 32 + i];
        qrow[hh * DQK + DN + i]      = x1 * c - x2 * s;
        qrow[hh * DQK + DN + 32 + i] = x2 * c + x1 * s;
    }
    if (threadIdx.x < 32) {
        int i = threadIdx.x;
        float c = cs[i], s = cs[32 + i];
        float x1 = latent[(size_t)t * lat_stride + KV_RANK + i];
        float x2 = latent[(size_t)t * lat_stride + KV_RANK + 32 + i];
        kpe[t * DR + i]      = __float2half_rn(x1 * c - x2 * s);
        kpe[t * DR + 32 + i] = __float2half_rn(x2 * c + x1 * s);
    }
    __syncthreads();
    for (int idx = threadIdx.x; idx < NH * DQK; idx += blockDim.x) {
        int hh = idx / DQK, d = idx % DQK;
        size_t o = ((size_t)hh * T_TOK + t) * DQK + d;
        hf hi, lo;
        split1(qrow[idx] * qsc, hi, lo);
        qh[o] = hi; ql[o] = lo;
    }
}

// ---------------------------------------------------------------------------
// Tensor-core flash attention (causal), K/V double-buffered.
// Q exact (hi+lo) for QK^T; P hi-only for PV.
// ---------------------------------------------------------------------------
#define AM 128
#define AN 64
#define FQH 0
#define FQL (FQH + AM*384)            // 49152
#define FK0 (FQL + AM*384)            // 98304
#define FK1 (FK0 + AN*384)            // 122880
#define FV0 (FK1 + AN*384)            // 147456
#define FV1 (FV0 + AN*256)            // 163840
#define FLASH_SMEM (FV1 + AN*256)     // 180224 B

__global__ __launch_bounds__(256) void flash_mma_kernel(
    const hf* __restrict__ qh, const hf* __restrict__ ql,
    const hf* __restrict__ kv16,   // [T, 16*256]
    const hf* __restrict__ kpe,    // [T, 64]
    hf* __restrict__ attn)
{
    extern __shared__ char smem[];
    const int m0 = blockIdx.x * AM;
    const int h  = blockIdx.y;
    const int tid = threadIdx.x, lane = tid & 31, warp = tid >> 5;
    const int wm = warp * 16;
    const float L2E = 1.4426950408889634f;

    // Q load (own cp.async group)
    {
        const hf* qh_g = qh + ((size_t)h * T_TOK + m0) * DQK;
        const hf* ql_g = ql + ((size_t)h * T_TOK + m0) * DQK;
        for (int i = tid; i < AM * 24; i += 256) {
            int r = i / 24, c = i % 24, pc = c ^ (r & 7);
            cp16(smem_u32(smem + FQH + r * 384 + pc * 16), qh_g + (size_t)r * DQK + c * 8, 16);
            cp16(smem_u32(smem + FQL + r * 384 + pc * 16), ql_g + (size_t)r * DQK + c * 8, 16);
        }
        cp_commit();
    }

    auto load_kv = [&](int nt, int b) {
        const int n0 = nt * AN;
        char* kb = smem + (b ? FK1 : FK0);
        char* vb = smem + (b ? FV1 : FV0);
        const hf* kv_g = kv16 + (size_t)n0 * (NH * KV_OUT) + h * KV_OUT;
        const hf* pe_g = kpe + (size_t)n0 * DR;
        for (int i = tid; i < AN * 24; i += 256) {
            int r = i / 24, c = i % 24, pc = c ^ (r & 7);
            const hf* src = (c < 16)
                ? kv_g + (size_t)r * (NH * KV_OUT) + c * 8
                : pe_g + (size_t)r * DR + (c - 16) * 8;
            cp16(smem_u32(kb + r * 384 + pc * 16), src, 16);
        }
        const hf* v_g = kv_g + DN;
        for (int i = tid; i < AN * 16; i += 256) {
            int r = i >> 4, c = i & 15, pc = c ^ (r & 7);
            cp16(smem_u32(vb + r * 256 + pc * 16),
                 v_g + (size_t)r * (NH * KV_OUT) + c * 8, 16);
        }
    };

    float o[16][4];
#pragma unroll
    for (int i = 0; i < 16; i++)
#pragma unroll
        for (int j = 0; j < 4; j++) o[i][j] = 0.f;
    float m0r = -1e30f, m1r = -1e30f, l0 = 0.f, l1 = 0.f;

    const unsigned aQh = smem_u32(smem + FQH), aQl = smem_u32(smem + FQL);

    const int ntiles = 2 * blockIdx.x + 2;
    load_kv(0, 0); cp_commit();

    for (int nt = 0; nt < ntiles; nt++) {
        const int n0 = nt * AN;
        const int b = nt & 1;
        if (nt + 1 < ntiles) load_kv(nt + 1, (nt + 1) & 1);
        cp_commit();           // exactly one group per iteration
        cp_wait<1>();          // tile nt (and Q on iter 0) complete
        __syncthreads();

        const unsigned aKh = smem_u32(smem + (b ? FK1 : FK0));
        const unsigned aVh = smem_u32(smem + (b ? FV1 : FV0));

        float s[8][4];
#pragma unroll
        for (int j = 0; j < 8; j++)
#pragma unroll
            for (int c = 0; c < 4; c++) s[j][c] = 0.f;

#pragma unroll
        for (int kt = 0; kt < 12; kt++) {
            unsigned ah[4], al[4];
            {
                int r = wm + (lane & 15), c = kt * 2 + (lane >> 4);
                int pc = c ^ (r & 7);
                unsigned off = (unsigned)(r * 384 + pc * 16);
                ldm4(ah, aQh + off);
                ldm4(al, aQl + off);
            }
#pragma unroll
            for (int kb = 0; kb < 4; kb++) {
                int r = kb * 16 + (lane & 15), c = kt * 2 + (lane >> 4);
                int pc = c ^ (r & 7);
                unsigned off = (unsigned)(r * 384 + pc * 16);
                unsigned tb[4];
                ldm4(tb, aKh + off);
                unsigned bh0[2] = {tb[0], tb[2]}, bh1[2] = {tb[1], tb[3]};
                mma16816(s[kb * 2], ah, bh0);
                mma16816(s[kb * 2], al, bh0);
                mma16816(s[kb * 2 + 1], ah, bh1);
                mma16816(s[kb * 2 + 1], al, bh1);
            }
        }

        if (n0 + AN > m0) {
            int q0 = m0 + wm + (lane >> 2);
#pragma unroll
            for (int j = 0; j < 8; j++) {
                int k0 = n0 + j * 8 + (lane & 3) * 2;
                if (k0     > q0)     s[j][0] = -1e30f;
                if (k0 + 1 > q0)     s[j][1] = -1e30f;
                if (k0     > q0 + 8) s[j][2] = -1e30f;
                if (k0 + 1 > q0 + 8) s[j][3] = -1e30f;
            }
        }

        float mx0 = -1e30f, mx1 = -1e30f;
#pragma unroll
        for (int j = 0; j < 8; j++) {
            mx0 = fmaxf(mx0, fmaxf(s[j][0], s[j][1]));
            mx1 = fmaxf(mx1, fmaxf(s[j][2], s[j][3]));
        }
        mx0 = fmaxf(mx0, __shfl_xor_sync(0xffffffffu, mx0, 1));
        mx0 = fmaxf(mx0, __shfl_xor_sync(0xffffffffu, mx0, 2));
        mx1 = fmaxf(mx1, __shfl_xor_sync(0xffffffffu, mx1, 1));
        mx1 = fmaxf(mx1, __shfl_xor_sync(0xffffffffu, mx1, 2));
        float mn0 = fmaxf(m0r, mx0), mn1 = fmaxf(m1r, mx1);
        float f0 = exp2f((m0r - mn0) * L2E), f1 = exp2f((m1r - mn1) * L2E);
        m0r = mn0; m1r = mn1;

        unsigned ph[8], ph2[8];
        float sum0 = 0.f, sum1 = 0.f;
#pragma unroll
        for (int j = 0; j < 8; j++) {
            float p0 = exp2f((s[j][0] - mn0) * L2E);
            float p1 = exp2f((s[j][1] - mn0) * L2E);
            float p2 = exp2f((s[j][2] - mn1) * L2E);
            float p3 = exp2f((s[j][3] - mn1) * L2E);
            sum0 += p0 + p1; sum1 += p2 + p3;
            ph[j]  = packhf(__float2half_rn(p0), __float2half_rn(p1));
            ph2[j] = packhf(__float2half_rn(p2), __float2half_rn(p3));
        }
        sum0 += __shfl_xor_sync(0xffffffffu, sum0, 1);
        sum0 += __shfl_xor_sync(0xffffffffu, sum0, 2);
        sum1 += __shfl_xor_sync(0xffffffffu, sum1, 1);
        sum1 += __shfl_xor_sync(0xffffffffu, sum1, 2);
        l0 = l0 * f0 + sum0;
        l1 = l1 * f1 + sum1;
#pragma unroll
        for (int j = 0; j < 16; j++) {
            o[j][0] *= f0; o[j][1] *= f0; o[j][2] *= f1; o[j][3] *= f1;
        }

#pragma unroll
        for (int kt = 0; kt < 4; kt++) {
            unsigned ahp[4] = {ph[2 * kt], ph2[2 * kt], ph[2 * kt + 1], ph2[2 * kt + 1]};
#pragma unroll
            for (int nv = 0; nv < 8; nv++) {
                int r = kt * 16 + (lane & 15), c = nv * 2 + (lane >> 4);
                int pc = c ^ (r & 7);
                unsigned off = (unsigned)(r * 256 + pc * 16);
                unsigned tb[4];
                ldm4t(tb, aVh + off);
                unsigned bh0[2] = {tb[0], tb[1]}, bh1[2] = {tb[2], tb[3]};
                mma16816(o[nv * 2], ahp, bh0);
                mma16816(o[nv * 2 + 1], ahp, bh1);
            }
        }
        __syncthreads();   // all warps done with buffer b before iter nt+1 overwrites it
    }

    float il0 = 1.f / l0, il1 = 1.f / l1;
    int r0 = m0 + wm + (lane >> 2);
#pragma unroll
    for (int j = 0; j < 16; j++) {
        int dv = j * 8 + (lane & 3) * 2;
        size_t off = (size_t)r0 * (NH * DV) + h * DV + dv;
        *(__half2*)(attn + off) =
            __half2(__float2half_rn(o[j][0] * il0), __float2half_rn(o[j][1] * il0));
        off += (size_t)8 * (NH * DV);
        *(__half2*)(attn + off) =
            __half2(__float2half_rn(o[j][2] * il1), __float2half_rn(o[j][3] * il1));
    }
}

// ---------------------------------------------------------------------------
// Launch
// ---------------------------------------------------------------------------
extern "C" void kernel_launch(void* const* d_in, const int* in_sizes, int n_in,
                              void* d_out, int out_size)
{
    const int*   positions = (const int*)  d_in[0];
    const float* hidden    = (const float*)d_in[1];
    const float* scaling   = (const float*)d_in[2];
    const float* w_q_a     = (const float*)d_in[3];
    const float* q_a_ln_w  = (const float*)d_in[4];
    const float* w_q_b     = (const float*)d_in[5];
    const float* w_kv_a    = (const float*)d_in[6];
    const float* kv_a_ln_w = (const float*)d_in[7];
    const float* w_kv_b    = (const float*)d_in[8];
    const float* w_o       = (const float*)d_in[9];
    const float* cs_cache  = (const float*)d_in[10];
    float* out = (float*)d_out;

    hf *Hh, *Wa_h, *Wqb_h, *Wkvb_h, *Wo_h;
    hf *qa_h, *kvan_h;
    hf *qhp, *qlp, *kv16, *kpe, *attn;
    float *qalat, *qb;
    cudaGetSymbolAddress((void**)&Hh, g_Hh);
    cudaGetSymbolAddress((void**)&Wa_h, g_Wa_h);
    cudaGetSymbolAddress((void**)&Wqb_h, g_Wqb_h);
    cudaGetSymbolAddress((void**)&Wkvb_h, g_Wkvb_h);
    cudaGetSymbolAddress((void**)&Wo_h, g_Wo_h);
    cudaGetSymbolAddress((void**)&qa_h, g_qa_h);
    cudaGetSymbolAddress((void**)&kvan_h, g_kvan_h);
    cudaGetSymbolAddress((void**)&qhp, g_qh); cudaGetSymbolAddress((void**)&qlp, g_ql);
    cudaGetSymbolAddress((void**)&kv16, g_kv16);
    cudaGetSymbolAddress((void**)&kpe, g_kpe);
    cudaGetSymbolAddress((void**)&attn, g_attn);
    cudaGetSymbolAddress((void**)&qalat, g_qalat);
    cudaGetSymbolAddress((void**)&qb, g_q);

    cudaFuncSetAttribute(mma_gemm1_kernel, cudaFuncAttributeMaxDynamicSharedMemorySize,
                         GEMM_SMEM);
    cudaFuncSetAttribute(mma_gemm_dual_kernel, cudaFuncAttributeMaxDynamicSharedMemorySize,
                         GEMM_SMEM);
    cudaFuncSetAttribute(flash_mma_kernel, cudaFuncAttributeMaxDynamicSharedMemorySize,
                         FLASH_SMEM);

    // 1. splits (4x batched loads)
    {
        int total4 = HID * FUSED_N / 4;
        split_fuse_kernel<<<(total4 + 1023) / 1024, 256>>>(w_q_a, w_kv_a, Wa_h);
    }
    {
        int n40 = T_TOK * HID / 4;
        int n41 = Q_RANK * NH * DQK / 4;
        int n42 = KV_RANK * NH * KV_OUT / 4;
        int n43 = NH * DV * HID / 4;
        int tot = n40 + n41 + n42 + n43;
        split4_h_kernel<<<(tot + 1023) / 1024, 256>>>(
            hidden, Hh, n40, w_q_b, Wqb_h, n41, w_kv_b, Wkvb_h, n42, w_o, Wo_h, n43);
    }

    const dim3 blk(256);
    const int MT = T_TOK / CBM;  // 24

    // 2. [qa | latent] = hidden @ [w_q_a | w_kv_a]
    mma_gemm1_kernel<<<dim3((FUSED_N + CBN - 1) / CBN, MT), blk, GEMM_SMEM>>>(
        Hh, Wa_h, qalat, T_TOK, FUSED_N, HID);
    // 3. fused dual rmsnorm -> fp16 hi
    rmsnorm2_h_kernel<<<2 * T_TOK, 256>>>(qalat, q_a_ln_w, kv_a_ln_w, qa_h, kvan_h);
    // 4+5 fused: q (fp32 out) AND kv (fp16 out)
    {
        const int nblk_q  = (NH * DQK) / CBN;    // 24
        const int nblk_kv = (NH * KV_OUT) / CBN; // 32
        mma_gemm_dual_kernel<<<dim3(nblk_q + nblk_kv, MT), blk, GEMM_SMEM>>>(
            qa_h, Wqb_h, qb, NH * DQK, Q_RANK, nblk_q,
            kvan_h, Wkvb_h, kv16, NH * KV_OUT, KV_RANK);
    }
    // 6. rope + scale + head-major Q; k_pe -> fp16
    prep_kernel<<<T_TOK, 256>>>(positions, cs_cache, scaling,
                                qalat + Q_RANK, FUSED_N, qb, qhp, qlp, kpe);
    // 7. flash attention (K/V double-buffered)
    flash_mma_kernel<<<dim3(T_TOK / AM, NH), 256, FLASH_SMEM>>>(
        qhp, qlp, kv16, kpe, attn);
    // 8. out = attn @ w_o
    mma_gemm1_kernel<<<dim3(HID / CBN, MT), blk, GEMM_SMEM>>>(
        attn, Wo_h, out, T_TOK, HID, NH * DV);
}